// round 1
// baseline (speedup 1.0000x reference)
#include <cuda_runtime.h>
#include <math.h>

// ---------------------------------------------------------------------------
// Problem constants (Mamba2 block, B=2, L=4096)
// ---------------------------------------------------------------------------
namespace cfg {
constexpr int D_MODEL   = 2048;
constexpr int D_INNER   = 4096;   // EXPAND * D_MODEL
constexpr int D_STATE   = 64;
constexpr int D_CONV    = 4;
constexpr int NHEADS    = 64;
constexpr int HEADDIM   = 64;
constexpr int D_XBC     = D_INNER + 2 * D_STATE;           // 4224
constexpr int D_IN_PROJ = 2 * D_INNER + 2 * D_STATE + NHEADS; // 8384
constexpr int LSEQ      = 4096;
constexpr int BATCH     = 2;
constexpr int BL        = BATCH * LSEQ;                    // 8192 tokens
constexpr int CHUNK     = 64;
constexpr int NCHUNK    = LSEQ / CHUNK;                    // 64 per batch
}

// ---------------------------------------------------------------------------
// Scratch (allocation-free: __device__ globals)
// ---------------------------------------------------------------------------
__device__ float g_zx [(size_t)cfg::BL * cfg::D_IN_PROJ]; // raw in-proj output
__device__ float g_xbc[(size_t)cfg::BL * cfg::D_XBC];     // conv+silu output
__device__ float g_dt [(size_t)cfg::BL * cfg::NHEADS];    // softplus(dt+bias)
__device__ float g_y  [(size_t)cfg::BL * cfg::D_INNER];   // SSD output (+D*x)
__device__ float g_nm [(size_t)cfg::BL * cfg::D_INNER];   // gated+normed

// ---------------------------------------------------------------------------
// GEMM: C[M,N] = A[M,K] * B[N,K]^T   (both row-major, K contiguous)
// 128x128x8 tiles, 256 threads, 8x8 microtile. M,K assumed %128/%8 == 0.
// N guarded (8384 is not a multiple of 128).
// ---------------------------------------------------------------------------
__global__ __launch_bounds__(256) void gemm_nt_kernel(
    const float* __restrict__ A, const float* __restrict__ B,
    float* __restrict__ C, int M, int N, int K)
{
    constexpr int BM = 128, BN = 128, BK = 8;
    __shared__ float As[BK][BM];
    __shared__ float Bs[BK][BN];

    const int tid = threadIdx.x;
    const int bm  = blockIdx.y * BM;
    const int bn  = blockIdx.x * BN;

    const int lr = tid >> 1;          // load row 0..127
    const int lk = (tid & 1) * 4;     // 0 or 4
    const int ty = tid >> 4;          // 0..15 (output row group)
    const int tx = tid & 15;          // 0..15 (output col group)

    float acc[8][8];
#pragma unroll
    for (int i = 0; i < 8; i++)
#pragma unroll
        for (int j = 0; j < 8; j++) acc[i][j] = 0.f;

    const float* Aptr = A + (size_t)(bm + lr) * K + lk;
    const bool  bval  = (bn + lr) < N;
    const float* Bptr = B + (size_t)(bn + lr) * K + lk;

    for (int k0 = 0; k0 < K; k0 += BK) {
        float4 av = *(const float4*)(Aptr + k0);
        float4 bv = bval ? *(const float4*)(Bptr + k0) : make_float4(0.f, 0.f, 0.f, 0.f);
        As[lk + 0][lr] = av.x; As[lk + 1][lr] = av.y;
        As[lk + 2][lr] = av.z; As[lk + 3][lr] = av.w;
        Bs[lk + 0][lr] = bv.x; Bs[lk + 1][lr] = bv.y;
        Bs[lk + 2][lr] = bv.z; Bs[lk + 3][lr] = bv.w;
        __syncthreads();
#pragma unroll
        for (int k = 0; k < BK; k++) {
            float a[8], b[8];
            *(float4*)&a[0] = *(const float4*)&As[k][ty * 8];
            *(float4*)&a[4] = *(const float4*)&As[k][ty * 8 + 4];
            *(float4*)&b[0] = *(const float4*)&Bs[k][tx * 8];
            *(float4*)&b[4] = *(const float4*)&Bs[k][tx * 8 + 4];
#pragma unroll
            for (int i = 0; i < 8; i++)
#pragma unroll
                for (int j = 0; j < 8; j++) acc[i][j] = fmaf(a[i], b[j], acc[i][j]);
        }
        __syncthreads();
    }

#pragma unroll
    for (int i = 0; i < 8; i++) {
        size_t crow = (size_t)(bm + ty * 8 + i) * N;
#pragma unroll
        for (int j = 0; j < 8; j++) {
            int col = bn + tx * 8 + j;
            if (col < N) C[crow + col] = acc[i][j];
        }
    }
}

// ---------------------------------------------------------------------------
// Depthwise causal conv (width 4) + bias + silu over the xBC slice of g_zx
// ---------------------------------------------------------------------------
__global__ void conv_silu_kernel(const float* __restrict__ zx,
                                 const float* __restrict__ cw,
                                 const float* __restrict__ cb,
                                 float* __restrict__ out)
{
    int idx = blockIdx.x * blockDim.x + threadIdx.x;
    if (idx >= cfg::BL * cfg::D_XBC) return;
    int j = idx % cfg::D_XBC;
    int t = idx / cfg::D_XBC;
    int l = t & (cfg::LSEQ - 1);
    int b = t >> 12;   // / 4096

    float v = cb[j];
#pragma unroll
    for (int k = 0; k < cfg::D_CONV; k++) {
        int ls = l + k - (cfg::D_CONV - 1);
        if (ls >= 0) {
            v = fmaf(cw[j * cfg::D_CONV + k],
                     zx[(size_t)(b * cfg::LSEQ + ls) * cfg::D_IN_PROJ + cfg::D_INNER + j],
                     v);
        }
    }
    // silu
    float sv = v / (1.f + expf(-v));
    out[(size_t)t * cfg::D_XBC + j] = sv;
}

// ---------------------------------------------------------------------------
// dt = softplus(dt_raw + dt_bias)
// ---------------------------------------------------------------------------
__global__ void dt_kernel(const float* __restrict__ zx,
                          const float* __restrict__ dt_bias,
                          float* __restrict__ out)
{
    int idx = blockIdx.x * blockDim.x + threadIdx.x;
    if (idx >= cfg::BL * cfg::NHEADS) return;
    int h = idx & 63;
    int t = idx >> 6;
    float x = zx[(size_t)t * cfg::D_IN_PROJ + cfg::D_INNER + cfg::D_XBC + h] + dt_bias[h];
    out[idx] = (x > 20.f) ? x : log1pf(expf(x));
}

// ---------------------------------------------------------------------------
// SSD chunked scan. One block per (batch, head), sequential over 64 chunks.
// State S[n][p] (64x64) lives in SMEM. All mini-GEMM operand layouts chosen
// so every inner-loop SMEM read is a row-contiguous float4.
// ---------------------------------------------------------------------------
struct SsdSmem {
    float S   [64][64];  // state, [n][p]
    float Xraw[64][64];  // [l][p]  x (post conv+silu)
    float Xs  [64][64];  // [l][p]  x * dt
    float Bl  [64][64];  // [l][n]
    float Bt  [64][64];  // [n][l]
    float Ct  [64][64];  // [n][l]
    float Wt  [64][64];  // [s][l]  masked decay-weighted CB
    float dts[64], dAl[64], Acum[64], eA[64], ws[64];
};

__global__ __launch_bounds__(256) void ssd_kernel(
    const float* __restrict__ xbc, const float* __restrict__ dtg,
    const float* __restrict__ A_log, const float* __restrict__ D_param,
    float* __restrict__ y)
{
    extern __shared__ char smraw[];
    SsdSmem& sm = *reinterpret_cast<SsdSmem*>(smraw);

    const int tid = threadIdx.x;
    const int b   = blockIdx.x >> 6;
    const int h   = blockIdx.x & 63;
    const float Aneg = -expf(A_log[h]);
    const float Dh   = D_param[h];
    const int ty = tid >> 4, tx = tid & 15;

    for (int idx = tid; idx < 64 * 64; idx += 256)
        (&sm.S[0][0])[idx] = 0.f;
    __syncthreads();

    for (int c = 0; c < cfg::NCHUNK; c++) {
        const int l0g = c * cfg::CHUNK;

        // ---- load chunk into SMEM ----
        for (int idx = tid; idx < 64 * 64; idx += 256) {
            int l = idx >> 6, q = idx & 63;
            size_t row = (size_t)(b * cfg::LSEQ + l0g + l);
            const float* xr = xbc + row * cfg::D_XBC;
            float dtv = dtg[row * cfg::NHEADS + h];
            float xv  = xr[h * cfg::HEADDIM + q];
            sm.Xraw[l][q] = xv;
            sm.Xs[l][q]   = xv * dtv;
            float bv = xr[cfg::D_INNER + q];
            sm.Bl[l][q] = bv;
            sm.Bt[q][l] = bv;
            sm.Ct[q][l] = xr[cfg::D_INNER + cfg::D_STATE + q];
        }
        if (tid < 64) {
            size_t row = (size_t)(b * cfg::LSEQ + l0g + tid);
            float dtv = dtg[row * cfg::NHEADS + h];
            sm.dts[tid] = dtv;
            sm.dAl[tid] = Aneg * dtv;
        }
        __syncthreads();

        // ---- inclusive prefix sum of dA (64 elems, serial) ----
        if (tid == 0) {
            float s = 0.f;
            for (int l = 0; l < 64; l++) { s += sm.dAl[l]; sm.Acum[l] = s; }
        }
        __syncthreads();
        if (tid < 64) {
            sm.eA[tid] = expf(sm.Acum[tid]);                 // <= 1
            sm.ws[tid] = expf(sm.Acum[63] - sm.Acum[tid]);   // <= 1
        }
        __syncthreads();

        // ---- Wt[s][l] = (s<=l) ? (C_l . B_s) * exp(Acum[l]-Acum[s]) : 0 ----
        {
            const int s0 = ty * 4, l0 = tx * 4;
            float acc[4][4];
#pragma unroll
            for (int i = 0; i < 4; i++)
#pragma unroll
                for (int j = 0; j < 4; j++) acc[i][j] = 0.f;
#pragma unroll 4
            for (int n = 0; n < 64; n++) {
                float4 av = *(const float4*)&sm.Bt[n][s0];
                float4 bv = *(const float4*)&sm.Ct[n][l0];
                float a[4] = {av.x, av.y, av.z, av.w};
                float bb[4] = {bv.x, bv.y, bv.z, bv.w};
#pragma unroll
                for (int i = 0; i < 4; i++)
#pragma unroll
                    for (int j = 0; j < 4; j++) acc[i][j] = fmaf(a[i], bb[j], acc[i][j]);
            }
#pragma unroll
            for (int i = 0; i < 4; i++)
#pragma unroll
                for (int j = 0; j < 4; j++) {
                    int s = s0 + i, l = l0 + j;
                    float w = (s <= l) ? expf(sm.Acum[l] - sm.Acum[s]) : 0.f;
                    sm.Wt[s][l] = acc[i][j] * w;
                }
        }
        __syncthreads();

        // ---- Y[l][p] = sum_s Wt[s][l]*Xs[s][p] + eA[l]*sum_n Ct[n][l]*S[n][p]
        //                + Dh * Xraw[l][p] ----
        {
            const int l0 = ty * 4, p0 = tx * 4;
            float yd[4][4], yo[4][4];
#pragma unroll
            for (int i = 0; i < 4; i++)
#pragma unroll
                for (int j = 0; j < 4; j++) { yd[i][j] = 0.f; yo[i][j] = 0.f; }
#pragma unroll 4
            for (int s = 0; s < 64; s++) {
                float4 av = *(const float4*)&sm.Wt[s][l0];
                float4 bv = *(const float4*)&sm.Xs[s][p0];
                float a[4] = {av.x, av.y, av.z, av.w};
                float bb[4] = {bv.x, bv.y, bv.z, bv.w};
#pragma unroll
                for (int i = 0; i < 4; i++)
#pragma unroll
                    for (int j = 0; j < 4; j++) yd[i][j] = fmaf(a[i], bb[j], yd[i][j]);
            }
#pragma unroll 4
            for (int n = 0; n < 64; n++) {
                float4 av = *(const float4*)&sm.Ct[n][l0];
                float4 bv = *(const float4*)&sm.S[n][p0];
                float a[4] = {av.x, av.y, av.z, av.w};
                float bb[4] = {bv.x, bv.y, bv.z, bv.w};
#pragma unroll
                for (int i = 0; i < 4; i++)
#pragma unroll
                    for (int j = 0; j < 4; j++) yo[i][j] = fmaf(a[i], bb[j], yo[i][j]);
            }
#pragma unroll
            for (int i = 0; i < 4; i++) {
                int l = l0 + i;
                size_t row = (size_t)(b * cfg::LSEQ + l0g + l);
                float ea = sm.eA[l];
                float4 o;
                o.x = yd[i][0] + ea * yo[i][0] + Dh * sm.Xraw[l][p0 + 0];
                o.y = yd[i][1] + ea * yo[i][1] + Dh * sm.Xraw[l][p0 + 1];
                o.z = yd[i][2] + ea * yo[i][2] + Dh * sm.Xraw[l][p0 + 2];
                o.w = yd[i][3] + ea * yo[i][3] + Dh * sm.Xraw[l][p0 + 3];
                *(float4*)(y + row * cfg::D_INNER + h * cfg::HEADDIM + p0) = o;
            }
        }
        __syncthreads();  // all reads of S done before update

        // ---- S[n][p] = exp(Asum)*S + sum_l ws[l]*Bl[l][n]*Xs[l][p] ----
        {
            const int n0 = ty * 4, p0 = tx * 4;
            float sa[4][4];
#pragma unroll
            for (int i = 0; i < 4; i++)
#pragma unroll
                for (int j = 0; j < 4; j++) sa[i][j] = 0.f;
#pragma unroll 4
            for (int l = 0; l < 64; l++) {
                float w = sm.ws[l];
                float4 av = *(const float4*)&sm.Bl[l][n0];
                float4 bv = *(const float4*)&sm.Xs[l][p0];
                float a[4] = {av.x * w, av.y * w, av.z * w, av.w * w};
                float bb[4] = {bv.x, bv.y, bv.z, bv.w};
#pragma unroll
                for (int i = 0; i < 4; i++)
#pragma unroll
                    for (int j = 0; j < 4; j++) sa[i][j] = fmaf(a[i], bb[j], sa[i][j]);
            }
            float dec = sm.eA[63];
#pragma unroll
            for (int i = 0; i < 4; i++)
#pragma unroll
                for (int j = 0; j < 4; j++)
                    sm.S[n0 + i][p0 + j] = dec * sm.S[n0 + i][p0 + j] + sa[i][j];
        }
        __syncthreads();  // S update + (next) SMEM overwrite ordering
    }
}

// ---------------------------------------------------------------------------
// y_gated = y * silu(z); RMSNorm over 4096 (ngroups=1); * norm_w
// ---------------------------------------------------------------------------
__global__ __launch_bounds__(256) void gate_norm_kernel(
    const float* __restrict__ y, const float* __restrict__ zx,
    const float* __restrict__ nw, float* __restrict__ out)
{
    __shared__ float gbuf[cfg::D_INNER];
    __shared__ float red[8];
    const int t = blockIdx.x;
    const int tid = threadIdx.x;
    const float* yr = y + (size_t)t * cfg::D_INNER;
    const float* zr = zx + (size_t)t * cfg::D_IN_PROJ;

    float ss = 0.f;
    for (int i = tid; i < cfg::D_INNER; i += 256) {
        float zv = zr[i];
        float gv = yr[i] * (zv / (1.f + expf(-zv)));
        gbuf[i] = gv;
        ss = fmaf(gv, gv, ss);
    }
#pragma unroll
    for (int o = 16; o; o >>= 1) ss += __shfl_xor_sync(0xffffffffu, ss, o);
    if ((tid & 31) == 0) red[tid >> 5] = ss;
    __syncthreads();
    if (tid < 32) {
        float v = (tid < 8) ? red[tid] : 0.f;
#pragma unroll
        for (int o = 4; o; o >>= 1) v += __shfl_xor_sync(0xffffffffu, v, o);
        if (tid == 0) red[0] = v;
    }
    __syncthreads();
    const float scale = rsqrtf(red[0] * (1.f / cfg::D_INNER) + 1e-5f);
    for (int i = tid; i < cfg::D_INNER; i += 256)
        out[(size_t)t * cfg::D_INNER + i] = gbuf[i] * scale * nw[i];
}

// ---------------------------------------------------------------------------
// Host launch
// ---------------------------------------------------------------------------
extern "C" void kernel_launch(void* const* d_in, const int* in_sizes, int n_in,
                              void* d_out, int out_size)
{
    (void)in_sizes; (void)n_in; (void)out_size;
    const float* u       = (const float*)d_in[0];
    const float* W_in    = (const float*)d_in[1];
    const float* conv_w  = (const float*)d_in[2];
    const float* conv_b  = (const float*)d_in[3];
    const float* dt_bias = (const float*)d_in[4];
    const float* A_log   = (const float*)d_in[5];
    const float* D_param = (const float*)d_in[6];
    const float* norm_w  = (const float*)d_in[7];
    const float* W_out   = (const float*)d_in[8];
    float* out = (float*)d_out;

    void *pzx, *pxbc, *pdt, *py, *pnm;
    cudaGetSymbolAddress(&pzx,  g_zx);
    cudaGetSymbolAddress(&pxbc, g_xbc);
    cudaGetSymbolAddress(&pdt,  g_dt);
    cudaGetSymbolAddress(&py,   g_y);
    cudaGetSymbolAddress(&pnm,  g_nm);
    float* zx  = (float*)pzx;
    float* xbc = (float*)pxbc;
    float* dtb = (float*)pdt;
    float* yb  = (float*)py;
    float* nm  = (float*)pnm;

    // GEMM1: zx[8192,8384] = u[8192,2048] @ W_in[8384,2048]^T
    {
        dim3 grid((cfg::D_IN_PROJ + 127) / 128, cfg::BL / 128);
        gemm_nt_kernel<<<grid, 256>>>(u, W_in, zx, cfg::BL, cfg::D_IN_PROJ, cfg::D_MODEL);
    }
    // conv + silu
    {
        int n = cfg::BL * cfg::D_XBC;
        conv_silu_kernel<<<(n + 255) / 256, 256>>>(zx, conv_w, conv_b, xbc);
    }
    // dt softplus
    {
        int n = cfg::BL * cfg::NHEADS;
        dt_kernel<<<(n + 255) / 256, 256>>>(zx, dt_bias, dtb);
    }
    // SSD scan
    {
        static_assert(sizeof(SsdSmem) < 200 * 1024, "smem");
        cudaFuncSetAttribute(ssd_kernel, cudaFuncAttributeMaxDynamicSharedMemorySize,
                             (int)sizeof(SsdSmem));
        ssd_kernel<<<cfg::BATCH * cfg::NHEADS, 256, sizeof(SsdSmem)>>>(
            xbc, dtb, A_log, D_param, yb);
    }
    // gate + rmsnorm
    gate_norm_kernel<<<cfg::BL, 256>>>(yb, zx, norm_w, nm);
    // GEMM2: out[8192,2048] = nm[8192,4096] @ W_out[2048,4096]^T
    {
        dim3 grid(cfg::D_MODEL / 128, cfg::BL / 128);
        gemm_nt_kernel<<<grid, 256>>>(nm, W_out, out, cfg::BL, cfg::D_MODEL, cfg::D_INNER);
    }
}

// round 3
// speedup vs baseline: 2.3839x; 2.3839x over previous
#include <cuda_runtime.h>
#include <cuda_bf16.h>
#include <math.h>
#include <stdint.h>

// ---------------------------------------------------------------------------
// Problem constants (Mamba2 block, B=2, L=4096)
// ---------------------------------------------------------------------------
namespace cfg {
constexpr int D_MODEL   = 2048;
constexpr int D_INNER   = 4096;
constexpr int D_STATE   = 64;
constexpr int D_CONV    = 4;
constexpr int NHEADS    = 64;
constexpr int HEADDIM   = 64;
constexpr int D_XBC     = D_INNER + 2 * D_STATE;              // 4224
constexpr int D_IN_PROJ = 2 * D_INNER + 2 * D_STATE + NHEADS; // 8384
constexpr int LSEQ      = 4096;
constexpr int BATCH     = 2;
constexpr int BL        = BATCH * LSEQ;                       // 8192
constexpr int CHUNK     = 64;
constexpr int NCHUNK    = LSEQ / CHUNK;
// padded N for GEMM1 B-operand (66 blocks of 128)
constexpr int N1_PAD    = 8448;
}

// ---------------------------------------------------------------------------
// Scratch (allocation-free: __device__ globals; zero-initialized at load,
// padding rows of the weight planes are never written and stay zero)
// ---------------------------------------------------------------------------
__device__ float g_zx [(size_t)cfg::BL * cfg::D_IN_PROJ];
__device__ float g_xbc[(size_t)cfg::BL * cfg::D_XBC];
__device__ float g_dt [(size_t)cfg::BL * cfg::NHEADS];
__device__ float g_y  [(size_t)cfg::BL * cfg::D_INNER];

__device__ __nv_bfloat16 g_uh [(size_t)cfg::BL * cfg::D_MODEL];
__device__ __nv_bfloat16 g_ul [(size_t)cfg::BL * cfg::D_MODEL];
__device__ __nv_bfloat16 g_wih[(size_t)cfg::N1_PAD * cfg::D_MODEL];   // padded rows zero
__device__ __nv_bfloat16 g_wil[(size_t)cfg::N1_PAD * cfg::D_MODEL];
__device__ __nv_bfloat16 g_nmh[(size_t)cfg::BL * cfg::D_INNER];
__device__ __nv_bfloat16 g_nml[(size_t)cfg::BL * cfg::D_INNER];
__device__ __nv_bfloat16 g_woh[(size_t)cfg::D_MODEL * cfg::D_INNER];
__device__ __nv_bfloat16 g_wol[(size_t)cfg::D_MODEL * cfg::D_INNER];

// ---------------------------------------------------------------------------
// PTX helpers (family-portable: mma.sync / ldmatrix / cp.async only)
// ---------------------------------------------------------------------------
__device__ __forceinline__ uint32_t smem_u32(const void* p) {
    uint32_t a;
    asm("{ .reg .u64 t; cvta.to.shared.u64 t, %1; cvt.u32.u64 %0, t; }"
        : "=r"(a) : "l"(p));
    return a;
}
__device__ __forceinline__ void cp_async16(uint32_t dst, const void* src) {
    asm volatile("cp.async.cg.shared.global [%0], [%1], 16;"
                 :: "r"(dst), "l"(src) : "memory");
}
__device__ __forceinline__ void ldsm4(uint32_t r[4], uint32_t addr) {
    asm volatile("ldmatrix.sync.aligned.m8n8.x4.shared.b16 {%0,%1,%2,%3}, [%4];"
                 : "=r"(r[0]), "=r"(r[1]), "=r"(r[2]), "=r"(r[3]) : "r"(addr));
}
__device__ __forceinline__ void mma16816(float c[4], const uint32_t a[4],
                                         uint32_t b0, uint32_t b1) {
    asm volatile(
        "mma.sync.aligned.m16n8k16.row.col.f32.bf16.bf16.f32 "
        "{%0,%1,%2,%3}, {%4,%5,%6,%7}, {%8,%9}, {%0,%1,%2,%3};"
        : "+f"(c[0]), "+f"(c[1]), "+f"(c[2]), "+f"(c[3])
        : "r"(a[0]), "r"(a[1]), "r"(a[2]), "r"(a[3]), "r"(b0), "r"(b1));
}

// ---------------------------------------------------------------------------
// HMMA GEMM: C[M,N] = (Ah+Al)[M,K] * (Bh+Bl)[Npad,K]^T  (3-pass bf16 emu,
// fp32 accum). Block 128x128x32, 8 warps (2x4), warp tile 64x32, 3-stage
// cp.async pipeline, swizzled SMEM (conflict-free ldmatrix).
// Requirements: M%128==0, K%32==0, K/32>=3, B buffers padded to gridN*128 rows.
// ---------------------------------------------------------------------------
namespace mg {
constexpr int PLANE = 128 * 32 * 2;          // 8192 B per plane tile
constexpr int STAGE = 4 * PLANE;             // Ah, Al, Bh, Bl
constexpr int STAGES = 3;
constexpr int SMEM_BYTES = STAGES * STAGE;   // 98304
}

__global__ __launch_bounds__(256) void gemm_mma_kernel(
    const __nv_bfloat16* __restrict__ Ah, const __nv_bfloat16* __restrict__ Al,
    const __nv_bfloat16* __restrict__ Bh, const __nv_bfloat16* __restrict__ Bl,
    float* __restrict__ C, int M, int N, int K)
{
    extern __shared__ char smraw[];
    const uint32_t sb = smem_u32(smraw);
    const int tid  = threadIdx.x;
    const int bm   = blockIdx.y * 128;
    const int bn   = blockIdx.x * 128;
    const int wid  = tid >> 5, lane = tid & 31;
    const int wm   = wid & 1;       // 0..1 : 64-row half
    const int wn   = wid >> 1;      // 0..3 : 32-col quarter
    const int NK   = K >> 5;

    auto issue_load = [&](int stage, int kblk) {
        const uint32_t sbase = sb + stage * mg::STAGE;
        const int k0 = kblk * 32;
#pragma unroll
        for (int it = 0; it < 8; it++) {
            int id = it * 256 + tid;           // 0..2047
            int p  = id >> 9;                  // plane 0..3
            int c  = id & 511;
            int r  = c >> 2, g = c & 3;
            uint32_t dst = sbase + p * mg::PLANE + r * 64 +
                           ((g ^ ((r >> 1) & 3)) << 4);
            const __nv_bfloat16* src;
            if      (p == 0) src = Ah + (size_t)(bm + r) * K + k0 + g * 8;
            else if (p == 1) src = Al + (size_t)(bm + r) * K + k0 + g * 8;
            else if (p == 2) src = Bh + (size_t)(bn + r) * K + k0 + g * 8;
            else             src = Bl + (size_t)(bn + r) * K + k0 + g * 8;
            cp_async16(dst, src);
        }
    };

    float acc[4][4][4];
#pragma unroll
    for (int i = 0; i < 4; i++)
#pragma unroll
        for (int j = 0; j < 4; j++)
#pragma unroll
            for (int q = 0; q < 4; q++) acc[i][j][q] = 0.f;

#pragma unroll
    for (int s = 0; s < mg::STAGES; s++) {
        issue_load(s, s);
        asm volatile("cp.async.commit_group;" ::: "memory");
    }

    for (int kb = 0; kb < NK; kb++) {
        asm volatile("cp.async.wait_group 2;" ::: "memory");
        __syncthreads();

        const uint32_t st = sb + (kb % mg::STAGES) * mg::STAGE;
        const uint32_t sAh = st, sAl = st + mg::PLANE;
        const uint32_t sBh = st + 2 * mg::PLANE, sBl = st + 3 * mg::PLANE;

        // B fragments: x4 ldmatrix covers 8n x 32k (both k16 steps)
        uint32_t bh[4][4], bl[4][4];
#pragma unroll
        for (int nt = 0; nt < 4; nt++) {
            int nr = wn * 32 + nt * 8 + (lane & 7);
            int g  = lane >> 3;
            uint32_t off = nr * 64 + ((g ^ ((nr >> 1) & 3)) << 4);
            ldsm4(bh[nt], sBh + off);
            ldsm4(bl[nt], sBl + off);
        }
#pragma unroll
        for (int ks = 0; ks < 2; ks++) {
            uint32_t a[4][4];
#pragma unroll
            for (int mt = 0; mt < 4; mt++) {
                int ar = wm * 64 + mt * 16 + (lane & 15);
                int g  = ks * 2 + (lane >> 4);
                ldsm4(a[mt], sAh + ar * 64 + ((g ^ ((ar >> 1) & 3)) << 4));
            }
#pragma unroll
            for (int mt = 0; mt < 4; mt++)
#pragma unroll
                for (int nt = 0; nt < 4; nt++)
                    mma16816(acc[mt][nt], a[mt], bh[nt][2 * ks], bh[nt][2 * ks + 1]);
#pragma unroll
            for (int mt = 0; mt < 4; mt++)
#pragma unroll
                for (int nt = 0; nt < 4; nt++)
                    mma16816(acc[mt][nt], a[mt], bl[nt][2 * ks], bl[nt][2 * ks + 1]);
#pragma unroll
            for (int mt = 0; mt < 4; mt++) {
                int ar = wm * 64 + mt * 16 + (lane & 15);
                int g  = ks * 2 + (lane >> 4);
                ldsm4(a[mt], sAl + ar * 64 + ((g ^ ((ar >> 1) & 3)) << 4));
            }
#pragma unroll
            for (int mt = 0; mt < 4; mt++)
#pragma unroll
                for (int nt = 0; nt < 4; nt++)
                    mma16816(acc[mt][nt], a[mt], bh[nt][2 * ks], bh[nt][2 * ks + 1]);
        }
        __syncthreads();
        if (kb + mg::STAGES < NK) issue_load(kb % mg::STAGES, kb + mg::STAGES);
        asm volatile("cp.async.commit_group;" ::: "memory");
    }

    // epilogue: direct fp32 stores (col-guarded for N=8384 edge)
#pragma unroll
    for (int mt = 0; mt < 4; mt++) {
#pragma unroll
        for (int nt = 0; nt < 4; nt++) {
            int row = bm + wm * 64 + mt * 16 + (lane >> 2);
            int col = bn + wn * 32 + nt * 8 + (lane & 3) * 2;
            if (col < N) {
                float2 v01 = make_float2(acc[mt][nt][0], acc[mt][nt][1]);
                float2 v23 = make_float2(acc[mt][nt][2], acc[mt][nt][3]);
                *(float2*)(C + (size_t)row * N + col)       = v01;
                *(float2*)(C + (size_t)(row + 8) * N + col) = v23;
            }
        }
    }
}

// ---------------------------------------------------------------------------
// fp32 -> bf16 (hi, lo) split
// ---------------------------------------------------------------------------
__global__ void split_bf16_kernel(const float* __restrict__ src,
                                  __nv_bfloat16* __restrict__ hi,
                                  __nv_bfloat16* __restrict__ lo, int n4)
{
    int i = blockIdx.x * blockDim.x + threadIdx.x;
    if (i >= n4) return;
    float4 v = ((const float4*)src)[i];
    __nv_bfloat16 h0 = __float2bfloat16(v.x), h1 = __float2bfloat16(v.y);
    __nv_bfloat16 h2 = __float2bfloat16(v.z), h3 = __float2bfloat16(v.w);
    __nv_bfloat16 l0 = __float2bfloat16(v.x - __bfloat162float(h0));
    __nv_bfloat16 l1 = __float2bfloat16(v.y - __bfloat162float(h1));
    __nv_bfloat16 l2 = __float2bfloat16(v.z - __bfloat162float(h2));
    __nv_bfloat16 l3 = __float2bfloat16(v.w - __bfloat162float(h3));
    ((__nv_bfloat162*)hi)[2 * i]     = __halves2bfloat162(h0, h1);
    ((__nv_bfloat162*)hi)[2 * i + 1] = __halves2bfloat162(h2, h3);
    ((__nv_bfloat162*)lo)[2 * i]     = __halves2bfloat162(l0, l1);
    ((__nv_bfloat162*)lo)[2 * i + 1] = __halves2bfloat162(l2, l3);
}

// ---------------------------------------------------------------------------
// Depthwise causal conv (width 4) + bias + silu
// ---------------------------------------------------------------------------
__global__ void conv_silu_kernel(const float* __restrict__ zx,
                                 const float* __restrict__ cw,
                                 const float* __restrict__ cb,
                                 float* __restrict__ out)
{
    int idx = blockIdx.x * blockDim.x + threadIdx.x;
    if (idx >= cfg::BL * cfg::D_XBC) return;
    int j = idx % cfg::D_XBC;
    int t = idx / cfg::D_XBC;
    int l = t & (cfg::LSEQ - 1);
    int b = t >> 12;

    float v = cb[j];
#pragma unroll
    for (int k = 0; k < cfg::D_CONV; k++) {
        int ls = l + k - (cfg::D_CONV - 1);
        if (ls >= 0)
            v = fmaf(cw[j * cfg::D_CONV + k],
                     zx[(size_t)(b * cfg::LSEQ + ls) * cfg::D_IN_PROJ + cfg::D_INNER + j], v);
    }
    out[(size_t)t * cfg::D_XBC + j] = v / (1.f + expf(-v));
}

__global__ void dt_kernel(const float* __restrict__ zx,
                          const float* __restrict__ dt_bias,
                          float* __restrict__ out)
{
    int idx = blockIdx.x * blockDim.x + threadIdx.x;
    if (idx >= cfg::BL * cfg::NHEADS) return;
    int h = idx & 63;
    int t = idx >> 6;
    float x = zx[(size_t)t * cfg::D_IN_PROJ + cfg::D_INNER + cfg::D_XBC + h] + dt_bias[h];
    out[idx] = (x > 20.f) ? x : log1pf(expf(x));
}

// ---------------------------------------------------------------------------
// SSD chunked scan (unchanged)
// ---------------------------------------------------------------------------
struct SsdSmem {
    float S   [64][64];
    float Xraw[64][64];
    float Xs  [64][64];
    float Bl  [64][64];
    float Bt  [64][64];
    float Ct  [64][64];
    float Wt  [64][64];
    float dts[64], dAl[64], Acum[64], eA[64], ws[64];
};

__global__ __launch_bounds__(256) void ssd_kernel(
    const float* __restrict__ xbc, const float* __restrict__ dtg,
    const float* __restrict__ A_log, const float* __restrict__ D_param,
    float* __restrict__ y)
{
    extern __shared__ char smraw[];
    SsdSmem& sm = *reinterpret_cast<SsdSmem*>(smraw);

    const int tid = threadIdx.x;
    const int b   = blockIdx.x >> 6;
    const int h   = blockIdx.x & 63;
    const float Aneg = -expf(A_log[h]);
    const float Dh   = D_param[h];
    const int ty = tid >> 4, tx = tid & 15;

    for (int idx = tid; idx < 64 * 64; idx += 256)
        (&sm.S[0][0])[idx] = 0.f;
    __syncthreads();

    for (int c = 0; c < cfg::NCHUNK; c++) {
        const int l0g = c * cfg::CHUNK;

        for (int idx = tid; idx < 64 * 64; idx += 256) {
            int l = idx >> 6, q = idx & 63;
            size_t row = (size_t)(b * cfg::LSEQ + l0g + l);
            const float* xr = xbc + row * cfg::D_XBC;
            float dtv = dtg[row * cfg::NHEADS + h];
            float xv  = xr[h * cfg::HEADDIM + q];
            sm.Xraw[l][q] = xv;
            sm.Xs[l][q]   = xv * dtv;
            float bv = xr[cfg::D_INNER + q];
            sm.Bl[l][q] = bv;
            sm.Bt[q][l] = bv;
            sm.Ct[q][l] = xr[cfg::D_INNER + cfg::D_STATE + q];
        }
        if (tid < 64) {
            size_t row = (size_t)(b * cfg::LSEQ + l0g + tid);
            float dtv = dtg[row * cfg::NHEADS + h];
            sm.dts[tid] = dtv;
            sm.dAl[tid] = Aneg * dtv;
        }
        __syncthreads();

        if (tid == 0) {
            float s = 0.f;
            for (int l = 0; l < 64; l++) { s += sm.dAl[l]; sm.Acum[l] = s; }
        }
        __syncthreads();
        if (tid < 64) {
            sm.eA[tid] = expf(sm.Acum[tid]);
            sm.ws[tid] = expf(sm.Acum[63] - sm.Acum[tid]);
        }
        __syncthreads();

        {
            const int s0 = ty * 4, l0 = tx * 4;
            float acc[4][4];
#pragma unroll
            for (int i = 0; i < 4; i++)
#pragma unroll
                for (int j = 0; j < 4; j++) acc[i][j] = 0.f;
#pragma unroll 4
            for (int n = 0; n < 64; n++) {
                float4 av = *(const float4*)&sm.Bt[n][s0];
                float4 bv = *(const float4*)&sm.Ct[n][l0];
                float a[4] = {av.x, av.y, av.z, av.w};
                float bb[4] = {bv.x, bv.y, bv.z, bv.w};
#pragma unroll
                for (int i = 0; i < 4; i++)
#pragma unroll
                    for (int j = 0; j < 4; j++) acc[i][j] = fmaf(a[i], bb[j], acc[i][j]);
            }
#pragma unroll
            for (int i = 0; i < 4; i++)
#pragma unroll
                for (int j = 0; j < 4; j++) {
                    int s = s0 + i, l = l0 + j;
                    float w = (s <= l) ? expf(sm.Acum[l] - sm.Acum[s]) : 0.f;
                    sm.Wt[s][l] = acc[i][j] * w;
                }
        }
        __syncthreads();

        {
            const int l0 = ty * 4, p0 = tx * 4;
            float yd[4][4], yo[4][4];
#pragma unroll
            for (int i = 0; i < 4; i++)
#pragma unroll
                for (int j = 0; j < 4; j++) { yd[i][j] = 0.f; yo[i][j] = 0.f; }
#pragma unroll 4
            for (int s = 0; s < 64; s++) {
                float4 av = *(const float4*)&sm.Wt[s][l0];
                float4 bv = *(const float4*)&sm.Xs[s][p0];
                float a[4] = {av.x, av.y, av.z, av.w};
                float bb[4] = {bv.x, bv.y, bv.z, bv.w};
#pragma unroll
                for (int i = 0; i < 4; i++)
#pragma unroll
                    for (int j = 0; j < 4; j++) yd[i][j] = fmaf(a[i], bb[j], yd[i][j]);
            }
#pragma unroll 4
            for (int n = 0; n < 64; n++) {
                float4 av = *(const float4*)&sm.Ct[n][l0];
                float4 bv = *(const float4*)&sm.S[n][p0];
                float a[4] = {av.x, av.y, av.z, av.w};
                float bb[4] = {bv.x, bv.y, bv.z, bv.w};
#pragma unroll
                for (int i = 0; i < 4; i++)
#pragma unroll
                    for (int j = 0; j < 4; j++) yo[i][j] = fmaf(a[i], bb[j], yo[i][j]);
            }
#pragma unroll
            for (int i = 0; i < 4; i++) {
                int l = l0 + i;
                size_t row = (size_t)(b * cfg::LSEQ + l0g + l);
                float ea = sm.eA[l];
                float4 o;
                o.x = yd[i][0] + ea * yo[i][0] + Dh * sm.Xraw[l][p0 + 0];
                o.y = yd[i][1] + ea * yo[i][1] + Dh * sm.Xraw[l][p0 + 1];
                o.z = yd[i][2] + ea * yo[i][2] + Dh * sm.Xraw[l][p0 + 2];
                o.w = yd[i][3] + ea * yo[i][3] + Dh * sm.Xraw[l][p0 + 3];
                *(float4*)(y + row * cfg::D_INNER + h * cfg::HEADDIM + p0) = o;
            }
        }
        __syncthreads();

        {
            const int n0 = ty * 4, p0 = tx * 4;
            float sa[4][4];
#pragma unroll
            for (int i = 0; i < 4; i++)
#pragma unroll
                for (int j = 0; j < 4; j++) sa[i][j] = 0.f;
#pragma unroll 4
            for (int l = 0; l < 64; l++) {
                float w = sm.ws[l];
                float4 av = *(const float4*)&sm.Bl[l][n0];
                float4 bv = *(const float4*)&sm.Xs[l][p0];
                float a[4] = {av.x * w, av.y * w, av.z * w, av.w * w};
                float bb[4] = {bv.x, bv.y, bv.z, bv.w};
#pragma unroll
                for (int i = 0; i < 4; i++)
#pragma unroll
                    for (int j = 0; j < 4; j++) sa[i][j] = fmaf(a[i], bb[j], sa[i][j]);
            }
            float dec = sm.eA[63];
#pragma unroll
            for (int i = 0; i < 4; i++)
#pragma unroll
                for (int j = 0; j < 4; j++)
                    sm.S[n0 + i][p0 + j] = dec * sm.S[n0 + i][p0 + j] + sa[i][j];
        }
        __syncthreads();
    }
}

// ---------------------------------------------------------------------------
// gate + RMSNorm; writes bf16 hi/lo planes for GEMM2 directly
// ---------------------------------------------------------------------------
__global__ __launch_bounds__(256) void gate_norm_kernel(
    const float* __restrict__ y, const float* __restrict__ zx,
    const float* __restrict__ nw,
    __nv_bfloat16* __restrict__ nmh, __nv_bfloat16* __restrict__ nml)
{
    __shared__ float gbuf[cfg::D_INNER];
    __shared__ float red[8];
    const int t = blockIdx.x;
    const int tid = threadIdx.x;
    const float* yr = y + (size_t)t * cfg::D_INNER;
    const float* zr = zx + (size_t)t * cfg::D_IN_PROJ;

    float ss = 0.f;
    for (int i = tid; i < cfg::D_INNER; i += 256) {
        float zv = zr[i];
        float gv = yr[i] * (zv / (1.f + expf(-zv)));
        gbuf[i] = gv;
        ss = fmaf(gv, gv, ss);
    }
#pragma unroll
    for (int o = 16; o; o >>= 1) ss += __shfl_xor_sync(0xffffffffu, ss, o);
    if ((tid & 31) == 0) red[tid >> 5] = ss;
    __syncthreads();
    if (tid < 32) {
        float v = (tid < 8) ? red[tid] : 0.f;
#pragma unroll
        for (int o = 4; o; o >>= 1) v += __shfl_xor_sync(0xffffffffu, v, o);
        if (tid == 0) red[0] = v;
    }
    __syncthreads();
    const float scale = rsqrtf(red[0] * (1.f / cfg::D_INNER) + 1e-5f);
    for (int i = tid; i < cfg::D_INNER; i += 256) {
        float val = gbuf[i] * scale * nw[i];
        __nv_bfloat16 h = __float2bfloat16(val);
        size_t idx = (size_t)t * cfg::D_INNER + i;
        nmh[idx] = h;
        nml[idx] = __float2bfloat16(val - __bfloat162float(h));
    }
}

// ---------------------------------------------------------------------------
// Host launch
// ---------------------------------------------------------------------------
extern "C" void kernel_launch(void* const* d_in, const int* in_sizes, int n_in,
                              void* d_out, int out_size)
{
    (void)in_sizes; (void)n_in; (void)out_size;
    const float* u       = (const float*)d_in[0];
    const float* W_in    = (const float*)d_in[1];
    const float* conv_w  = (const float*)d_in[2];
    const float* conv_b  = (const float*)d_in[3];
    const float* dt_bias = (const float*)d_in[4];
    const float* A_log   = (const float*)d_in[5];
    const float* D_param = (const float*)d_in[6];
    const float* norm_w  = (const float*)d_in[7];
    const float* W_out   = (const float*)d_in[8];
    float* out = (float*)d_out;

    void *pzx, *pxbc, *pdt, *py;
    void *puh, *pul, *pwih, *pwil, *pnmh, *pnml, *pwoh, *pwol;
    cudaGetSymbolAddress(&pzx,  g_zx);
    cudaGetSymbolAddress(&pxbc, g_xbc);
    cudaGetSymbolAddress(&pdt,  g_dt);
    cudaGetSymbolAddress(&py,   g_y);
    cudaGetSymbolAddress(&puh,  g_uh);
    cudaGetSymbolAddress(&pul,  g_ul);
    cudaGetSymbolAddress(&pwih, g_wih);
    cudaGetSymbolAddress(&pwil, g_wil);
    cudaGetSymbolAddress(&pnmh, g_nmh);
    cudaGetSymbolAddress(&pnml, g_nml);
    cudaGetSymbolAddress(&pwoh, g_woh);
    cudaGetSymbolAddress(&pwol, g_wol);
    float* zx  = (float*)pzx;
    float* xbc = (float*)pxbc;
    float* dtb = (float*)pdt;
    float* yb  = (float*)py;
    __nv_bfloat16* uh  = (__nv_bfloat16*)puh;
    __nv_bfloat16* ul  = (__nv_bfloat16*)pul;
    __nv_bfloat16* wih = (__nv_bfloat16*)pwih;
    __nv_bfloat16* wil = (__nv_bfloat16*)pwil;
    __nv_bfloat16* nmh = (__nv_bfloat16*)pnmh;
    __nv_bfloat16* nml = (__nv_bfloat16*)pnml;
    __nv_bfloat16* woh = (__nv_bfloat16*)pwoh;
    __nv_bfloat16* wol = (__nv_bfloat16*)pwol;

    cudaFuncSetAttribute(gemm_mma_kernel, cudaFuncAttributeMaxDynamicSharedMemorySize,
                         mg::SMEM_BYTES);

    // fp32 -> bf16 hi/lo splits
    {
        int n4 = cfg::BL * cfg::D_MODEL / 4;
        split_bf16_kernel<<<(n4 + 255) / 256, 256>>>(u, uh, ul, n4);
        n4 = cfg::D_IN_PROJ * cfg::D_MODEL / 4;
        split_bf16_kernel<<<(n4 + 255) / 256, 256>>>(W_in, wih, wil, n4);
        n4 = cfg::D_MODEL * cfg::D_INNER / 4;
        split_bf16_kernel<<<(n4 + 255) / 256, 256>>>(W_out, woh, wol, n4);
    }
    // GEMM1: zx[8192,8384] = u @ W_in^T  (HMMA, 3-pass bf16)
    {
        dim3 grid(cfg::N1_PAD / 128, cfg::BL / 128);
        gemm_mma_kernel<<<grid, 256, mg::SMEM_BYTES>>>(uh, ul, wih, wil, zx,
                                                       cfg::BL, cfg::D_IN_PROJ, cfg::D_MODEL);
    }
    // conv + silu
    {
        int n = cfg::BL * cfg::D_XBC;
        conv_silu_kernel<<<(n + 255) / 256, 256>>>(zx, conv_w, conv_b, xbc);
    }
    // dt softplus
    {
        int n = cfg::BL * cfg::NHEADS;
        dt_kernel<<<(n + 255) / 256, 256>>>(zx, dt_bias, dtb);
    }
    // SSD scan
    {
        cudaFuncSetAttribute(ssd_kernel, cudaFuncAttributeMaxDynamicSharedMemorySize,
                             (int)sizeof(SsdSmem));
        ssd_kernel<<<cfg::BATCH * cfg::NHEADS, 256, sizeof(SsdSmem)>>>(
            xbc, dtb, A_log, D_param, yb);
    }
    // gate + rmsnorm -> bf16 hi/lo
    gate_norm_kernel<<<cfg::BL, 256>>>(yb, zx, norm_w, nmh, nml);
    // GEMM2: out[8192,2048] = nm @ W_out^T
    {
        dim3 grid(cfg::D_MODEL / 128, cfg::BL / 128);
        gemm_mma_kernel<<<grid, 256, mg::SMEM_BYTES>>>(nmh, nml, woh, wol, out,
                                                       cfg::BL, cfg::D_MODEL, cfg::D_INNER);
    }
}

// round 4
// speedup vs baseline: 2.9247x; 1.2268x over previous
#include <cuda_runtime.h>
#include <cuda_bf16.h>
#include <math.h>
#include <stdint.h>

// ---------------------------------------------------------------------------
// Problem constants (Mamba2 block, B=2, L=4096)
// ---------------------------------------------------------------------------
namespace cfg {
constexpr int D_MODEL   = 2048;
constexpr int D_INNER   = 4096;
constexpr int D_STATE   = 64;
constexpr int D_CONV    = 4;
constexpr int NHEADS    = 64;
constexpr int HEADDIM   = 64;
constexpr int D_XBC     = D_INNER + 2 * D_STATE;              // 4224
constexpr int D_IN_PROJ = 2 * D_INNER + 2 * D_STATE + NHEADS; // 8384
constexpr int LSEQ      = 4096;
constexpr int BATCH     = 2;
constexpr int BL        = BATCH * LSEQ;                       // 8192
constexpr int CHUNK     = 64;
constexpr int NCHUNK    = LSEQ / CHUNK;                       // 64
constexpr int NBH       = BATCH * NHEADS;                     // 128
constexpr int N1_PAD    = 8448;
}

// ---------------------------------------------------------------------------
// Scratch (allocation-free: __device__ globals; zero-init at load)
// ---------------------------------------------------------------------------
__device__ float g_zx [(size_t)cfg::BL * cfg::D_IN_PROJ];
__device__ float g_xbc[(size_t)cfg::BL * cfg::D_XBC];
__device__ float g_dt [(size_t)cfg::BL * cfg::NHEADS];
__device__ float g_y  [(size_t)cfg::BL * cfg::D_INNER];

// SSD intermediates
__device__ float g_G    [(size_t)cfg::NBH * cfg::NCHUNK * 64 * 64];
__device__ float g_sprev[(size_t)cfg::NBH * cfg::NCHUNK * 64 * 64];
__device__ float g_acum [(size_t)cfg::NBH * cfg::NCHUNK * 64];

__device__ __nv_bfloat16 g_uh [(size_t)cfg::BL * cfg::D_MODEL];
__device__ __nv_bfloat16 g_ul [(size_t)cfg::BL * cfg::D_MODEL];
__device__ __nv_bfloat16 g_wih[(size_t)cfg::N1_PAD * cfg::D_MODEL];   // pad rows zero
__device__ __nv_bfloat16 g_wil[(size_t)cfg::N1_PAD * cfg::D_MODEL];
__device__ __nv_bfloat16 g_nmh[(size_t)cfg::BL * cfg::D_INNER];
__device__ __nv_bfloat16 g_nml[(size_t)cfg::BL * cfg::D_INNER];
__device__ __nv_bfloat16 g_woh[(size_t)cfg::D_MODEL * cfg::D_INNER];
__device__ __nv_bfloat16 g_wol[(size_t)cfg::D_MODEL * cfg::D_INNER];

// ---------------------------------------------------------------------------
// PTX helpers (family-portable: mma.sync / ldmatrix / cp.async)
// ---------------------------------------------------------------------------
__device__ __forceinline__ uint32_t smem_u32(const void* p) {
    uint32_t a;
    asm("{ .reg .u64 t; cvta.to.shared.u64 t, %1; cvt.u32.u64 %0, t; }"
        : "=r"(a) : "l"(p));
    return a;
}
__device__ __forceinline__ void cp_async16(uint32_t dst, const void* src) {
    asm volatile("cp.async.cg.shared.global [%0], [%1], 16;"
                 :: "r"(dst), "l"(src) : "memory");
}
__device__ __forceinline__ void ldsm4(uint32_t r[4], uint32_t addr) {
    asm volatile("ldmatrix.sync.aligned.m8n8.x4.shared.b16 {%0,%1,%2,%3}, [%4];"
                 : "=r"(r[0]), "=r"(r[1]), "=r"(r[2]), "=r"(r[3]) : "r"(addr));
}
__device__ __forceinline__ void ldsm2(uint32_t r[2], uint32_t addr) {
    asm volatile("ldmatrix.sync.aligned.m8n8.x2.shared.b16 {%0,%1}, [%2];"
                 : "=r"(r[0]), "=r"(r[1]) : "r"(addr));
}
__device__ __forceinline__ void mma16816(float c[4], const uint32_t a[4],
                                         uint32_t b0, uint32_t b1) {
    asm volatile(
        "mma.sync.aligned.m16n8k16.row.col.f32.bf16.bf16.f32 "
        "{%0,%1,%2,%3}, {%4,%5,%6,%7}, {%8,%9}, {%0,%1,%2,%3};"
        : "+f"(c[0]), "+f"(c[1]), "+f"(c[2]), "+f"(c[3])
        : "r"(a[0]), "r"(a[1]), "r"(a[2]), "r"(a[3]), "r"(b0), "r"(b1));
}

// ---------------------------------------------------------------------------
// HMMA GEMM: C = (Ah+Al)*(Bh+Bl)^T, fp32 accum, 3-pass bf16 emulation.
// Block 128x128x32, 8 warps, warp tile 64x32. 2-stage cp.async pipeline,
// 2 CTAs/SM (64KB smem, <=128 regs).
// ---------------------------------------------------------------------------
namespace mg {
constexpr int PLANE = 128 * 32 * 2;          // 8192 B
constexpr int STAGE = 4 * PLANE;             // 32768 B (Ah, Al, Bh, Bl)
constexpr int STAGES = 2;
constexpr int SMEM_BYTES = STAGES * STAGE;   // 65536
}

__global__ __launch_bounds__(256, 2) void gemm_mma_kernel(
    const __nv_bfloat16* __restrict__ Ah, const __nv_bfloat16* __restrict__ Al,
    const __nv_bfloat16* __restrict__ Bh, const __nv_bfloat16* __restrict__ Bl,
    float* __restrict__ C, int M, int N, int K)
{
    extern __shared__ char smraw[];
    const uint32_t sb = smem_u32(smraw);
    const int tid  = threadIdx.x;
    const int bm   = blockIdx.y * 128;
    const int bn   = blockIdx.x * 128;
    const int wid  = tid >> 5, lane = tid & 31;
    const int wm   = wid & 1;
    const int wn   = wid >> 1;
    const int NK   = K >> 5;

    auto issue_load = [&](int stage, int kblk) {
        const uint32_t sbase = sb + stage * mg::STAGE;
        const int k0 = kblk * 32;
#pragma unroll
        for (int it = 0; it < 8; it++) {
            int id = it * 256 + tid;
            int p  = id >> 9;
            int c  = id & 511;
            int r  = c >> 2, g = c & 3;
            uint32_t dst = sbase + p * mg::PLANE + r * 64 +
                           ((g ^ ((r >> 1) & 3)) << 4);
            const __nv_bfloat16* src;
            if      (p == 0) src = Ah + (size_t)(bm + r) * K + k0 + g * 8;
            else if (p == 1) src = Al + (size_t)(bm + r) * K + k0 + g * 8;
            else if (p == 2) src = Bh + (size_t)(bn + r) * K + k0 + g * 8;
            else             src = Bl + (size_t)(bn + r) * K + k0 + g * 8;
            cp_async16(dst, src);
        }
    };

    float acc[4][4][4];
#pragma unroll
    for (int i = 0; i < 4; i++)
#pragma unroll
        for (int j = 0; j < 4; j++)
#pragma unroll
            for (int q = 0; q < 4; q++) acc[i][j][q] = 0.f;

    issue_load(0, 0);
    asm volatile("cp.async.commit_group;" ::: "memory");
    issue_load(1, 1);
    asm volatile("cp.async.commit_group;" ::: "memory");

    for (int kb = 0; kb < NK; kb++) {
        asm volatile("cp.async.wait_group 1;" ::: "memory");
        __syncthreads();

        const uint32_t st = sb + (kb & 1) * mg::STAGE;
        const uint32_t sAh = st, sAl = st + mg::PLANE;
        const uint32_t sBh = st + 2 * mg::PLANE, sBl = st + 3 * mg::PLANE;

#pragma unroll
        for (int ks = 0; ks < 2; ks++) {
            uint32_t bh[4][2], bl[4][2];
#pragma unroll
            for (int nt = 0; nt < 4; nt++) {
                int nr = wn * 32 + nt * 8 + (lane & 7);
                int g  = 2 * ks + ((lane >> 3) & 1);
                uint32_t off = nr * 64 + ((g ^ ((nr >> 1) & 3)) << 4);
                ldsm2(bh[nt], sBh + off);
                ldsm2(bl[nt], sBl + off);
            }
            uint32_t a[4][4];
#pragma unroll
            for (int mt = 0; mt < 4; mt++) {
                int ar = wm * 64 + mt * 16 + (lane & 15);
                int g  = ks * 2 + (lane >> 4);
                ldsm4(a[mt], sAh + ar * 64 + ((g ^ ((ar >> 1) & 3)) << 4));
            }
#pragma unroll
            for (int mt = 0; mt < 4; mt++)
#pragma unroll
                for (int nt = 0; nt < 4; nt++)
                    mma16816(acc[mt][nt], a[mt], bh[nt][0], bh[nt][1]);
#pragma unroll
            for (int mt = 0; mt < 4; mt++)
#pragma unroll
                for (int nt = 0; nt < 4; nt++)
                    mma16816(acc[mt][nt], a[mt], bl[nt][0], bl[nt][1]);
#pragma unroll
            for (int mt = 0; mt < 4; mt++) {
                int ar = wm * 64 + mt * 16 + (lane & 15);
                int g  = ks * 2 + (lane >> 4);
                ldsm4(a[mt], sAl + ar * 64 + ((g ^ ((ar >> 1) & 3)) << 4));
            }
#pragma unroll
            for (int mt = 0; mt < 4; mt++)
#pragma unroll
                for (int nt = 0; nt < 4; nt++)
                    mma16816(acc[mt][nt], a[mt], bh[nt][0], bh[nt][1]);
        }
        __syncthreads();
        if (kb + 2 < NK) issue_load(kb & 1, kb + 2);
        asm volatile("cp.async.commit_group;" ::: "memory");
    }

#pragma unroll
    for (int mt = 0; mt < 4; mt++) {
#pragma unroll
        for (int nt = 0; nt < 4; nt++) {
            int row = bm + wm * 64 + mt * 16 + (lane >> 2);
            int col = bn + wn * 32 + nt * 8 + (lane & 3) * 2;
            if (col < N) {
                *(float2*)(C + (size_t)row * N + col) =
                    make_float2(acc[mt][nt][0], acc[mt][nt][1]);
                *(float2*)(C + (size_t)(row + 8) * N + col) =
                    make_float2(acc[mt][nt][2], acc[mt][nt][3]);
            }
        }
    }
}

// ---------------------------------------------------------------------------
// fp32 -> bf16 (hi, lo) split
// ---------------------------------------------------------------------------
__global__ void split_bf16_kernel(const float* __restrict__ src,
                                  __nv_bfloat16* __restrict__ hi,
                                  __nv_bfloat16* __restrict__ lo, int n4)
{
    int i = blockIdx.x * blockDim.x + threadIdx.x;
    if (i >= n4) return;
    float4 v = ((const float4*)src)[i];
    __nv_bfloat16 h0 = __float2bfloat16(v.x), h1 = __float2bfloat16(v.y);
    __nv_bfloat16 h2 = __float2bfloat16(v.z), h3 = __float2bfloat16(v.w);
    __nv_bfloat16 l0 = __float2bfloat16(v.x - __bfloat162float(h0));
    __nv_bfloat16 l1 = __float2bfloat16(v.y - __bfloat162float(h1));
    __nv_bfloat16 l2 = __float2bfloat16(v.z - __bfloat162float(h2));
    __nv_bfloat16 l3 = __float2bfloat16(v.w - __bfloat162float(h3));
    ((__nv_bfloat162*)hi)[2 * i]     = __halves2bfloat162(h0, h1);
    ((__nv_bfloat162*)hi)[2 * i + 1] = __halves2bfloat162(h2, h3);
    ((__nv_bfloat162*)lo)[2 * i]     = __halves2bfloat162(l0, l1);
    ((__nv_bfloat162*)lo)[2 * i + 1] = __halves2bfloat162(l2, l3);
}

// ---------------------------------------------------------------------------
// Depthwise causal conv (width 4) + bias + silu;  dt softplus
// ---------------------------------------------------------------------------
__global__ void conv_silu_kernel(const float* __restrict__ zx,
                                 const float* __restrict__ cw,
                                 const float* __restrict__ cb,
                                 float* __restrict__ out)
{
    int idx = blockIdx.x * blockDim.x + threadIdx.x;
    if (idx >= cfg::BL * cfg::D_XBC) return;
    int j = idx % cfg::D_XBC;
    int t = idx / cfg::D_XBC;
    int l = t & (cfg::LSEQ - 1);
    int b = t >> 12;

    float v = cb[j];
#pragma unroll
    for (int k = 0; k < cfg::D_CONV; k++) {
        int ls = l + k - (cfg::D_CONV - 1);
        if (ls >= 0)
            v = fmaf(cw[j * cfg::D_CONV + k],
                     zx[(size_t)(b * cfg::LSEQ + ls) * cfg::D_IN_PROJ + cfg::D_INNER + j], v);
    }
    out[(size_t)t * cfg::D_XBC + j] = v / (1.f + expf(-v));
}

__global__ void dt_kernel(const float* __restrict__ zx,
                          const float* __restrict__ dt_bias,
                          float* __restrict__ out)
{
    int idx = blockIdx.x * blockDim.x + threadIdx.x;
    if (idx >= cfg::BL * cfg::NHEADS) return;
    int h = idx & 63;
    int t = idx >> 6;
    float x = zx[(size_t)t * cfg::D_IN_PROJ + cfg::D_INNER + cfg::D_XBC + h] + dt_bias[h];
    out[idx] = (x > 20.f) ? x : log1pf(expf(x));
}

// ---------------------------------------------------------------------------
// SSD pass 1: per (bh, chunk) — chunk state contribution G and Acum.
// grid = NBH * NCHUNK = 8192, 256 threads.
// ---------------------------------------------------------------------------
__global__ __launch_bounds__(256) void ssd_pass1(
    const float* __restrict__ xbc, const float* __restrict__ dtg,
    const float* __restrict__ A_log,
    float* __restrict__ G, float* __restrict__ acum)
{
    __shared__ float Bl[64][64], Xs[64][64];
    __shared__ float dAl[64], Acum[64], ws[64];
    const int blk = blockIdx.x;
    const int c = blk & 63, bh = blk >> 6;
    const int h = bh & 63, b = bh >> 6;
    const int tid = threadIdx.x;
    const float Aneg = -expf(A_log[h]);
    const int l0g = c * cfg::CHUNK;
    const int ty = tid >> 4, tx = tid & 15;

    for (int idx = tid; idx < 64 * 64; idx += 256) {
        int l = idx >> 6, q = idx & 63;
        size_t row = (size_t)(b * cfg::LSEQ + l0g + l);
        const float* xr = xbc + row * cfg::D_XBC;
        float dtv = dtg[row * cfg::NHEADS + h];
        Xs[l][q] = xr[h * cfg::HEADDIM + q] * dtv;
        Bl[l][q] = xr[cfg::D_INNER + q];
    }
    if (tid < 64) {
        size_t row = (size_t)(b * cfg::LSEQ + l0g + tid);
        dAl[tid] = Aneg * dtg[row * cfg::NHEADS + h];
    }
    __syncthreads();
    if (tid == 0) {
        float s = 0.f;
        for (int l = 0; l < 64; l++) { s += dAl[l]; Acum[l] = s; }
    }
    __syncthreads();
    if (tid < 64) {
        ws[tid] = expf(Acum[63] - Acum[tid]);
        acum[(size_t)blk * 64 + tid] = Acum[tid];
    }
    __syncthreads();

    // G[n][p] = sum_l ws[l] * Bl[l][n] * Xs[l][p]
    const int n0 = ty * 4, p0 = tx * 4;
    float sa[4][4];
#pragma unroll
    for (int i = 0; i < 4; i++)
#pragma unroll
        for (int j = 0; j < 4; j++) sa[i][j] = 0.f;
#pragma unroll 4
    for (int l = 0; l < 64; l++) {
        float w = ws[l];
        float4 av = *(const float4*)&Bl[l][n0];
        float4 bv = *(const float4*)&Xs[l][p0];
        float a[4] = {av.x * w, av.y * w, av.z * w, av.w * w};
        float bb[4] = {bv.x, bv.y, bv.z, bv.w};
#pragma unroll
        for (int i = 0; i < 4; i++)
#pragma unroll
            for (int j = 0; j < 4; j++) sa[i][j] = fmaf(a[i], bb[j], sa[i][j]);
    }
    float* gout = G + (size_t)blk * 4096;
#pragma unroll
    for (int i = 0; i < 4; i++)
        *(float4*)(gout + (n0 + i) * 64 + p0) =
            make_float4(sa[i][0], sa[i][1], sa[i][2], sa[i][3]);
}

// ---------------------------------------------------------------------------
// SSD pass 2: sequential scan of chunk states. grid = NBH = 128, 256 threads.
// sprev[c] = state entering chunk c; S <- exp(Acum63_c)*S + G_c.
// ---------------------------------------------------------------------------
__global__ __launch_bounds__(256) void ssd_pass2(
    const float* __restrict__ G, const float* __restrict__ acum,
    float* __restrict__ sprev)
{
    const int bh = blockIdx.x;
    const int tid = threadIdx.x;
    float4 S[4] = {make_float4(0, 0, 0, 0), make_float4(0, 0, 0, 0),
                   make_float4(0, 0, 0, 0), make_float4(0, 0, 0, 0)};
    for (int c = 0; c < cfg::NCHUNK; c++) {
        const size_t base = ((size_t)bh * cfg::NCHUNK + c) * 4096;
        const float ea = expf(acum[((size_t)bh * cfg::NCHUNK + c) * 64 + 63]);
#pragma unroll
        for (int k = 0; k < 4; k++) {
            int f4 = tid + k * 256;
            *(float4*)(sprev + base + f4 * 4) = S[k];
            float4 g = *(const float4*)(G + base + f4 * 4);
            S[k].x = ea * S[k].x + g.x;
            S[k].y = ea * S[k].y + g.y;
            S[k].z = ea * S[k].z + g.z;
            S[k].w = ea * S[k].w + g.w;
        }
    }
}

// ---------------------------------------------------------------------------
// SSD pass 3: per (bh, chunk) — Wt = masked decay CB, Y = Y_diag + Y_off + D*x.
// grid = 8192, 256 threads, dynamic smem.
// ---------------------------------------------------------------------------
struct P3Smem {
    float Bt[64][64], Ct[64][64], Xs[64][64], Xraw[64][64], Wt[64][64], Sp[64][64];
    float Acum[64], eA[64];
};

__global__ __launch_bounds__(256) void ssd_pass3(
    const float* __restrict__ xbc, const float* __restrict__ dtg,
    const float* __restrict__ D_param,
    const float* __restrict__ sprev, const float* __restrict__ acum,
    float* __restrict__ y)
{
    extern __shared__ char smraw[];
    P3Smem& sm = *reinterpret_cast<P3Smem*>(smraw);
    const int blk = blockIdx.x;
    const int c = blk & 63, bh = blk >> 6;
    const int h = bh & 63, b = bh >> 6;
    const int tid = threadIdx.x;
    const float Dh = D_param[h];
    const int l0g = c * cfg::CHUNK;
    const int ty = tid >> 4, tx = tid & 15;

    for (int idx = tid; idx < 64 * 64; idx += 256) {
        int l = idx >> 6, q = idx & 63;
        size_t row = (size_t)(b * cfg::LSEQ + l0g + l);
        const float* xr = xbc + row * cfg::D_XBC;
        float dtv = dtg[row * cfg::NHEADS + h];
        float xv  = xr[h * cfg::HEADDIM + q];
        sm.Xraw[l][q] = xv;
        sm.Xs[l][q]   = xv * dtv;
        sm.Bt[q][l]   = xr[cfg::D_INNER + q];
        sm.Ct[q][l]   = xr[cfg::D_INNER + cfg::D_STATE + q];
        (&sm.Sp[0][0])[idx] = sprev[(size_t)blk * 4096 + idx];
    }
    if (tid < 64) {
        float a = acum[(size_t)blk * 64 + tid];
        sm.Acum[tid] = a;
        sm.eA[tid]   = expf(a);
    }
    __syncthreads();

    // Wt[s][l] = (s<=l) ? (C_l . B_s) * exp(Acum[l]-Acum[s]) : 0
    {
        const int s0 = ty * 4, l0 = tx * 4;
        float acc[4][4];
#pragma unroll
        for (int i = 0; i < 4; i++)
#pragma unroll
            for (int j = 0; j < 4; j++) acc[i][j] = 0.f;
#pragma unroll 4
        for (int n = 0; n < 64; n++) {
            float4 av = *(const float4*)&sm.Bt[n][s0];
            float4 bv = *(const float4*)&sm.Ct[n][l0];
            float a[4] = {av.x, av.y, av.z, av.w};
            float bb[4] = {bv.x, bv.y, bv.z, bv.w};
#pragma unroll
            for (int i = 0; i < 4; i++)
#pragma unroll
                for (int j = 0; j < 4; j++) acc[i][j] = fmaf(a[i], bb[j], acc[i][j]);
        }
#pragma unroll
        for (int i = 0; i < 4; i++)
#pragma unroll
            for (int j = 0; j < 4; j++) {
                int s = s0 + i, l = l0 + j;
                float w = (s <= l) ? expf(sm.Acum[l] - sm.Acum[s]) : 0.f;
                sm.Wt[s][l] = acc[i][j] * w;
            }
    }
    __syncthreads();

    // Y[l][p] = sum_s Wt[s][l]*Xs[s][p] + eA[l]*sum_n Ct[n][l]*Sp[n][p] + Dh*Xraw
    {
        const int l0 = ty * 4, p0 = tx * 4;
        float yd[4][4], yo[4][4];
#pragma unroll
        for (int i = 0; i < 4; i++)
#pragma unroll
            for (int j = 0; j < 4; j++) { yd[i][j] = 0.f; yo[i][j] = 0.f; }
#pragma unroll 4
        for (int s = 0; s < 64; s++) {
            float4 av = *(const float4*)&sm.Wt[s][l0];
            float4 bv = *(const float4*)&sm.Xs[s][p0];
            float a[4] = {av.x, av.y, av.z, av.w};
            float bb[4] = {bv.x, bv.y, bv.z, bv.w};
#pragma unroll
            for (int i = 0; i < 4; i++)
#pragma unroll
                for (int j = 0; j < 4; j++) yd[i][j] = fmaf(a[i], bb[j], yd[i][j]);
        }
#pragma unroll 4
        for (int n = 0; n < 64; n++) {
            float4 av = *(const float4*)&sm.Ct[n][l0];
            float4 bv = *(const float4*)&sm.Sp[n][p0];
            float a[4] = {av.x, av.y, av.z, av.w};
            float bb[4] = {bv.x, bv.y, bv.z, bv.w};
#pragma unroll
            for (int i = 0; i < 4; i++)
#pragma unroll
                for (int j = 0; j < 4; j++) yo[i][j] = fmaf(a[i], bb[j], yo[i][j]);
        }
#pragma unroll
        for (int i = 0; i < 4; i++) {
            int l = l0 + i;
            size_t row = (size_t)(b * cfg::LSEQ + l0g + l);
            float ea = sm.eA[l];
            float4 o;
            o.x = yd[i][0] + ea * yo[i][0] + Dh * sm.Xraw[l][p0 + 0];
            o.y = yd[i][1] + ea * yo[i][1] + Dh * sm.Xraw[l][p0 + 1];
            o.z = yd[i][2] + ea * yo[i][2] + Dh * sm.Xraw[l][p0 + 2];
            o.w = yd[i][3] + ea * yo[i][3] + Dh * sm.Xraw[l][p0 + 3];
            *(float4*)(y + row * cfg::D_INNER + h * cfg::HEADDIM + p0) = o;
        }
    }
}

// ---------------------------------------------------------------------------
// gate + RMSNorm -> bf16 hi/lo
// ---------------------------------------------------------------------------
__global__ __launch_bounds__(256) void gate_norm_kernel(
    const float* __restrict__ y, const float* __restrict__ zx,
    const float* __restrict__ nw,
    __nv_bfloat16* __restrict__ nmh, __nv_bfloat16* __restrict__ nml)
{
    __shared__ float gbuf[cfg::D_INNER];
    __shared__ float red[8];
    const int t = blockIdx.x;
    const int tid = threadIdx.x;
    const float* yr = y + (size_t)t * cfg::D_INNER;
    const float* zr = zx + (size_t)t * cfg::D_IN_PROJ;

    float ss = 0.f;
    for (int i = tid; i < cfg::D_INNER; i += 256) {
        float zv = zr[i];
        float gv = yr[i] * (zv / (1.f + expf(-zv)));
        gbuf[i] = gv;
        ss = fmaf(gv, gv, ss);
    }
#pragma unroll
    for (int o = 16; o; o >>= 1) ss += __shfl_xor_sync(0xffffffffu, ss, o);
    if ((tid & 31) == 0) red[tid >> 5] = ss;
    __syncthreads();
    if (tid < 32) {
        float v = (tid < 8) ? red[tid] : 0.f;
#pragma unroll
        for (int o = 4; o; o >>= 1) v += __shfl_xor_sync(0xffffffffu, v, o);
        if (tid == 0) red[0] = v;
    }
    __syncthreads();
    const float scale = rsqrtf(red[0] * (1.f / cfg::D_INNER) + 1e-5f);
    for (int i = tid; i < cfg::D_INNER; i += 256) {
        float val = gbuf[i] * scale * nw[i];
        __nv_bfloat16 h = __float2bfloat16(val);
        size_t idx = (size_t)t * cfg::D_INNER + i;
        nmh[idx] = h;
        nml[idx] = __float2bfloat16(val - __bfloat162float(h));
    }
}

// ---------------------------------------------------------------------------
// Host launch
// ---------------------------------------------------------------------------
extern "C" void kernel_launch(void* const* d_in, const int* in_sizes, int n_in,
                              void* d_out, int out_size)
{
    (void)in_sizes; (void)n_in; (void)out_size;
    const float* u       = (const float*)d_in[0];
    const float* W_in    = (const float*)d_in[1];
    const float* conv_w  = (const float*)d_in[2];
    const float* conv_b  = (const float*)d_in[3];
    const float* dt_bias = (const float*)d_in[4];
    const float* A_log   = (const float*)d_in[5];
    const float* D_param = (const float*)d_in[6];
    const float* norm_w  = (const float*)d_in[7];
    const float* W_out   = (const float*)d_in[8];
    float* out = (float*)d_out;

    void *pzx, *pxbc, *pdt, *py, *pG, *psp, *pac;
    void *puh, *pul, *pwih, *pwil, *pnmh, *pnml, *pwoh, *pwol;
    cudaGetSymbolAddress(&pzx,  g_zx);
    cudaGetSymbolAddress(&pxbc, g_xbc);
    cudaGetSymbolAddress(&pdt,  g_dt);
    cudaGetSymbolAddress(&py,   g_y);
    cudaGetSymbolAddress(&pG,   g_G);
    cudaGetSymbolAddress(&psp,  g_sprev);
    cudaGetSymbolAddress(&pac,  g_acum);
    cudaGetSymbolAddress(&puh,  g_uh);
    cudaGetSymbolAddress(&pul,  g_ul);
    cudaGetSymbolAddress(&pwih, g_wih);
    cudaGetSymbolAddress(&pwil, g_wil);
    cudaGetSymbolAddress(&pnmh, g_nmh);
    cudaGetSymbolAddress(&pnml, g_nml);
    cudaGetSymbolAddress(&pwoh, g_woh);
    cudaGetSymbolAddress(&pwol, g_wol);
    float* zx  = (float*)pzx;
    float* xbc = (float*)pxbc;
    float* dtb = (float*)pdt;
    float* yb  = (float*)py;
    float* Gb  = (float*)pG;
    float* spb = (float*)psp;
    float* acb = (float*)pac;
    __nv_bfloat16* uh  = (__nv_bfloat16*)puh;
    __nv_bfloat16* ul  = (__nv_bfloat16*)pul;
    __nv_bfloat16* wih = (__nv_bfloat16*)pwih;
    __nv_bfloat16* wil = (__nv_bfloat16*)pwil;
    __nv_bfloat16* nmh = (__nv_bfloat16*)pnmh;
    __nv_bfloat16* nml = (__nv_bfloat16*)pnml;
    __nv_bfloat16* woh = (__nv_bfloat16*)pwoh;
    __nv_bfloat16* wol = (__nv_bfloat16*)pwol;

    cudaFuncSetAttribute(gemm_mma_kernel, cudaFuncAttributeMaxDynamicSharedMemorySize,
                         mg::SMEM_BYTES);
    cudaFuncSetAttribute(ssd_pass3, cudaFuncAttributeMaxDynamicSharedMemorySize,
                         (int)sizeof(P3Smem));

    // fp32 -> bf16 hi/lo splits
    {
        int n4 = cfg::BL * cfg::D_MODEL / 4;
        split_bf16_kernel<<<(n4 + 255) / 256, 256>>>(u, uh, ul, n4);
        n4 = cfg::D_IN_PROJ * cfg::D_MODEL / 4;
        split_bf16_kernel<<<(n4 + 255) / 256, 256>>>(W_in, wih, wil, n4);
        n4 = cfg::D_MODEL * cfg::D_INNER / 4;
        split_bf16_kernel<<<(n4 + 255) / 256, 256>>>(W_out, woh, wol, n4);
    }
    // GEMM1: zx = u @ W_in^T
    {
        dim3 grid(cfg::N1_PAD / 128, cfg::BL / 128);
        gemm_mma_kernel<<<grid, 256, mg::SMEM_BYTES>>>(uh, ul, wih, wil, zx,
                                                       cfg::BL, cfg::D_IN_PROJ, cfg::D_MODEL);
    }
    // conv + silu; dt softplus
    {
        int n = cfg::BL * cfg::D_XBC;
        conv_silu_kernel<<<(n + 255) / 256, 256>>>(zx, conv_w, conv_b, xbc);
        n = cfg::BL * cfg::NHEADS;
        dt_kernel<<<(n + 255) / 256, 256>>>(zx, dt_bias, dtb);
    }
    // SSD: 3 passes
    ssd_pass1<<<cfg::NBH * cfg::NCHUNK, 256>>>(xbc, dtb, A_log, Gb, acb);
    ssd_pass2<<<cfg::NBH, 256>>>(Gb, acb, spb);
    ssd_pass3<<<cfg::NBH * cfg::NCHUNK, 256, sizeof(P3Smem)>>>(
        xbc, dtb, D_param, spb, acb, yb);
    // gate + rmsnorm -> bf16 hi/lo
    gate_norm_kernel<<<cfg::BL, 256>>>(yb, zx, norm_w, nmh, nml);
    // GEMM2: out = nm @ W_out^T
    {
        dim3 grid(cfg::D_MODEL / 128, cfg::BL / 128);
        gemm_mma_kernel<<<grid, 256, mg::SMEM_BYTES>>>(nmh, nml, woh, wol, out,
                                                       cfg::BL, cfg::D_MODEL, cfg::D_INNER);
    }
}

// round 5
// speedup vs baseline: 2.9457x; 1.0072x over previous
#include <cuda_runtime.h>
#include <cuda_bf16.h>
#include <math.h>
#include <stdint.h>

// ---------------------------------------------------------------------------
// Problem constants (Mamba2 block, B=2, L=4096)
// ---------------------------------------------------------------------------
namespace cfg {
constexpr int D_MODEL   = 2048;
constexpr int D_INNER   = 4096;
constexpr int D_STATE   = 64;
constexpr int D_CONV    = 4;
constexpr int NHEADS    = 64;
constexpr int HEADDIM   = 64;
constexpr int D_XBC     = D_INNER + 2 * D_STATE;              // 4224
constexpr int D_IN_PROJ = 2 * D_INNER + 2 * D_STATE + NHEADS; // 8384
constexpr int LSEQ      = 4096;
constexpr int BATCH     = 2;
constexpr int BL        = BATCH * LSEQ;                       // 8192
constexpr int CHUNK     = 64;
constexpr int NCHUNK    = LSEQ / CHUNK;                       // 64
constexpr int NBH       = BATCH * NHEADS;                     // 128
constexpr int N1_PAD    = 8448;
}

// ---------------------------------------------------------------------------
// Scratch (allocation-free: __device__ globals; zero-init at load)
// ---------------------------------------------------------------------------
__device__ float g_zx [(size_t)cfg::BL * cfg::D_IN_PROJ];
__device__ float g_xbc[(size_t)cfg::BL * cfg::D_XBC];
__device__ float g_dt [(size_t)cfg::BL * cfg::NHEADS];
__device__ float g_y  [(size_t)cfg::BL * cfg::D_INNER];

// SSD intermediates
__device__ float g_G    [(size_t)cfg::NBH * cfg::NCHUNK * 64 * 64];
__device__ float g_sprev[(size_t)cfg::NBH * cfg::NCHUNK * 64 * 64];
__device__ float g_acum [(size_t)cfg::NBH * cfg::NCHUNK * 64];

__device__ __nv_bfloat16 g_uh [(size_t)cfg::BL * cfg::D_MODEL];
__device__ __nv_bfloat16 g_ul [(size_t)cfg::BL * cfg::D_MODEL];
__device__ __nv_bfloat16 g_wih[(size_t)cfg::N1_PAD * cfg::D_MODEL];   // pad rows zero
__device__ __nv_bfloat16 g_wil[(size_t)cfg::N1_PAD * cfg::D_MODEL];
__device__ __nv_bfloat16 g_nmh[(size_t)cfg::BL * cfg::D_INNER];
__device__ __nv_bfloat16 g_nml[(size_t)cfg::BL * cfg::D_INNER];
__device__ __nv_bfloat16 g_woh[(size_t)cfg::D_MODEL * cfg::D_INNER];
__device__ __nv_bfloat16 g_wol[(size_t)cfg::D_MODEL * cfg::D_INNER];

// ---------------------------------------------------------------------------
// PTX helpers (family-portable: mma.sync / ldmatrix / cp.async)
// ---------------------------------------------------------------------------
__device__ __forceinline__ uint32_t smem_u32(const void* p) {
    uint32_t a;
    asm("{ .reg .u64 t; cvta.to.shared.u64 t, %1; cvt.u32.u64 %0, t; }"
        : "=r"(a) : "l"(p));
    return a;
}
__device__ __forceinline__ void cp_async16(uint32_t dst, const void* src) {
    asm volatile("cp.async.cg.shared.global [%0], [%1], 16;"
                 :: "r"(dst), "l"(src) : "memory");
}
__device__ __forceinline__ void ldsm4(uint32_t r[4], uint32_t addr) {
    asm volatile("ldmatrix.sync.aligned.m8n8.x4.shared.b16 {%0,%1,%2,%3}, [%4];"
                 : "=r"(r[0]), "=r"(r[1]), "=r"(r[2]), "=r"(r[3]) : "r"(addr));
}
__device__ __forceinline__ void ldsm2(uint32_t r[2], uint32_t addr) {
    asm volatile("ldmatrix.sync.aligned.m8n8.x2.shared.b16 {%0,%1}, [%2];"
                 : "=r"(r[0]), "=r"(r[1]) : "r"(addr));
}
__device__ __forceinline__ void mma16816(float c[4], const uint32_t a[4],
                                         uint32_t b0, uint32_t b1) {
    asm volatile(
        "mma.sync.aligned.m16n8k16.row.col.f32.bf16.bf16.f32 "
        "{%0,%1,%2,%3}, {%4,%5,%6,%7}, {%8,%9}, {%0,%1,%2,%3};"
        : "+f"(c[0]), "+f"(c[1]), "+f"(c[2]), "+f"(c[3])
        : "r"(a[0]), "r"(a[1]), "r"(a[2]), "r"(a[3]), "r"(b0), "r"(b1));
}

// ---------------------------------------------------------------------------
// HMMA GEMM: C = (Ah+Al)*(Bh+Bl)^T, fp32 accum, 3-pass bf16 emulation.
// Block 128x128x32, 8 warps, warp tile 64x32. 3-stage cp.async pipeline,
// 2 CTAs/SM (96KB smem/CTA, <=128 regs).
// ---------------------------------------------------------------------------
namespace mg {
constexpr int PLANE = 128 * 32 * 2;          // 8192 B
constexpr int STAGE = 4 * PLANE;             // 32768 B (Ah, Al, Bh, Bl)
constexpr int STAGES = 3;
constexpr int SMEM_BYTES = STAGES * STAGE;   // 98304
}

__global__ __launch_bounds__(256, 2) void gemm_mma_kernel(
    const __nv_bfloat16* __restrict__ Ah, const __nv_bfloat16* __restrict__ Al,
    const __nv_bfloat16* __restrict__ Bh, const __nv_bfloat16* __restrict__ Bl,
    float* __restrict__ C, int M, int N, int K)
{
    extern __shared__ char smraw[];
    const uint32_t sb = smem_u32(smraw);
    const int tid  = threadIdx.x;
    const int bm   = blockIdx.y * 128;
    const int bn   = blockIdx.x * 128;
    const int wid  = tid >> 5, lane = tid & 31;
    const int wm   = wid & 1;
    const int wn   = wid >> 1;
    const int NK   = K >> 5;

    auto issue_load = [&](int stage, int kblk) {
        const uint32_t sbase = sb + stage * mg::STAGE;
        const int k0 = kblk * 32;
#pragma unroll
        for (int it = 0; it < 8; it++) {
            int id = it * 256 + tid;
            int p  = id >> 9;
            int c  = id & 511;
            int r  = c >> 2, g = c & 3;
            uint32_t dst = sbase + p * mg::PLANE + r * 64 +
                           ((g ^ ((r >> 1) & 3)) << 4);
            const __nv_bfloat16* src;
            if      (p == 0) src = Ah + (size_t)(bm + r) * K + k0 + g * 8;
            else if (p == 1) src = Al + (size_t)(bm + r) * K + k0 + g * 8;
            else if (p == 2) src = Bh + (size_t)(bn + r) * K + k0 + g * 8;
            else             src = Bl + (size_t)(bn + r) * K + k0 + g * 8;
            cp_async16(dst, src);
        }
    };

    float acc[4][4][4];
#pragma unroll
    for (int i = 0; i < 4; i++)
#pragma unroll
        for (int j = 0; j < 4; j++)
#pragma unroll
            for (int q = 0; q < 4; q++) acc[i][j][q] = 0.f;

#pragma unroll
    for (int s = 0; s < mg::STAGES; s++) {
        issue_load(s, s);
        asm volatile("cp.async.commit_group;" ::: "memory");
    }

    for (int kb = 0; kb < NK; kb++) {
        asm volatile("cp.async.wait_group 2;" ::: "memory");
        __syncthreads();

        const uint32_t st = sb + (kb % mg::STAGES) * mg::STAGE;
        const uint32_t sAh = st, sAl = st + mg::PLANE;
        const uint32_t sBh = st + 2 * mg::PLANE, sBl = st + 3 * mg::PLANE;

#pragma unroll
        for (int ks = 0; ks < 2; ks++) {
            uint32_t bh[4][2], bl[4][2];
#pragma unroll
            for (int nt = 0; nt < 4; nt++) {
                int nr = wn * 32 + nt * 8 + (lane & 7);
                int g  = 2 * ks + ((lane >> 3) & 1);
                uint32_t off = nr * 64 + ((g ^ ((nr >> 1) & 3)) << 4);
                ldsm2(bh[nt], sBh + off);
                ldsm2(bl[nt], sBl + off);
            }
            uint32_t a[4][4];
#pragma unroll
            for (int mt = 0; mt < 4; mt++) {
                int ar = wm * 64 + mt * 16 + (lane & 15);
                int g  = ks * 2 + (lane >> 4);
                ldsm4(a[mt], sAh + ar * 64 + ((g ^ ((ar >> 1) & 3)) << 4));
            }
#pragma unroll
            for (int mt = 0; mt < 4; mt++)
#pragma unroll
                for (int nt = 0; nt < 4; nt++)
                    mma16816(acc[mt][nt], a[mt], bh[nt][0], bh[nt][1]);
#pragma unroll
            for (int mt = 0; mt < 4; mt++)
#pragma unroll
                for (int nt = 0; nt < 4; nt++)
                    mma16816(acc[mt][nt], a[mt], bl[nt][0], bl[nt][1]);
#pragma unroll
            for (int mt = 0; mt < 4; mt++) {
                int ar = wm * 64 + mt * 16 + (lane & 15);
                int g  = ks * 2 + (lane >> 4);
                ldsm4(a[mt], sAl + ar * 64 + ((g ^ ((ar >> 1) & 3)) << 4));
            }
#pragma unroll
            for (int mt = 0; mt < 4; mt++)
#pragma unroll
                for (int nt = 0; nt < 4; nt++)
                    mma16816(acc[mt][nt], a[mt], bh[nt][0], bh[nt][1]);
        }
        __syncthreads();
        if (kb + mg::STAGES < NK) issue_load(kb % mg::STAGES, kb + mg::STAGES);
        asm volatile("cp.async.commit_group;" ::: "memory");
    }

#pragma unroll
    for (int mt = 0; mt < 4; mt++) {
#pragma unroll
        for (int nt = 0; nt < 4; nt++) {
            int row = bm + wm * 64 + mt * 16 + (lane >> 2);
            int col = bn + wn * 32 + nt * 8 + (lane & 3) * 2;
            if (col < N) {
                *(float2*)(C + (size_t)row * N + col) =
                    make_float2(acc[mt][nt][0], acc[mt][nt][1]);
                *(float2*)(C + (size_t)(row + 8) * N + col) =
                    make_float2(acc[mt][nt][2], acc[mt][nt][3]);
            }
        }
    }
}

// ---------------------------------------------------------------------------
// fp32 -> bf16 (hi, lo) split
// ---------------------------------------------------------------------------
__global__ void split_bf16_kernel(const float* __restrict__ src,
                                  __nv_bfloat16* __restrict__ hi,
                                  __nv_bfloat16* __restrict__ lo, int n4)
{
    int i = blockIdx.x * blockDim.x + threadIdx.x;
    if (i >= n4) return;
    float4 v = ((const float4*)src)[i];
    __nv_bfloat16 h0 = __float2bfloat16(v.x), h1 = __float2bfloat16(v.y);
    __nv_bfloat16 h2 = __float2bfloat16(v.z), h3 = __float2bfloat16(v.w);
    __nv_bfloat16 l0 = __float2bfloat16(v.x - __bfloat162float(h0));
    __nv_bfloat16 l1 = __float2bfloat16(v.y - __bfloat162float(h1));
    __nv_bfloat16 l2 = __float2bfloat16(v.z - __bfloat162float(h2));
    __nv_bfloat16 l3 = __float2bfloat16(v.w - __bfloat162float(h3));
    ((__nv_bfloat162*)hi)[2 * i]     = __halves2bfloat162(h0, h1);
    ((__nv_bfloat162*)hi)[2 * i + 1] = __halves2bfloat162(h2, h3);
    ((__nv_bfloat162*)lo)[2 * i]     = __halves2bfloat162(l0, l1);
    ((__nv_bfloat162*)lo)[2 * i + 1] = __halves2bfloat162(l2, l3);
}

// ---------------------------------------------------------------------------
// Depthwise causal conv (width 4) + bias + silu;  dt softplus
// ---------------------------------------------------------------------------
__global__ void conv_silu_kernel(const float* __restrict__ zx,
                                 const float* __restrict__ cw,
                                 const float* __restrict__ cb,
                                 float* __restrict__ out)
{
    int idx = blockIdx.x * blockDim.x + threadIdx.x;
    if (idx >= cfg::BL * cfg::D_XBC) return;
    int j = idx % cfg::D_XBC;
    int t = idx / cfg::D_XBC;
    int l = t & (cfg::LSEQ - 1);
    int b = t >> 12;

    float v = cb[j];
#pragma unroll
    for (int k = 0; k < cfg::D_CONV; k++) {
        int ls = l + k - (cfg::D_CONV - 1);
        if (ls >= 0)
            v = fmaf(cw[j * cfg::D_CONV + k],
                     zx[(size_t)(b * cfg::LSEQ + ls) * cfg::D_IN_PROJ + cfg::D_INNER + j], v);
    }
    out[(size_t)t * cfg::D_XBC + j] = v / (1.f + expf(-v));
}

__global__ void dt_kernel(const float* __restrict__ zx,
                          const float* __restrict__ dt_bias,
                          float* __restrict__ out)
{
    int idx = blockIdx.x * blockDim.x + threadIdx.x;
    if (idx >= cfg::BL * cfg::NHEADS) return;
    int h = idx & 63;
    int t = idx >> 6;
    float x = zx[(size_t)t * cfg::D_IN_PROJ + cfg::D_INNER + cfg::D_XBC + h] + dt_bias[h];
    out[idx] = (x > 20.f) ? x : log1pf(expf(x));
}

// ---------------------------------------------------------------------------
// SSD pass 1: per (bh, chunk) — chunk state contribution G and Acum.
// ---------------------------------------------------------------------------
__global__ __launch_bounds__(256) void ssd_pass1(
    const float* __restrict__ xbc, const float* __restrict__ dtg,
    const float* __restrict__ A_log,
    float* __restrict__ G, float* __restrict__ acum)
{
    __shared__ float Bl[64][64], Xs[64][64];
    __shared__ float dAl[64], Acum[64], ws[64];
    const int blk = blockIdx.x;
    const int c = blk & 63, bh = blk >> 6;
    const int h = bh & 63, b = bh >> 6;
    const int tid = threadIdx.x;
    const float Aneg = -expf(A_log[h]);
    const int l0g = c * cfg::CHUNK;
    const int ty = tid >> 4, tx = tid & 15;

    for (int idx = tid; idx < 64 * 64; idx += 256) {
        int l = idx >> 6, q = idx & 63;
        size_t row = (size_t)(b * cfg::LSEQ + l0g + l);
        const float* xr = xbc + row * cfg::D_XBC;
        float dtv = dtg[row * cfg::NHEADS + h];
        Xs[l][q] = xr[h * cfg::HEADDIM + q] * dtv;
        Bl[l][q] = xr[cfg::D_INNER + q];
    }
    if (tid < 64) {
        size_t row = (size_t)(b * cfg::LSEQ + l0g + tid);
        dAl[tid] = Aneg * dtg[row * cfg::NHEADS + h];
    }
    __syncthreads();
    if (tid == 0) {
        float s = 0.f;
        for (int l = 0; l < 64; l++) { s += dAl[l]; Acum[l] = s; }
    }
    __syncthreads();
    if (tid < 64) {
        ws[tid] = expf(Acum[63] - Acum[tid]);
        acum[(size_t)blk * 64 + tid] = Acum[tid];
    }
    __syncthreads();

    const int n0 = ty * 4, p0 = tx * 4;
    float sa[4][4];
#pragma unroll
    for (int i = 0; i < 4; i++)
#pragma unroll
        for (int j = 0; j < 4; j++) sa[i][j] = 0.f;
#pragma unroll 4
    for (int l = 0; l < 64; l++) {
        float w = ws[l];
        float4 av = *(const float4*)&Bl[l][n0];
        float4 bv = *(const float4*)&Xs[l][p0];
        float a[4] = {av.x * w, av.y * w, av.z * w, av.w * w};
        float bb[4] = {bv.x, bv.y, bv.z, bv.w};
#pragma unroll
        for (int i = 0; i < 4; i++)
#pragma unroll
            for (int j = 0; j < 4; j++) sa[i][j] = fmaf(a[i], bb[j], sa[i][j]);
    }
    float* gout = G + (size_t)blk * 4096;
#pragma unroll
    for (int i = 0; i < 4; i++)
        *(float4*)(gout + (n0 + i) * 64 + p0) =
            make_float4(sa[i][0], sa[i][1], sa[i][2], sa[i][3]);
}

// ---------------------------------------------------------------------------
// SSD pass 2: elementwise chunk-state scan. grid = NBH*4 = 512, 256 threads;
// each block scans a 1024-element slice of the 64x64 state.
// ---------------------------------------------------------------------------
__global__ __launch_bounds__(256) void ssd_pass2(
    const float* __restrict__ G, const float* __restrict__ acum,
    float* __restrict__ sprev)
{
    __shared__ float eAc[cfg::NCHUNK];
    const int bh    = blockIdx.x >> 2;
    const int slice = blockIdx.x & 3;
    const int tid   = threadIdx.x;
    if (tid < cfg::NCHUNK)
        eAc[tid] = expf(acum[((size_t)bh * cfg::NCHUNK + tid) * 64 + 63]);
    __syncthreads();

    const int f4 = slice * 256 + tid;   // float4 index within 4096-elem state
    float4 S = make_float4(0.f, 0.f, 0.f, 0.f);
    const size_t bhbase = (size_t)bh * cfg::NCHUNK * 4096;
    for (int c = 0; c < cfg::NCHUNK; c++) {
        const size_t base = bhbase + (size_t)c * 4096 + f4 * 4;
        *(float4*)(sprev + base) = S;
        float4 g = *(const float4*)(G + base);
        float ea = eAc[c];
        S.x = fmaf(ea, S.x, g.x);
        S.y = fmaf(ea, S.y, g.y);
        S.z = fmaf(ea, S.z, g.z);
        S.w = fmaf(ea, S.w, g.w);
    }
}

// ---------------------------------------------------------------------------
// SSD pass 3: per (bh, chunk) — Wt = masked decay CB, Y = Y_diag + Y_off + D*x.
// ---------------------------------------------------------------------------
struct P3Smem {
    float Bt[64][64], Ct[64][64], Xs[64][64], Xraw[64][64], Wt[64][64], Sp[64][64];
    float Acum[64], eA[64];
};

__global__ __launch_bounds__(256) void ssd_pass3(
    const float* __restrict__ xbc, const float* __restrict__ dtg,
    const float* __restrict__ D_param,
    const float* __restrict__ sprev, const float* __restrict__ acum,
    float* __restrict__ y)
{
    extern __shared__ char smraw[];
    P3Smem& sm = *reinterpret_cast<P3Smem*>(smraw);
    const int blk = blockIdx.x;
    const int c = blk & 63, bh = blk >> 6;
    const int h = bh & 63, b = bh >> 6;
    const int tid = threadIdx.x;
    const float Dh = D_param[h];
    const int l0g = c * cfg::CHUNK;
    const int ty = tid >> 4, tx = tid & 15;

    for (int idx = tid; idx < 64 * 64; idx += 256) {
        int l = idx >> 6, q = idx & 63;
        size_t row = (size_t)(b * cfg::LSEQ + l0g + l);
        const float* xr = xbc + row * cfg::D_XBC;
        float dtv = dtg[row * cfg::NHEADS + h];
        float xv  = xr[h * cfg::HEADDIM + q];
        sm.Xraw[l][q] = xv;
        sm.Xs[l][q]   = xv * dtv;
        sm.Bt[q][l]   = xr[cfg::D_INNER + q];
        sm.Ct[q][l]   = xr[cfg::D_INNER + cfg::D_STATE + q];
        (&sm.Sp[0][0])[idx] = sprev[(size_t)blk * 4096 + idx];
    }
    if (tid < 64) {
        float a = acum[(size_t)blk * 64 + tid];
        sm.Acum[tid] = a;
        sm.eA[tid]   = expf(a);
    }
    __syncthreads();

    {
        const int s0 = ty * 4, l0 = tx * 4;
        float acc[4][4];
#pragma unroll
        for (int i = 0; i < 4; i++)
#pragma unroll
            for (int j = 0; j < 4; j++) acc[i][j] = 0.f;
#pragma unroll 4
        for (int n = 0; n < 64; n++) {
            float4 av = *(const float4*)&sm.Bt[n][s0];
            float4 bv = *(const float4*)&sm.Ct[n][l0];
            float a[4] = {av.x, av.y, av.z, av.w};
            float bb[4] = {bv.x, bv.y, bv.z, bv.w};
#pragma unroll
            for (int i = 0; i < 4; i++)
#pragma unroll
                for (int j = 0; j < 4; j++) acc[i][j] = fmaf(a[i], bb[j], acc[i][j]);
        }
#pragma unroll
        for (int i = 0; i < 4; i++)
#pragma unroll
            for (int j = 0; j < 4; j++) {
                int s = s0 + i, l = l0 + j;
                float w = (s <= l) ? expf(sm.Acum[l] - sm.Acum[s]) : 0.f;
                sm.Wt[s][l] = acc[i][j] * w;
            }
    }
    __syncthreads();

    {
        const int l0 = ty * 4, p0 = tx * 4;
        float yd[4][4], yo[4][4];
#pragma unroll
        for (int i = 0; i < 4; i++)
#pragma unroll
            for (int j = 0; j < 4; j++) { yd[i][j] = 0.f; yo[i][j] = 0.f; }
#pragma unroll 4
        for (int s = 0; s < 64; s++) {
            float4 av = *(const float4*)&sm.Wt[s][l0];
            float4 bv = *(const float4*)&sm.Xs[s][p0];
            float a[4] = {av.x, av.y, av.z, av.w};
            float bb[4] = {bv.x, bv.y, bv.z, bv.w};
#pragma unroll
            for (int i = 0; i < 4; i++)
#pragma unroll
                for (int j = 0; j < 4; j++) yd[i][j] = fmaf(a[i], bb[j], yd[i][j]);
        }
#pragma unroll 4
        for (int n = 0; n < 64; n++) {
            float4 av = *(const float4*)&sm.Ct[n][l0];
            float4 bv = *(const float4*)&sm.Sp[n][p0];
            float a[4] = {av.x, av.y, av.z, av.w};
            float bb[4] = {bv.x, bv.y, bv.z, bv.w};
#pragma unroll
            for (int i = 0; i < 4; i++)
#pragma unroll
                for (int j = 0; j < 4; j++) yo[i][j] = fmaf(a[i], bb[j], yo[i][j]);
        }
#pragma unroll
        for (int i = 0; i < 4; i++) {
            int l = l0 + i;
            size_t row = (size_t)(b * cfg::LSEQ + l0g + l);
            float ea = sm.eA[l];
            float4 o;
            o.x = yd[i][0] + ea * yo[i][0] + Dh * sm.Xraw[l][p0 + 0];
            o.y = yd[i][1] + ea * yo[i][1] + Dh * sm.Xraw[l][p0 + 1];
            o.z = yd[i][2] + ea * yo[i][2] + Dh * sm.Xraw[l][p0 + 2];
            o.w = yd[i][3] + ea * yo[i][3] + Dh * sm.Xraw[l][p0 + 3];
            *(float4*)(y + row * cfg::D_INNER + h * cfg::HEADDIM + p0) = o;
        }
    }
}

// ---------------------------------------------------------------------------
// gate + RMSNorm -> bf16 hi/lo
// ---------------------------------------------------------------------------
__global__ __launch_bounds__(256) void gate_norm_kernel(
    const float* __restrict__ y, const float* __restrict__ zx,
    const float* __restrict__ nw,
    __nv_bfloat16* __restrict__ nmh, __nv_bfloat16* __restrict__ nml)
{
    __shared__ float gbuf[cfg::D_INNER];
    __shared__ float red[8];
    const int t = blockIdx.x;
    const int tid = threadIdx.x;
    const float* yr = y + (size_t)t * cfg::D_INNER;
    const float* zr = zx + (size_t)t * cfg::D_IN_PROJ;

    float ss = 0.f;
    for (int i = tid; i < cfg::D_INNER; i += 256) {
        float zv = zr[i];
        float gv = yr[i] * (zv / (1.f + expf(-zv)));
        gbuf[i] = gv;
        ss = fmaf(gv, gv, ss);
    }
#pragma unroll
    for (int o = 16; o; o >>= 1) ss += __shfl_xor_sync(0xffffffffu, ss, o);
    if ((tid & 31) == 0) red[tid >> 5] = ss;
    __syncthreads();
    if (tid < 32) {
        float v = (tid < 8) ? red[tid] : 0.f;
#pragma unroll
        for (int o = 4; o; o >>= 1) v += __shfl_xor_sync(0xffffffffu, v, o);
        if (tid == 0) red[0] = v;
    }
    __syncthreads();
    const float scale = rsqrtf(red[0] * (1.f / cfg::D_INNER) + 1e-5f);
    for (int i = tid; i < cfg::D_INNER; i += 256) {
        float val = gbuf[i] * scale * nw[i];
        __nv_bfloat16 h = __float2bfloat16(val);
        size_t idx = (size_t)t * cfg::D_INNER + i;
        nmh[idx] = h;
        nml[idx] = __float2bfloat16(val - __bfloat162float(h));
    }
}

// ---------------------------------------------------------------------------
// Host launch
// ---------------------------------------------------------------------------
extern "C" void kernel_launch(void* const* d_in, const int* in_sizes, int n_in,
                              void* d_out, int out_size)
{
    (void)in_sizes; (void)n_in; (void)out_size;
    const float* u       = (const float*)d_in[0];
    const float* W_in    = (const float*)d_in[1];
    const float* conv_w  = (const float*)d_in[2];
    const float* conv_b  = (const float*)d_in[3];
    const float* dt_bias = (const float*)d_in[4];
    const float* A_log   = (const float*)d_in[5];
    const float* D_param = (const float*)d_in[6];
    const float* norm_w  = (const float*)d_in[7];
    const float* W_out   = (const float*)d_in[8];
    float* out = (float*)d_out;

    void *pzx, *pxbc, *pdt, *py, *pG, *psp, *pac;
    void *puh, *pul, *pwih, *pwil, *pnmh, *pnml, *pwoh, *pwol;
    cudaGetSymbolAddress(&pzx,  g_zx);
    cudaGetSymbolAddress(&pxbc, g_xbc);
    cudaGetSymbolAddress(&pdt,  g_dt);
    cudaGetSymbolAddress(&py,   g_y);
    cudaGetSymbolAddress(&pG,   g_G);
    cudaGetSymbolAddress(&psp,  g_sprev);
    cudaGetSymbolAddress(&pac,  g_acum);
    cudaGetSymbolAddress(&puh,  g_uh);
    cudaGetSymbolAddress(&pul,  g_ul);
    cudaGetSymbolAddress(&pwih, g_wih);
    cudaGetSymbolAddress(&pwil, g_wil);
    cudaGetSymbolAddress(&pnmh, g_nmh);
    cudaGetSymbolAddress(&pnml, g_nml);
    cudaGetSymbolAddress(&pwoh, g_woh);
    cudaGetSymbolAddress(&pwol, g_wol);
    float* zx  = (float*)pzx;
    float* xbc = (float*)pxbc;
    float* dtb = (float*)pdt;
    float* yb  = (float*)py;
    float* Gb  = (float*)pG;
    float* spb = (float*)psp;
    float* acb = (float*)pac;
    __nv_bfloat16* uh  = (__nv_bfloat16*)puh;
    __nv_bfloat16* ul  = (__nv_bfloat16*)pul;
    __nv_bfloat16* wih = (__nv_bfloat16*)pwih;
    __nv_bfloat16* wil = (__nv_bfloat16*)pwil;
    __nv_bfloat16* nmh = (__nv_bfloat16*)pnmh;
    __nv_bfloat16* nml = (__nv_bfloat16*)pnml;
    __nv_bfloat16* woh = (__nv_bfloat16*)pwoh;
    __nv_bfloat16* wol = (__nv_bfloat16*)pwol;

    cudaFuncSetAttribute(gemm_mma_kernel, cudaFuncAttributeMaxDynamicSharedMemorySize,
                         mg::SMEM_BYTES);
    cudaFuncSetAttribute(ssd_pass3, cudaFuncAttributeMaxDynamicSharedMemorySize,
                         (int)sizeof(P3Smem));

    // fp32 -> bf16 hi/lo splits
    {
        int n4 = cfg::BL * cfg::D_MODEL / 4;
        split_bf16_kernel<<<(n4 + 255) / 256, 256>>>(u, uh, ul, n4);
        n4 = cfg::D_IN_PROJ * cfg::D_MODEL / 4;
        split_bf16_kernel<<<(n4 + 255) / 256, 256>>>(W_in, wih, wil, n4);
        n4 = cfg::D_MODEL * cfg::D_INNER / 4;
        split_bf16_kernel<<<(n4 + 255) / 256, 256>>>(W_out, woh, wol, n4);
    }
    // GEMM1: zx = u @ W_in^T
    {
        dim3 grid(cfg::N1_PAD / 128, cfg::BL / 128);
        gemm_mma_kernel<<<grid, 256, mg::SMEM_BYTES>>>(uh, ul, wih, wil, zx,
                                                       cfg::BL, cfg::D_IN_PROJ, cfg::D_MODEL);
    }
    // conv + silu; dt softplus
    {
        int n = cfg::BL * cfg::D_XBC;
        conv_silu_kernel<<<(n + 255) / 256, 256>>>(zx, conv_w, conv_b, xbc);
        n = cfg::BL * cfg::NHEADS;
        dt_kernel<<<(n + 255) / 256, 256>>>(zx, dt_bias, dtb);
    }
    // SSD: 3 passes
    ssd_pass1<<<cfg::NBH * cfg::NCHUNK, 256>>>(xbc, dtb, A_log, Gb, acb);
    ssd_pass2<<<cfg::NBH * 4, 256>>>(Gb, acb, spb);
    ssd_pass3<<<cfg::NBH * cfg::NCHUNK, 256, sizeof(P3Smem)>>>(
        xbc, dtb, D_param, spb, acb, yb);
    // gate + rmsnorm -> bf16 hi/lo
    gate_norm_kernel<<<cfg::BL, 256>>>(yb, zx, norm_w, nmh, nml);
    // GEMM2: out = nm @ W_out^T
    {
        dim3 grid(cfg::D_MODEL / 128, cfg::BL / 128);
        gemm_mma_kernel<<<grid, 256, mg::SMEM_BYTES>>>(nmh, nml, woh, wol, out,
                                                       cfg::BL, cfg::D_MODEL, cfg::D_INNER);
    }
}

// round 7
// speedup vs baseline: 2.9462x; 1.0002x over previous
#include <cuda_runtime.h>
#include <cuda_bf16.h>
#include <math.h>
#include <stdint.h>

// ---------------------------------------------------------------------------
// Problem constants (Mamba2 block, B=2, L=4096)
// ---------------------------------------------------------------------------
namespace cfg {
constexpr int D_MODEL   = 2048;
constexpr int D_INNER   = 4096;
constexpr int D_STATE   = 64;
constexpr int D_CONV    = 4;
constexpr int NHEADS    = 64;
constexpr int HEADDIM   = 64;
constexpr int D_XBC     = D_INNER + 2 * D_STATE;              // 4224
constexpr int D_IN_PROJ = 2 * D_INNER + 2 * D_STATE + NHEADS; // 8384
constexpr int LSEQ      = 4096;
constexpr int BATCH     = 2;
constexpr int BL        = BATCH * LSEQ;                       // 8192
constexpr int CHUNK     = 64;
constexpr int NCHUNK    = LSEQ / CHUNK;                       // 64
constexpr int NBH       = BATCH * NHEADS;                     // 128
constexpr int N1_PAD    = 8448;
}

// ---------------------------------------------------------------------------
// Scratch (allocation-free: __device__ globals; zero-init at load)
// ---------------------------------------------------------------------------
__device__ float g_zx [(size_t)cfg::BL * cfg::D_IN_PROJ];
__device__ float g_xbc[(size_t)cfg::BL * cfg::D_XBC];
__device__ float g_dt [(size_t)cfg::BL * cfg::NHEADS];
__device__ float g_y  [(size_t)cfg::BL * cfg::D_INNER];

// SSD intermediates
__device__ float g_G    [(size_t)cfg::NBH * cfg::NCHUNK * 64 * 64];
__device__ float g_sprev[(size_t)cfg::NBH * cfg::NCHUNK * 64 * 64];
__device__ float g_acum [(size_t)cfg::NBH * cfg::NCHUNK * 64];

__device__ __nv_bfloat16 g_uh [(size_t)cfg::BL * cfg::D_MODEL];
__device__ __nv_bfloat16 g_ul [(size_t)cfg::BL * cfg::D_MODEL];
__device__ __nv_bfloat16 g_wih[(size_t)cfg::N1_PAD * cfg::D_MODEL];   // pad rows zero
__device__ __nv_bfloat16 g_wil[(size_t)cfg::N1_PAD * cfg::D_MODEL];
__device__ __nv_bfloat16 g_nmh[(size_t)cfg::BL * cfg::D_INNER];
__device__ __nv_bfloat16 g_nml[(size_t)cfg::BL * cfg::D_INNER];
__device__ __nv_bfloat16 g_woh[(size_t)cfg::D_MODEL * cfg::D_INNER];
__device__ __nv_bfloat16 g_wol[(size_t)cfg::D_MODEL * cfg::D_INNER];

// ---------------------------------------------------------------------------
// PTX helpers (family-portable: mma.sync / ldmatrix / cp.async)
// ---------------------------------------------------------------------------
__device__ __forceinline__ uint32_t smem_u32(const void* p) {
    uint32_t a;
    asm("{ .reg .u64 t; cvta.to.shared.u64 t, %1; cvt.u32.u64 %0, t; }"
        : "=r"(a) : "l"(p));
    return a;
}
__device__ __forceinline__ void cp_async16(uint32_t dst, const void* src) {
    asm volatile("cp.async.cg.shared.global [%0], [%1], 16;"
                 :: "r"(dst), "l"(src) : "memory");
}
__device__ __forceinline__ void ldsm4(uint32_t r[4], uint32_t addr) {
    asm volatile("ldmatrix.sync.aligned.m8n8.x4.shared.b16 {%0,%1,%2,%3}, [%4];"
                 : "=r"(r[0]), "=r"(r[1]), "=r"(r[2]), "=r"(r[3]) : "r"(addr));
}
__device__ __forceinline__ void ldsm2(uint32_t r[2], uint32_t addr) {
    asm volatile("ldmatrix.sync.aligned.m8n8.x2.shared.b16 {%0,%1}, [%2];"
                 : "=r"(r[0]), "=r"(r[1]) : "r"(addr));
}
__device__ __forceinline__ void mma16816(float c[4], const uint32_t a[4],
                                         uint32_t b0, uint32_t b1) {
    asm volatile(
        "mma.sync.aligned.m16n8k16.row.col.f32.bf16.bf16.f32 "
        "{%0,%1,%2,%3}, {%4,%5,%6,%7}, {%8,%9}, {%0,%1,%2,%3};"
        : "+f"(c[0]), "+f"(c[1]), "+f"(c[2]), "+f"(c[3])
        : "r"(a[0]), "r"(a[1]), "r"(a[2]), "r"(a[3]), "r"(b0), "r"(b1));
}

// ---------------------------------------------------------------------------
// HMMA GEMM: C = (Ah+Al)*(Bh+Bl)^T, fp32 accum, 3-pass bf16 emulation.
// Block 128x128x32, 8 warps, warp tile 64x32. 3-slot cp.async pipeline with
// ONE barrier per K-step, ordered: wait -> barrier -> issue(kb+2) -> compute.
//   - issue at iter kb targets slot (kb+2)%3 == (kb-1)%3, whose last readers
//     (iteration kb-1) are ordered by the top-of-kb barrier.
//   - wait_group 1 BEFORE the barrier makes every thread's copies for
//     kblk <= kb visible to all threads after the barrier.
// ---------------------------------------------------------------------------
namespace mg {
constexpr int PLANE = 128 * 32 * 2;          // 8192 B
constexpr int STAGE = 4 * PLANE;             // 32768 B (Ah, Al, Bh, Bl)
constexpr int STAGES = 3;
constexpr int SMEM_BYTES = STAGES * STAGE;   // 98304
}

__global__ __launch_bounds__(256, 2) void gemm_mma_kernel(
    const __nv_bfloat16* __restrict__ Ah, const __nv_bfloat16* __restrict__ Al,
    const __nv_bfloat16* __restrict__ Bh, const __nv_bfloat16* __restrict__ Bl,
    float* __restrict__ C, int M, int N, int K)
{
    extern __shared__ char smraw[];
    const uint32_t sb = smem_u32(smraw);
    const int tid  = threadIdx.x;
    const int bm   = blockIdx.y * 128;
    const int bn   = blockIdx.x * 128;
    const int wid  = tid >> 5, lane = tid & 31;
    const int wm   = wid & 1;
    const int wn   = wid >> 1;
    const int NK   = K >> 5;

    auto issue_load = [&](int stage, int kblk) {
        const uint32_t sbase = sb + stage * mg::STAGE;
        const int k0 = kblk * 32;
#pragma unroll
        for (int it = 0; it < 8; it++) {
            int id = it * 256 + tid;
            int p  = id >> 9;
            int c  = id & 511;
            int r  = c >> 2, g = c & 3;
            uint32_t dst = sbase + p * mg::PLANE + r * 64 +
                           ((g ^ ((r >> 1) & 3)) << 4);
            const __nv_bfloat16* src;
            if      (p == 0) src = Ah + (size_t)(bm + r) * K + k0 + g * 8;
            else if (p == 1) src = Al + (size_t)(bm + r) * K + k0 + g * 8;
            else if (p == 2) src = Bh + (size_t)(bn + r) * K + k0 + g * 8;
            else             src = Bl + (size_t)(bn + r) * K + k0 + g * 8;
            cp_async16(dst, src);
        }
    };

    float acc[4][4][4];
#pragma unroll
    for (int i = 0; i < 4; i++)
#pragma unroll
        for (int j = 0; j < 4; j++)
#pragma unroll
            for (int q = 0; q < 4; q++) acc[i][j][q] = 0.f;

    // prologue: 2 stages in flight
    issue_load(0, 0);
    asm volatile("cp.async.commit_group;" ::: "memory");
    issue_load(1, 1);
    asm volatile("cp.async.commit_group;" ::: "memory");

    for (int kb = 0; kb < NK; kb++) {
        asm volatile("cp.async.wait_group 1;" ::: "memory");
        __syncthreads();   // single barrier per iteration

        if (kb + 2 < NK) {
            issue_load((kb + 2) % mg::STAGES, kb + 2);  // slot (kb-1)%3: freed
            asm volatile("cp.async.commit_group;" ::: "memory");
        }

        const uint32_t st = sb + (kb % mg::STAGES) * mg::STAGE;
        const uint32_t sAh = st, sAl = st + mg::PLANE;
        const uint32_t sBh = st + 2 * mg::PLANE, sBl = st + 3 * mg::PLANE;

#pragma unroll
        for (int ks = 0; ks < 2; ks++) {
            uint32_t bh[4][2], bl[4][2];
#pragma unroll
            for (int nt = 0; nt < 4; nt++) {
                int nr = wn * 32 + nt * 8 + (lane & 7);
                int g  = 2 * ks + ((lane >> 3) & 1);
                uint32_t off = nr * 64 + ((g ^ ((nr >> 1) & 3)) << 4);
                ldsm2(bh[nt], sBh + off);
                ldsm2(bl[nt], sBl + off);
            }
            uint32_t a[4][4];
#pragma unroll
            for (int mt = 0; mt < 4; mt++) {
                int ar = wm * 64 + mt * 16 + (lane & 15);
                int g  = ks * 2 + (lane >> 4);
                ldsm4(a[mt], sAh + ar * 64 + ((g ^ ((ar >> 1) & 3)) << 4));
            }
#pragma unroll
            for (int mt = 0; mt < 4; mt++)
#pragma unroll
                for (int nt = 0; nt < 4; nt++)
                    mma16816(acc[mt][nt], a[mt], bh[nt][0], bh[nt][1]);
#pragma unroll
            for (int mt = 0; mt < 4; mt++)
#pragma unroll
                for (int nt = 0; nt < 4; nt++)
                    mma16816(acc[mt][nt], a[mt], bl[nt][0], bl[nt][1]);
#pragma unroll
            for (int mt = 0; mt < 4; mt++) {
                int ar = wm * 64 + mt * 16 + (lane & 15);
                int g  = ks * 2 + (lane >> 4);
                ldsm4(a[mt], sAl + ar * 64 + ((g ^ ((ar >> 1) & 3)) << 4));
            }
#pragma unroll
            for (int mt = 0; mt < 4; mt++)
#pragma unroll
                for (int nt = 0; nt < 4; nt++)
                    mma16816(acc[mt][nt], a[mt], bh[nt][0], bh[nt][1]);
        }
    }

#pragma unroll
    for (int mt = 0; mt < 4; mt++) {
#pragma unroll
        for (int nt = 0; nt < 4; nt++) {
            int row = bm + wm * 64 + mt * 16 + (lane >> 2);
            int col = bn + wn * 32 + nt * 8 + (lane & 3) * 2;
            if (col < N) {
                *(float2*)(C + (size_t)row * N + col) =
                    make_float2(acc[mt][nt][0], acc[mt][nt][1]);
                *(float2*)(C + (size_t)(row + 8) * N + col) =
                    make_float2(acc[mt][nt][2], acc[mt][nt][3]);
            }
        }
    }
}

// ---------------------------------------------------------------------------
// fp32 -> bf16 (hi, lo) split
// ---------------------------------------------------------------------------
__global__ void split_bf16_kernel(const float* __restrict__ src,
                                  __nv_bfloat16* __restrict__ hi,
                                  __nv_bfloat16* __restrict__ lo, int n4)
{
    int i = blockIdx.x * blockDim.x + threadIdx.x;
    if (i >= n4) return;
    float4 v = ((const float4*)src)[i];
    __nv_bfloat16 h0 = __float2bfloat16(v.x), h1 = __float2bfloat16(v.y);
    __nv_bfloat16 h2 = __float2bfloat16(v.z), h3 = __float2bfloat16(v.w);
    __nv_bfloat16 l0 = __float2bfloat16(v.x - __bfloat162float(h0));
    __nv_bfloat16 l1 = __float2bfloat16(v.y - __bfloat162float(h1));
    __nv_bfloat16 l2 = __float2bfloat16(v.z - __bfloat162float(h2));
    __nv_bfloat16 l3 = __float2bfloat16(v.w - __bfloat162float(h3));
    ((__nv_bfloat162*)hi)[2 * i]     = __halves2bfloat162(h0, h1);
    ((__nv_bfloat162*)hi)[2 * i + 1] = __halves2bfloat162(h2, h3);
    ((__nv_bfloat162*)lo)[2 * i]     = __halves2bfloat162(l0, l1);
    ((__nv_bfloat162*)lo)[2 * i + 1] = __halves2bfloat162(l2, l3);
}

// ---------------------------------------------------------------------------
// Fused depthwise causal conv (width 4) + bias + silu, plus dt softplus.
// ---------------------------------------------------------------------------
namespace fc {
constexpr int NCONV = (cfg::BL * cfg::D_XBC + 255) / 256;
constexpr int NDT   = (cfg::BL * cfg::NHEADS + 255) / 256;
}

__global__ void conv_dt_kernel(const float* __restrict__ zx,
                               const float* __restrict__ cw,
                               const float* __restrict__ cb,
                               const float* __restrict__ dt_bias,
                               float* __restrict__ xbc_out,
                               float* __restrict__ dt_out)
{
    int blk = blockIdx.x;
    if (blk < fc::NCONV) {
        int idx = blk * 256 + threadIdx.x;
        if (idx >= cfg::BL * cfg::D_XBC) return;
        int j = idx % cfg::D_XBC;
        int t = idx / cfg::D_XBC;
        int l = t & (cfg::LSEQ - 1);
        int b = t >> 12;
        float v = cb[j];
#pragma unroll
        for (int k = 0; k < cfg::D_CONV; k++) {
            int ls = l + k - (cfg::D_CONV - 1);
            if (ls >= 0)
                v = fmaf(cw[j * cfg::D_CONV + k],
                         zx[(size_t)(b * cfg::LSEQ + ls) * cfg::D_IN_PROJ + cfg::D_INNER + j], v);
        }
        xbc_out[(size_t)t * cfg::D_XBC + j] = v / (1.f + expf(-v));
    } else {
        int idx = (blk - fc::NCONV) * 256 + threadIdx.x;
        if (idx >= cfg::BL * cfg::NHEADS) return;
        int h = idx & 63;
        int t = idx >> 6;
        float x = zx[(size_t)t * cfg::D_IN_PROJ + cfg::D_INNER + cfg::D_XBC + h] + dt_bias[h];
        dt_out[idx] = (x > 20.f) ? x : log1pf(expf(x));
    }
}

// ---------------------------------------------------------------------------
// SSD pass 1: per (bh, chunk) — chunk state contribution G and Acum.
// ---------------------------------------------------------------------------
__global__ __launch_bounds__(256) void ssd_pass1(
    const float* __restrict__ xbc, const float* __restrict__ dtg,
    const float* __restrict__ A_log,
    float* __restrict__ G, float* __restrict__ acum)
{
    __shared__ float Bl[64][64], Xs[64][64];
    __shared__ float Acum[64], ws[64];
    const int blk = blockIdx.x;
    const int c = blk & 63, bh = blk >> 6;
    const int h = bh & 63, b = bh >> 6;
    const int tid = threadIdx.x;
    const float Aneg = -expf(A_log[h]);
    const int l0g = c * cfg::CHUNK;
    const int ty = tid >> 4, tx = tid & 15;

    for (int idx = tid; idx < 64 * 64; idx += 256) {
        int l = idx >> 6, q = idx & 63;
        size_t row = (size_t)(b * cfg::LSEQ + l0g + l);
        const float* xr = xbc + row * cfg::D_XBC;
        float dtv = dtg[row * cfg::NHEADS + h];
        Xs[l][q] = xr[h * cfg::HEADDIM + q] * dtv;
        Bl[l][q] = xr[cfg::D_INNER + q];
    }
    // warp-parallel inclusive scan of dA over 64 elems (warps 0-1)
    if (tid < 64) {
        const int lane = tid & 31;
        size_t row = (size_t)(b * cfg::LSEQ + l0g + tid);
        float v = Aneg * dtg[row * cfg::NHEADS + h];
#pragma unroll
        for (int o = 1; o < 32; o <<= 1) {
            float n = __shfl_up_sync(0xffffffffu, v, o);
            if (lane >= o) v += n;
        }
        Acum[tid] = v;
    }
    __syncthreads();
    if (tid < 64) {
        float v = Acum[tid] + ((tid >= 32) ? Acum[31] : 0.f);
        Acum[tid] = v;
    }
    __syncthreads();
    if (tid < 64) {
        ws[tid] = expf(Acum[63] - Acum[tid]);
        acum[(size_t)blk * 64 + tid] = Acum[tid];
    }
    __syncthreads();

    const int n0 = ty * 4, p0 = tx * 4;
    float sa[4][4];
#pragma unroll
    for (int i = 0; i < 4; i++)
#pragma unroll
        for (int j = 0; j < 4; j++) sa[i][j] = 0.f;
#pragma unroll 4
    for (int l = 0; l < 64; l++) {
        float w = ws[l];
        float4 av = *(const float4*)&Bl[l][n0];
        float4 bv = *(const float4*)&Xs[l][p0];
        float a[4] = {av.x * w, av.y * w, av.z * w, av.w * w};
        float bb[4] = {bv.x, bv.y, bv.z, bv.w};
#pragma unroll
        for (int i = 0; i < 4; i++)
#pragma unroll
            for (int j = 0; j < 4; j++) sa[i][j] = fmaf(a[i], bb[j], sa[i][j]);
    }
    float* gout = G + (size_t)blk * 4096;
#pragma unroll
    for (int i = 0; i < 4; i++)
        *(float4*)(gout + (n0 + i) * 64 + p0) =
            make_float4(sa[i][0], sa[i][1], sa[i][2], sa[i][3]);
}

// ---------------------------------------------------------------------------
// SSD pass 2: elementwise chunk-state scan. grid = NBH*4 = 512, 256 threads.
// ---------------------------------------------------------------------------
__global__ __launch_bounds__(256) void ssd_pass2(
    const float* __restrict__ G, const float* __restrict__ acum,
    float* __restrict__ sprev)
{
    __shared__ float eAc[cfg::NCHUNK];
    const int bh    = blockIdx.x >> 2;
    const int slice = blockIdx.x & 3;
    const int tid   = threadIdx.x;
    if (tid < cfg::NCHUNK)
        eAc[tid] = expf(acum[((size_t)bh * cfg::NCHUNK + tid) * 64 + 63]);
    __syncthreads();

    const int f4 = slice * 256 + tid;
    float4 S = make_float4(0.f, 0.f, 0.f, 0.f);
    const size_t bhbase = (size_t)bh * cfg::NCHUNK * 4096;
    for (int c = 0; c < cfg::NCHUNK; c++) {
        const size_t base = bhbase + (size_t)c * 4096 + f4 * 4;
        *(float4*)(sprev + base) = S;
        float4 g = *(const float4*)(G + base);
        float ea = eAc[c];
        S.x = fmaf(ea, S.x, g.x);
        S.y = fmaf(ea, S.y, g.y);
        S.z = fmaf(ea, S.z, g.z);
        S.w = fmaf(ea, S.w, g.w);
    }
}

// ---------------------------------------------------------------------------
// SSD pass 3: per (bh, chunk) — Wt = masked decay CB, Y = Y_diag + Y_off + D*x.
// ---------------------------------------------------------------------------
struct P3Smem {
    float Bt[64][64], Ct[64][64], Xs[64][64], Xraw[64][64], Wt[64][64], Sp[64][64];
    float Acum[64], eA[64];
};

__global__ __launch_bounds__(256) void ssd_pass3(
    const float* __restrict__ xbc, const float* __restrict__ dtg,
    const float* __restrict__ D_param,
    const float* __restrict__ sprev, const float* __restrict__ acum,
    float* __restrict__ y)
{
    extern __shared__ char smraw[];
    P3Smem& sm = *reinterpret_cast<P3Smem*>(smraw);
    const int blk = blockIdx.x;
    const int c = blk & 63, bh = blk >> 6;
    const int h = bh & 63, b = bh >> 6;
    const int tid = threadIdx.x;
    const float Dh = D_param[h];
    const int l0g = c * cfg::CHUNK;
    const int ty = tid >> 4, tx = tid & 15;

    for (int idx = tid; idx < 64 * 64; idx += 256) {
        int l = idx >> 6, q = idx & 63;
        size_t row = (size_t)(b * cfg::LSEQ + l0g + l);
        const float* xr = xbc + row * cfg::D_XBC;
        float dtv = dtg[row * cfg::NHEADS + h];
        float xv  = xr[h * cfg::HEADDIM + q];
        sm.Xraw[l][q] = xv;
        sm.Xs[l][q]   = xv * dtv;
        sm.Bt[q][l]   = xr[cfg::D_INNER + q];
        sm.Ct[q][l]   = xr[cfg::D_INNER + cfg::D_STATE + q];
        (&sm.Sp[0][0])[idx] = sprev[(size_t)blk * 4096 + idx];
    }
    if (tid < 64) {
        float a = acum[(size_t)blk * 64 + tid];
        sm.Acum[tid] = a;
        sm.eA[tid]   = expf(a);
    }
    __syncthreads();

    {
        const int s0 = ty * 4, l0 = tx * 4;
        float acc[4][4];
#pragma unroll
        for (int i = 0; i < 4; i++)
#pragma unroll
            for (int j = 0; j < 4; j++) acc[i][j] = 0.f;
#pragma unroll 4
        for (int n = 0; n < 64; n++) {
            float4 av = *(const float4*)&sm.Bt[n][s0];
            float4 bv = *(const float4*)&sm.Ct[n][l0];
            float a[4] = {av.x, av.y, av.z, av.w};
            float bb[4] = {bv.x, bv.y, bv.z, bv.w};
#pragma unroll
            for (int i = 0; i < 4; i++)
#pragma unroll
                for (int j = 0; j < 4; j++) acc[i][j] = fmaf(a[i], bb[j], acc[i][j]);
        }
#pragma unroll
        for (int i = 0; i < 4; i++)
#pragma unroll
            for (int j = 0; j < 4; j++) {
                int s = s0 + i, l = l0 + j;
                float w = (s <= l) ? expf(sm.Acum[l] - sm.Acum[s]) : 0.f;
                sm.Wt[s][l] = acc[i][j] * w;
            }
    }
    __syncthreads();

    {
        const int l0 = ty * 4, p0 = tx * 4;
        float yd[4][4], yo[4][4];
#pragma unroll
        for (int i = 0; i < 4; i++)
#pragma unroll
            for (int j = 0; j < 4; j++) { yd[i][j] = 0.f; yo[i][j] = 0.f; }
#pragma unroll 4
        for (int s = 0; s < 64; s++) {
            float4 av = *(const float4*)&sm.Wt[s][l0];
            float4 bv = *(const float4*)&sm.Xs[s][p0];
            float a[4] = {av.x, av.y, av.z, av.w};
            float bb[4] = {bv.x, bv.y, bv.z, bv.w};
#pragma unroll
            for (int i = 0; i < 4; i++)
#pragma unroll
                for (int j = 0; j < 4; j++) yd[i][j] = fmaf(a[i], bb[j], yd[i][j]);
        }
#pragma unroll 4
        for (int n = 0; n < 64; n++) {
            float4 av = *(const float4*)&sm.Ct[n][l0];
            float4 bv = *(const float4*)&sm.Sp[n][p0];
            float a[4] = {av.x, av.y, av.z, av.w};
            float bb[4] = {bv.x, bv.y, bv.z, bv.w};
#pragma unroll
            for (int i = 0; i < 4; i++)
#pragma unroll
                for (int j = 0; j < 4; j++) yo[i][j] = fmaf(a[i], bb[j], yo[i][j]);
        }
#pragma unroll
        for (int i = 0; i < 4; i++) {
            int l = l0 + i;
            size_t row = (size_t)(b * cfg::LSEQ + l0g + l);
            float ea = sm.eA[l];
            float4 o;
            o.x = yd[i][0] + ea * yo[i][0] + Dh * sm.Xraw[l][p0 + 0];
            o.y = yd[i][1] + ea * yo[i][1] + Dh * sm.Xraw[l][p0 + 1];
            o.z = yd[i][2] + ea * yo[i][2] + Dh * sm.Xraw[l][p0 + 2];
            o.w = yd[i][3] + ea * yo[i][3] + Dh * sm.Xraw[l][p0 + 3];
            *(float4*)(y + row * cfg::D_INNER + h * cfg::HEADDIM + p0) = o;
        }
    }
}

// ---------------------------------------------------------------------------
// gate + RMSNorm -> bf16 hi/lo
// ---------------------------------------------------------------------------
__global__ __launch_bounds__(256) void gate_norm_kernel(
    const float* __restrict__ y, const float* __restrict__ zx,
    const float* __restrict__ nw,
    __nv_bfloat16* __restrict__ nmh, __nv_bfloat16* __restrict__ nml)
{
    __shared__ float gbuf[cfg::D_INNER];
    __shared__ float red[8];
    const int t = blockIdx.x;
    const int tid = threadIdx.x;
    const float* yr = y + (size_t)t * cfg::D_INNER;
    const float* zr = zx + (size_t)t * cfg::D_IN_PROJ;

    float ss = 0.f;
    for (int i = tid; i < cfg::D_INNER; i += 256) {
        float zv = zr[i];
        float gv = yr[i] * (zv / (1.f + expf(-zv)));
        gbuf[i] = gv;
        ss = fmaf(gv, gv, ss);
    }
#pragma unroll
    for (int o = 16; o; o >>= 1) ss += __shfl_xor_sync(0xffffffffu, ss, o);
    if ((tid & 31) == 0) red[tid >> 5] = ss;
    __syncthreads();
    if (tid < 32) {
        float v = (tid < 8) ? red[tid] : 0.f;
#pragma unroll
        for (int o = 4; o; o >>= 1) v += __shfl_xor_sync(0xffffffffu, v, o);
        if (tid == 0) red[0] = v;
    }
    __syncthreads();
    const float scale = rsqrtf(red[0] * (1.f / cfg::D_INNER) + 1e-5f);
    for (int i = tid; i < cfg::D_INNER; i += 256) {
        float val = gbuf[i] * scale * nw[i];
        __nv_bfloat16 h = __float2bfloat16(val);
        size_t idx = (size_t)t * cfg::D_INNER + i;
        nmh[idx] = h;
        nml[idx] = __float2bfloat16(val - __bfloat162float(h));
    }
}

// ---------------------------------------------------------------------------
// Host launch
// ---------------------------------------------------------------------------
extern "C" void kernel_launch(void* const* d_in, const int* in_sizes, int n_in,
                              void* d_out, int out_size)
{
    (void)in_sizes; (void)n_in; (void)out_size;
    const float* u       = (const float*)d_in[0];
    const float* W_in    = (const float*)d_in[1];
    const float* conv_w  = (const float*)d_in[2];
    const float* conv_b  = (const float*)d_in[3];
    const float* dt_bias = (const float*)d_in[4];
    const float* A_log   = (const float*)d_in[5];
    const float* D_param = (const float*)d_in[6];
    const float* norm_w  = (const float*)d_in[7];
    const float* W_out   = (const float*)d_in[8];
    float* out = (float*)d_out;

    void *pzx, *pxbc, *pdt, *py, *pG, *psp, *pac;
    void *puh, *pul, *pwih, *pwil, *pnmh, *pnml, *pwoh, *pwol;
    cudaGetSymbolAddress(&pzx,  g_zx);
    cudaGetSymbolAddress(&pxbc, g_xbc);
    cudaGetSymbolAddress(&pdt,  g_dt);
    cudaGetSymbolAddress(&py,   g_y);
    cudaGetSymbolAddress(&pG,   g_G);
    cudaGetSymbolAddress(&psp,  g_sprev);
    cudaGetSymbolAddress(&pac,  g_acum);
    cudaGetSymbolAddress(&puh,  g_uh);
    cudaGetSymbolAddress(&pul,  g_ul);
    cudaGetSymbolAddress(&pwih, g_wih);
    cudaGetSymbolAddress(&pwil, g_wil);
    cudaGetSymbolAddress(&pnmh, g_nmh);
    cudaGetSymbolAddress(&pnml, g_nml);
    cudaGetSymbolAddress(&pwoh, g_woh);
    cudaGetSymbolAddress(&pwol, g_wol);
    float* zx  = (float*)pzx;
    float* xbc = (float*)pxbc;
    float* dtb = (float*)pdt;
    float* yb  = (float*)py;
    float* Gb  = (float*)pG;
    float* spb = (float*)psp;
    float* acb = (float*)pac;
    __nv_bfloat16* uh  = (__nv_bfloat16*)puh;
    __nv_bfloat16* ul  = (__nv_bfloat16*)pul;
    __nv_bfloat16* wih = (__nv_bfloat16*)pwih;
    __nv_bfloat16* wil = (__nv_bfloat16*)pwil;
    __nv_bfloat16* nmh = (__nv_bfloat16*)pnmh;
    __nv_bfloat16* nml = (__nv_bfloat16*)pnml;
    __nv_bfloat16* woh = (__nv_bfloat16*)pwoh;
    __nv_bfloat16* wol = (__nv_bfloat16*)pwol;

    cudaFuncSetAttribute(gemm_mma_kernel, cudaFuncAttributeMaxDynamicSharedMemorySize,
                         mg::SMEM_BYTES);
    cudaFuncSetAttribute(ssd_pass3, cudaFuncAttributeMaxDynamicSharedMemorySize,
                         (int)sizeof(P3Smem));

    // fp32 -> bf16 hi/lo splits
    {
        int n4 = cfg::BL * cfg::D_MODEL / 4;
        split_bf16_kernel<<<(n4 + 255) / 256, 256>>>(u, uh, ul, n4);
        n4 = cfg::D_IN_PROJ * cfg::D_MODEL / 4;
        split_bf16_kernel<<<(n4 + 255) / 256, 256>>>(W_in, wih, wil, n4);
        n4 = cfg::D_MODEL * cfg::D_INNER / 4;
        split_bf16_kernel<<<(n4 + 255) / 256, 256>>>(W_out, woh, wol, n4);
    }
    // GEMM1: zx = u @ W_in^T
    {
        dim3 grid(cfg::N1_PAD / 128, cfg::BL / 128);
        gemm_mma_kernel<<<grid, 256, mg::SMEM_BYTES>>>(uh, ul, wih, wil, zx,
                                                       cfg::BL, cfg::D_IN_PROJ, cfg::D_MODEL);
    }
    // fused conv+silu and dt softplus
    conv_dt_kernel<<<fc::NCONV + fc::NDT, 256>>>(zx, conv_w, conv_b, dt_bias, xbc, dtb);
    // SSD: 3 passes
    ssd_pass1<<<cfg::NBH * cfg::NCHUNK, 256>>>(xbc, dtb, A_log, Gb, acb);
    ssd_pass2<<<cfg::NBH * 4, 256>>>(Gb, acb, spb);
    ssd_pass3<<<cfg::NBH * cfg::NCHUNK, 256, sizeof(P3Smem)>>>(
        xbc, dtb, D_param, spb, acb, yb);
    // gate + rmsnorm -> bf16 hi/lo
    gate_norm_kernel<<<cfg::BL, 256>>>(yb, zx, norm_w, nmh, nml);
    // GEMM2: out = nm @ W_out^T
    {
        dim3 grid(cfg::D_MODEL / 128, cfg::BL / 128);
        gemm_mma_kernel<<<grid, 256, mg::SMEM_BYTES>>>(nmh, nml, woh, wol, out,
                                                       cfg::BL, cfg::D_MODEL, cfg::D_INNER);
    }
}

// round 8
// speedup vs baseline: 2.9542x; 1.0027x over previous
#include <cuda_runtime.h>
#include <cuda_bf16.h>
#include <math.h>
#include <stdint.h>

// ---------------------------------------------------------------------------
// Problem constants (Mamba2 block, B=2, L=4096)
// ---------------------------------------------------------------------------
namespace cfg {
constexpr int D_MODEL   = 2048;
constexpr int D_INNER   = 4096;
constexpr int D_STATE   = 64;
constexpr int D_CONV    = 4;
constexpr int NHEADS    = 64;
constexpr int HEADDIM   = 64;
constexpr int D_XBC     = D_INNER + 2 * D_STATE;              // 4224
constexpr int D_IN_PROJ = 2 * D_INNER + 2 * D_STATE + NHEADS; // 8384
constexpr int LSEQ      = 4096;
constexpr int BATCH     = 2;
constexpr int BL        = BATCH * LSEQ;                       // 8192
constexpr int CHUNK     = 64;
constexpr int NCHUNK    = LSEQ / CHUNK;                       // 64
constexpr int NBH       = BATCH * NHEADS;                     // 128
constexpr int N1_PAD    = 8448;
}

// ---------------------------------------------------------------------------
// Scratch (allocation-free: __device__ globals; zero-init at load)
// ---------------------------------------------------------------------------
__device__ float g_zx [(size_t)cfg::BL * cfg::D_IN_PROJ];
__device__ float g_xbc[(size_t)cfg::BL * cfg::D_XBC];
__device__ float g_dt [(size_t)cfg::BL * cfg::NHEADS];
__device__ float g_y  [(size_t)cfg::BL * cfg::D_INNER];

// SSD intermediates
__device__ float g_G    [(size_t)cfg::NBH * cfg::NCHUNK * 64 * 64];
__device__ float g_sprev[(size_t)cfg::NBH * cfg::NCHUNK * 64 * 64];
__device__ float g_acum [(size_t)cfg::NBH * cfg::NCHUNK * 64];

__device__ __nv_bfloat16 g_uh [(size_t)cfg::BL * cfg::D_MODEL];
__device__ __nv_bfloat16 g_ul [(size_t)cfg::BL * cfg::D_MODEL];
__device__ __nv_bfloat16 g_wih[(size_t)cfg::N1_PAD * cfg::D_MODEL];   // pad rows zero
__device__ __nv_bfloat16 g_wil[(size_t)cfg::N1_PAD * cfg::D_MODEL];
__device__ __nv_bfloat16 g_nmh[(size_t)cfg::BL * cfg::D_INNER];
__device__ __nv_bfloat16 g_nml[(size_t)cfg::BL * cfg::D_INNER];
__device__ __nv_bfloat16 g_woh[(size_t)cfg::D_MODEL * cfg::D_INNER];
__device__ __nv_bfloat16 g_wol[(size_t)cfg::D_MODEL * cfg::D_INNER];

// ---------------------------------------------------------------------------
// PTX helpers (family-portable: mma.sync / ldmatrix / cp.async)
// ---------------------------------------------------------------------------
__device__ __forceinline__ uint32_t smem_u32(const void* p) {
    uint32_t a;
    asm("{ .reg .u64 t; cvta.to.shared.u64 t, %1; cvt.u32.u64 %0, t; }"
        : "=r"(a) : "l"(p));
    return a;
}
__device__ __forceinline__ void cp_async16(uint32_t dst, const void* src) {
    asm volatile("cp.async.cg.shared.global [%0], [%1], 16;"
                 :: "r"(dst), "l"(src) : "memory");
}
__device__ __forceinline__ void ldsm4(uint32_t r[4], uint32_t addr) {
    asm volatile("ldmatrix.sync.aligned.m8n8.x4.shared.b16 {%0,%1,%2,%3}, [%4];"
                 : "=r"(r[0]), "=r"(r[1]), "=r"(r[2]), "=r"(r[3]) : "r"(addr));
}
__device__ __forceinline__ void ldsm2(uint32_t r[2], uint32_t addr) {
    asm volatile("ldmatrix.sync.aligned.m8n8.x2.shared.b16 {%0,%1}, [%2];"
                 : "=r"(r[0]), "=r"(r[1]) : "r"(addr));
}
__device__ __forceinline__ void mma16816(float c[4], const uint32_t a[4],
                                         uint32_t b0, uint32_t b1) {
    asm volatile(
        "mma.sync.aligned.m16n8k16.row.col.f32.bf16.bf16.f32 "
        "{%0,%1,%2,%3}, {%4,%5,%6,%7}, {%8,%9}, {%0,%1,%2,%3};"
        : "+f"(c[0]), "+f"(c[1]), "+f"(c[2]), "+f"(c[3])
        : "r"(a[0]), "r"(a[1]), "r"(a[2]), "r"(a[3]), "r"(b0), "r"(b1));
}

// ---------------------------------------------------------------------------
// HMMA GEMM: C = (Ah+Al)*(Bh+Bl)^T, fp32 accum, 3-pass bf16 emulation.
// Block 128x128x32, 8 warps, warp tile 64x32. 3-slot cp.async pipeline,
// one barrier per K-step. Loader address math fully hoisted: each thread
// owns (row r0 = tid/4, rows r0 & r0+64, byte-group g = tid%4) across all
// 4 planes; swizzle XOR is invariant to the +64 row offset.
// ---------------------------------------------------------------------------
namespace mg {
constexpr int PLANE = 128 * 32 * 2;          // 8192 B
constexpr int STAGE = 4 * PLANE;             // 32768 B (Ah, Al, Bh, Bl)
constexpr int STAGES = 3;
constexpr int SMEM_BYTES = STAGES * STAGE;   // 98304
}

__global__ __launch_bounds__(256, 2) void gemm_mma_kernel(
    const __nv_bfloat16* __restrict__ Ah, const __nv_bfloat16* __restrict__ Al,
    const __nv_bfloat16* __restrict__ Bh, const __nv_bfloat16* __restrict__ Bl,
    float* __restrict__ C, int M, int N, int K)
{
    extern __shared__ char smraw[];
    const uint32_t sb = smem_u32(smraw);
    const int tid  = threadIdx.x;
    const int bm   = blockIdx.y * 128;
    const int bn   = blockIdx.x * 128;
    const int wid  = tid >> 5, lane = tid & 31;
    const int wm   = wid & 1;
    const int wn   = wid >> 1;
    const int NK   = K >> 5;

    // ---- hoisted loader state ----
    const int r0 = tid >> 2;                 // 0..63
    const int gq = tid & 3;                  // 16B group within 64B row
    const uint32_t swz  = (uint32_t)((gq ^ ((r0 >> 1) & 3)) << 4);
    const uint32_t dst0 = (uint32_t)(r0 * 64) + swz;   // plane-relative
    const size_t rowskip = (size_t)64 * K;   // +64 rows, in elements
    const __nv_bfloat16* pAh = Ah + (size_t)(bm + r0) * K + gq * 8;
    const __nv_bfloat16* pAl = Al + (size_t)(bm + r0) * K + gq * 8;
    const __nv_bfloat16* pBh = Bh + (size_t)(bn + r0) * K + gq * 8;
    const __nv_bfloat16* pBl = Bl + (size_t)(bn + r0) * K + gq * 8;

    auto issue_load = [&](int stage, int kblk) {
        const uint32_t d = sb + stage * mg::STAGE + dst0;
        const int k0 = kblk * 32;
        cp_async16(d,                        pAh + k0);
        cp_async16(d + 4096,                 pAh + k0 + rowskip);
        cp_async16(d + mg::PLANE,            pAl + k0);
        cp_async16(d + mg::PLANE + 4096,     pAl + k0 + rowskip);
        cp_async16(d + 2 * mg::PLANE,        pBh + k0);
        cp_async16(d + 2 * mg::PLANE + 4096, pBh + k0 + rowskip);
        cp_async16(d + 3 * mg::PLANE,        pBl + k0);
        cp_async16(d + 3 * mg::PLANE + 4096, pBl + k0 + rowskip);
    };

    float acc[4][4][4];
#pragma unroll
    for (int i = 0; i < 4; i++)
#pragma unroll
        for (int j = 0; j < 4; j++)
#pragma unroll
            for (int q = 0; q < 4; q++) acc[i][j][q] = 0.f;

    // prologue: 2 stages in flight
    issue_load(0, 0);
    asm volatile("cp.async.commit_group;" ::: "memory");
    issue_load(1, 1);
    asm volatile("cp.async.commit_group;" ::: "memory");

    for (int kb = 0; kb < NK; kb++) {
        asm volatile("cp.async.wait_group 1;" ::: "memory");
        __syncthreads();   // single barrier per iteration

        if (kb + 2 < NK) {
            issue_load((kb + 2) % mg::STAGES, kb + 2);  // slot (kb-1)%3: freed
            asm volatile("cp.async.commit_group;" ::: "memory");
        }

        const uint32_t st = sb + (kb % mg::STAGES) * mg::STAGE;
        const uint32_t sAh = st, sAl = st + mg::PLANE;
        const uint32_t sBh = st + 2 * mg::PLANE, sBl = st + 3 * mg::PLANE;

#pragma unroll
        for (int ks = 0; ks < 2; ks++) {
            uint32_t bh[4][2], bl[4][2];
#pragma unroll
            for (int nt = 0; nt < 4; nt++) {
                int nr = wn * 32 + nt * 8 + (lane & 7);
                int g  = 2 * ks + ((lane >> 3) & 1);
                uint32_t off = nr * 64 + ((g ^ ((nr >> 1) & 3)) << 4);
                ldsm2(bh[nt], sBh + off);
                ldsm2(bl[nt], sBl + off);
            }
            uint32_t a[4][4];
#pragma unroll
            for (int mt = 0; mt < 4; mt++) {
                int ar = wm * 64 + mt * 16 + (lane & 15);
                int g  = ks * 2 + (lane >> 4);
                ldsm4(a[mt], sAh + ar * 64 + ((g ^ ((ar >> 1) & 3)) << 4));
            }
#pragma unroll
            for (int mt = 0; mt < 4; mt++)
#pragma unroll
                for (int nt = 0; nt < 4; nt++)
                    mma16816(acc[mt][nt], a[mt], bh[nt][0], bh[nt][1]);
#pragma unroll
            for (int mt = 0; mt < 4; mt++)
#pragma unroll
                for (int nt = 0; nt < 4; nt++)
                    mma16816(acc[mt][nt], a[mt], bl[nt][0], bl[nt][1]);
#pragma unroll
            for (int mt = 0; mt < 4; mt++) {
                int ar = wm * 64 + mt * 16 + (lane & 15);
                int g  = ks * 2 + (lane >> 4);
                ldsm4(a[mt], sAl + ar * 64 + ((g ^ ((ar >> 1) & 3)) << 4));
            }
#pragma unroll
            for (int mt = 0; mt < 4; mt++)
#pragma unroll
                for (int nt = 0; nt < 4; nt++)
                    mma16816(acc[mt][nt], a[mt], bh[nt][0], bh[nt][1]);
        }
    }

#pragma unroll
    for (int mt = 0; mt < 4; mt++) {
#pragma unroll
        for (int nt = 0; nt < 4; nt++) {
            int row = bm + wm * 64 + mt * 16 + (lane >> 2);
            int col = bn + wn * 32 + nt * 8 + (lane & 3) * 2;
            if (col < N) {
                *(float2*)(C + (size_t)row * N + col) =
                    make_float2(acc[mt][nt][0], acc[mt][nt][1]);
                *(float2*)(C + (size_t)(row + 8) * N + col) =
                    make_float2(acc[mt][nt][2], acc[mt][nt][3]);
            }
        }
    }
}

// ---------------------------------------------------------------------------
// fp32 -> bf16 (hi, lo) split
// ---------------------------------------------------------------------------
__global__ void split_bf16_kernel(const float* __restrict__ src,
                                  __nv_bfloat16* __restrict__ hi,
                                  __nv_bfloat16* __restrict__ lo, int n4)
{
    int i = blockIdx.x * blockDim.x + threadIdx.x;
    if (i >= n4) return;
    float4 v = ((const float4*)src)[i];
    __nv_bfloat16 h0 = __float2bfloat16(v.x), h1 = __float2bfloat16(v.y);
    __nv_bfloat16 h2 = __float2bfloat16(v.z), h3 = __float2bfloat16(v.w);
    __nv_bfloat16 l0 = __float2bfloat16(v.x - __bfloat162float(h0));
    __nv_bfloat16 l1 = __float2bfloat16(v.y - __bfloat162float(h1));
    __nv_bfloat16 l2 = __float2bfloat16(v.z - __bfloat162float(h2));
    __nv_bfloat16 l3 = __float2bfloat16(v.w - __bfloat162float(h3));
    ((__nv_bfloat162*)hi)[2 * i]     = __halves2bfloat162(h0, h1);
    ((__nv_bfloat162*)hi)[2 * i + 1] = __halves2bfloat162(h2, h3);
    ((__nv_bfloat162*)lo)[2 * i]     = __halves2bfloat162(l0, l1);
    ((__nv_bfloat162*)lo)[2 * i + 1] = __halves2bfloat162(l2, l3);
}

// ---------------------------------------------------------------------------
// Fused depthwise causal conv (width 4) + bias + silu, plus dt softplus.
// ---------------------------------------------------------------------------
namespace fc {
constexpr int NCONV = (cfg::BL * cfg::D_XBC + 255) / 256;
constexpr int NDT   = (cfg::BL * cfg::NHEADS + 255) / 256;
}

__global__ void conv_dt_kernel(const float* __restrict__ zx,
                               const float* __restrict__ cw,
                               const float* __restrict__ cb,
                               const float* __restrict__ dt_bias,
                               float* __restrict__ xbc_out,
                               float* __restrict__ dt_out)
{
    int blk = blockIdx.x;
    if (blk < fc::NCONV) {
        int idx = blk * 256 + threadIdx.x;
        if (idx >= cfg::BL * cfg::D_XBC) return;
        int j = idx % cfg::D_XBC;
        int t = idx / cfg::D_XBC;
        int l = t & (cfg::LSEQ - 1);
        int b = t >> 12;
        float v = cb[j];
#pragma unroll
        for (int k = 0; k < cfg::D_CONV; k++) {
            int ls = l + k - (cfg::D_CONV - 1);
            if (ls >= 0)
                v = fmaf(cw[j * cfg::D_CONV + k],
                         zx[(size_t)(b * cfg::LSEQ + ls) * cfg::D_IN_PROJ + cfg::D_INNER + j], v);
        }
        xbc_out[(size_t)t * cfg::D_XBC + j] = v / (1.f + expf(-v));
    } else {
        int idx = (blk - fc::NCONV) * 256 + threadIdx.x;
        if (idx >= cfg::BL * cfg::NHEADS) return;
        int h = idx & 63;
        int t = idx >> 6;
        float x = zx[(size_t)t * cfg::D_IN_PROJ + cfg::D_INNER + cfg::D_XBC + h] + dt_bias[h];
        dt_out[idx] = (x > 20.f) ? x : log1pf(expf(x));
    }
}

// ---------------------------------------------------------------------------
// SSD pass 1: per (bh, chunk) — chunk state contribution G and Acum.
// ---------------------------------------------------------------------------
__global__ __launch_bounds__(256) void ssd_pass1(
    const float* __restrict__ xbc, const float* __restrict__ dtg,
    const float* __restrict__ A_log,
    float* __restrict__ G, float* __restrict__ acum)
{
    __shared__ float Bl[64][64], Xs[64][64];
    __shared__ float Acum[64], ws[64];
    const int blk = blockIdx.x;
    const int c = blk & 63, bh = blk >> 6;
    const int h = bh & 63, b = bh >> 6;
    const int tid = threadIdx.x;
    const float Aneg = -expf(A_log[h]);
    const int l0g = c * cfg::CHUNK;
    const int ty = tid >> 4, tx = tid & 15;

    for (int idx = tid; idx < 64 * 64; idx += 256) {
        int l = idx >> 6, q = idx & 63;
        size_t row = (size_t)(b * cfg::LSEQ + l0g + l);
        const float* xr = xbc + row * cfg::D_XBC;
        float dtv = dtg[row * cfg::NHEADS + h];
        Xs[l][q] = xr[h * cfg::HEADDIM + q] * dtv;
        Bl[l][q] = xr[cfg::D_INNER + q];
    }
    if (tid < 64) {
        const int lane = tid & 31;
        size_t row = (size_t)(b * cfg::LSEQ + l0g + tid);
        float v = Aneg * dtg[row * cfg::NHEADS + h];
#pragma unroll
        for (int o = 1; o < 32; o <<= 1) {
            float n = __shfl_up_sync(0xffffffffu, v, o);
            if (lane >= o) v += n;
        }
        Acum[tid] = v;
    }
    __syncthreads();
    if (tid < 64) {
        float v = Acum[tid] + ((tid >= 32) ? Acum[31] : 0.f);
        Acum[tid] = v;
    }
    __syncthreads();
    if (tid < 64) {
        ws[tid] = expf(Acum[63] - Acum[tid]);
        acum[(size_t)blk * 64 + tid] = Acum[tid];
    }
    __syncthreads();

    const int n0 = ty * 4, p0 = tx * 4;
    float sa[4][4];
#pragma unroll
    for (int i = 0; i < 4; i++)
#pragma unroll
        for (int j = 0; j < 4; j++) sa[i][j] = 0.f;
#pragma unroll 4
    for (int l = 0; l < 64; l++) {
        float w = ws[l];
        float4 av = *(const float4*)&Bl[l][n0];
        float4 bv = *(const float4*)&Xs[l][p0];
        float a[4] = {av.x * w, av.y * w, av.z * w, av.w * w};
        float bb[4] = {bv.x, bv.y, bv.z, bv.w};
#pragma unroll
        for (int i = 0; i < 4; i++)
#pragma unroll
            for (int j = 0; j < 4; j++) sa[i][j] = fmaf(a[i], bb[j], sa[i][j]);
    }
    float* gout = G + (size_t)blk * 4096;
#pragma unroll
    for (int i = 0; i < 4; i++)
        *(float4*)(gout + (n0 + i) * 64 + p0) =
            make_float4(sa[i][0], sa[i][1], sa[i][2], sa[i][3]);
}

// ---------------------------------------------------------------------------
// SSD pass 2: elementwise chunk-state scan. grid = NBH*4 = 512, 256 threads.
// ---------------------------------------------------------------------------
__global__ __launch_bounds__(256) void ssd_pass2(
    const float* __restrict__ G, const float* __restrict__ acum,
    float* __restrict__ sprev)
{
    __shared__ float eAc[cfg::NCHUNK];
    const int bh    = blockIdx.x >> 2;
    const int slice = blockIdx.x & 3;
    const int tid   = threadIdx.x;
    if (tid < cfg::NCHUNK)
        eAc[tid] = expf(acum[((size_t)bh * cfg::NCHUNK + tid) * 64 + 63]);
    __syncthreads();

    const int f4 = slice * 256 + tid;
    float4 S = make_float4(0.f, 0.f, 0.f, 0.f);
    const size_t bhbase = (size_t)bh * cfg::NCHUNK * 4096;
    for (int c = 0; c < cfg::NCHUNK; c++) {
        const size_t base = bhbase + (size_t)c * 4096 + f4 * 4;
        *(float4*)(sprev + base) = S;
        float4 g = *(const float4*)(G + base);
        float ea = eAc[c];
        S.x = fmaf(ea, S.x, g.x);
        S.y = fmaf(ea, S.y, g.y);
        S.z = fmaf(ea, S.z, g.z);
        S.w = fmaf(ea, S.w, g.w);
    }
}

// ---------------------------------------------------------------------------
// SSD pass 3: per (bh, chunk) — Wt = masked decay CB, Y = Y_diag + Y_off + D*x.
// ---------------------------------------------------------------------------
struct P3Smem {
    float Bt[64][64], Ct[64][64], Xs[64][64], Xraw[64][64], Wt[64][64], Sp[64][64];
    float Acum[64], eA[64];
};

__global__ __launch_bounds__(256) void ssd_pass3(
    const float* __restrict__ xbc, const float* __restrict__ dtg,
    const float* __restrict__ D_param,
    const float* __restrict__ sprev, const float* __restrict__ acum,
    float* __restrict__ y)
{
    extern __shared__ char smraw[];
    P3Smem& sm = *reinterpret_cast<P3Smem*>(smraw);
    const int blk = blockIdx.x;
    const int c = blk & 63, bh = blk >> 6;
    const int h = bh & 63, b = bh >> 6;
    const int tid = threadIdx.x;
    const float Dh = D_param[h];
    const int l0g = c * cfg::CHUNK;
    const int ty = tid >> 4, tx = tid & 15;

    for (int idx = tid; idx < 64 * 64; idx += 256) {
        int l = idx >> 6, q = idx & 63;
        size_t row = (size_t)(b * cfg::LSEQ + l0g + l);
        const float* xr = xbc + row * cfg::D_XBC;
        float dtv = dtg[row * cfg::NHEADS + h];
        float xv  = xr[h * cfg::HEADDIM + q];
        sm.Xraw[l][q] = xv;
        sm.Xs[l][q]   = xv * dtv;
        sm.Bt[q][l]   = xr[cfg::D_INNER + q];
        sm.Ct[q][l]   = xr[cfg::D_INNER + cfg::D_STATE + q];
        (&sm.Sp[0][0])[idx] = sprev[(size_t)blk * 4096 + idx];
    }
    if (tid < 64) {
        float a = acum[(size_t)blk * 64 + tid];
        sm.Acum[tid] = a;
        sm.eA[tid]   = expf(a);
    }
    __syncthreads();

    {
        const int s0 = ty * 4, l0 = tx * 4;
        float acc[4][4];
#pragma unroll
        for (int i = 0; i < 4; i++)
#pragma unroll
            for (int j = 0; j < 4; j++) acc[i][j] = 0.f;
#pragma unroll 4
        for (int n = 0; n < 64; n++) {
            float4 av = *(const float4*)&sm.Bt[n][s0];
            float4 bv = *(const float4*)&sm.Ct[n][l0];
            float a[4] = {av.x, av.y, av.z, av.w};
            float bb[4] = {bv.x, bv.y, bv.z, bv.w};
#pragma unroll
            for (int i = 0; i < 4; i++)
#pragma unroll
                for (int j = 0; j < 4; j++) acc[i][j] = fmaf(a[i], bb[j], acc[i][j]);
        }
#pragma unroll
        for (int i = 0; i < 4; i++)
#pragma unroll
            for (int j = 0; j < 4; j++) {
                int s = s0 + i, l = l0 + j;
                float w = (s <= l) ? expf(sm.Acum[l] - sm.Acum[s]) : 0.f;
                sm.Wt[s][l] = acc[i][j] * w;
            }
    }
    __syncthreads();

    {
        const int l0 = ty * 4, p0 = tx * 4;
        float yd[4][4], yo[4][4];
#pragma unroll
        for (int i = 0; i < 4; i++)
#pragma unroll
            for (int j = 0; j < 4; j++) { yd[i][j] = 0.f; yo[i][j] = 0.f; }
#pragma unroll 4
        for (int s = 0; s < 64; s++) {
            float4 av = *(const float4*)&sm.Wt[s][l0];
            float4 bv = *(const float4*)&sm.Xs[s][p0];
            float a[4] = {av.x, av.y, av.z, av.w};
            float bb[4] = {bv.x, bv.y, bv.z, bv.w};
#pragma unroll
            for (int i = 0; i < 4; i++)
#pragma unroll
                for (int j = 0; j < 4; j++) yd[i][j] = fmaf(a[i], bb[j], yd[i][j]);
        }
#pragma unroll 4
        for (int n = 0; n < 64; n++) {
            float4 av = *(const float4*)&sm.Ct[n][l0];
            float4 bv = *(const float4*)&sm.Sp[n][p0];
            float a[4] = {av.x, av.y, av.z, av.w};
            float bb[4] = {bv.x, bv.y, bv.z, bv.w};
#pragma unroll
            for (int i = 0; i < 4; i++)
#pragma unroll
                for (int j = 0; j < 4; j++) yo[i][j] = fmaf(a[i], bb[j], yo[i][j]);
        }
#pragma unroll
        for (int i = 0; i < 4; i++) {
            int l = l0 + i;
            size_t row = (size_t)(b * cfg::LSEQ + l0g + l);
            float ea = sm.eA[l];
            float4 o;
            o.x = yd[i][0] + ea * yo[i][0] + Dh * sm.Xraw[l][p0 + 0];
            o.y = yd[i][1] + ea * yo[i][1] + Dh * sm.Xraw[l][p0 + 1];
            o.z = yd[i][2] + ea * yo[i][2] + Dh * sm.Xraw[l][p0 + 2];
            o.w = yd[i][3] + ea * yo[i][3] + Dh * sm.Xraw[l][p0 + 3];
            *(float4*)(y + row * cfg::D_INNER + h * cfg::HEADDIM + p0) = o;
        }
    }
}

// ---------------------------------------------------------------------------
// gate + RMSNorm -> bf16 hi/lo
// ---------------------------------------------------------------------------
__global__ __launch_bounds__(256) void gate_norm_kernel(
    const float* __restrict__ y, const float* __restrict__ zx,
    const float* __restrict__ nw,
    __nv_bfloat16* __restrict__ nmh, __nv_bfloat16* __restrict__ nml)
{
    __shared__ float gbuf[cfg::D_INNER];
    __shared__ float red[8];
    const int t = blockIdx.x;
    const int tid = threadIdx.x;
    const float* yr = y + (size_t)t * cfg::D_INNER;
    const float* zr = zx + (size_t)t * cfg::D_IN_PROJ;

    float ss = 0.f;
    for (int i = tid; i < cfg::D_INNER; i += 256) {
        float zv = zr[i];
        float gv = yr[i] * (zv / (1.f + expf(-zv)));
        gbuf[i] = gv;
        ss = fmaf(gv, gv, ss);
    }
#pragma unroll
    for (int o = 16; o; o >>= 1) ss += __shfl_xor_sync(0xffffffffu, ss, o);
    if ((tid & 31) == 0) red[tid >> 5] = ss;
    __syncthreads();
    if (tid < 32) {
        float v = (tid < 8) ? red[tid] : 0.f;
#pragma unroll
        for (int o = 4; o; o >>= 1) v += __shfl_xor_sync(0xffffffffu, v, o);
        if (tid == 0) red[0] = v;
    }
    __syncthreads();
    const float scale = rsqrtf(red[0] * (1.f / cfg::D_INNER) + 1e-5f);
    for (int i = tid; i < cfg::D_INNER; i += 256) {
        float val = gbuf[i] * scale * nw[i];
        __nv_bfloat16 h = __float2bfloat16(val);
        size_t idx = (size_t)t * cfg::D_INNER + i;
        nmh[idx] = h;
        nml[idx] = __float2bfloat16(val - __bfloat162float(h));
    }
}

// ---------------------------------------------------------------------------
// Host launch
// ---------------------------------------------------------------------------
extern "C" void kernel_launch(void* const* d_in, const int* in_sizes, int n_in,
                              void* d_out, int out_size)
{
    (void)in_sizes; (void)n_in; (void)out_size;
    const float* u       = (const float*)d_in[0];
    const float* W_in    = (const float*)d_in[1];
    const float* conv_w  = (const float*)d_in[2];
    const float* conv_b  = (const float*)d_in[3];
    const float* dt_bias = (const float*)d_in[4];
    const float* A_log   = (const float*)d_in[5];
    const float* D_param = (const float*)d_in[6];
    const float* norm_w  = (const float*)d_in[7];
    const float* W_out   = (const float*)d_in[8];
    float* out = (float*)d_out;

    void *pzx, *pxbc, *pdt, *py, *pG, *psp, *pac;
    void *puh, *pul, *pwih, *pwil, *pnmh, *pnml, *pwoh, *pwol;
    cudaGetSymbolAddress(&pzx,  g_zx);
    cudaGetSymbolAddress(&pxbc, g_xbc);
    cudaGetSymbolAddress(&pdt,  g_dt);
    cudaGetSymbolAddress(&py,   g_y);
    cudaGetSymbolAddress(&pG,   g_G);
    cudaGetSymbolAddress(&psp,  g_sprev);
    cudaGetSymbolAddress(&pac,  g_acum);
    cudaGetSymbolAddress(&puh,  g_uh);
    cudaGetSymbolAddress(&pul,  g_ul);
    cudaGetSymbolAddress(&pwih, g_wih);
    cudaGetSymbolAddress(&pwil, g_wil);
    cudaGetSymbolAddress(&pnmh, g_nmh);
    cudaGetSymbolAddress(&pnml, g_nml);
    cudaGetSymbolAddress(&pwoh, g_woh);
    cudaGetSymbolAddress(&pwol, g_wol);
    float* zx  = (float*)pzx;
    float* xbc = (float*)pxbc;
    float* dtb = (float*)pdt;
    float* yb  = (float*)py;
    float* Gb  = (float*)pG;
    float* spb = (float*)psp;
    float* acb = (float*)pac;
    __nv_bfloat16* uh  = (__nv_bfloat16*)puh;
    __nv_bfloat16* ul  = (__nv_bfloat16*)pul;
    __nv_bfloat16* wih = (__nv_bfloat16*)pwih;
    __nv_bfloat16* wil = (__nv_bfloat16*)pwil;
    __nv_bfloat16* nmh = (__nv_bfloat16*)pnmh;
    __nv_bfloat16* nml = (__nv_bfloat16*)pnml;
    __nv_bfloat16* woh = (__nv_bfloat16*)pwoh;
    __nv_bfloat16* wol = (__nv_bfloat16*)pwol;

    cudaFuncSetAttribute(gemm_mma_kernel, cudaFuncAttributeMaxDynamicSharedMemorySize,
                         mg::SMEM_BYTES);
    cudaFuncSetAttribute(ssd_pass3, cudaFuncAttributeMaxDynamicSharedMemorySize,
                         (int)sizeof(P3Smem));

    // fp32 -> bf16 hi/lo splits
    {
        int n4 = cfg::BL * cfg::D_MODEL / 4;
        split_bf16_kernel<<<(n4 + 255) / 256, 256>>>(u, uh, ul, n4);
        n4 = cfg::D_IN_PROJ * cfg::D_MODEL / 4;
        split_bf16_kernel<<<(n4 + 255) / 256, 256>>>(W_in, wih, wil, n4);
        n4 = cfg::D_MODEL * cfg::D_INNER / 4;
        split_bf16_kernel<<<(n4 + 255) / 256, 256>>>(W_out, woh, wol, n4);
    }
    // GEMM1: zx = u @ W_in^T
    {
        dim3 grid(cfg::N1_PAD / 128, cfg::BL / 128);
        gemm_mma_kernel<<<grid, 256, mg::SMEM_BYTES>>>(uh, ul, wih, wil, zx,
                                                       cfg::BL, cfg::D_IN_PROJ, cfg::D_MODEL);
    }
    // fused conv+silu and dt softplus
    conv_dt_kernel<<<fc::NCONV + fc::NDT, 256>>>(zx, conv_w, conv_b, dt_bias, xbc, dtb);
    // SSD: 3 passes
    ssd_pass1<<<cfg::NBH * cfg::NCHUNK, 256>>>(xbc, dtb, A_log, Gb, acb);
    ssd_pass2<<<cfg::NBH * 4, 256>>>(Gb, acb, spb);
    ssd_pass3<<<cfg::NBH * cfg::NCHUNK, 256, sizeof(P3Smem)>>>(
        xbc, dtb, D_param, spb, acb, yb);
    // gate + rmsnorm -> bf16 hi/lo
    gate_norm_kernel<<<cfg::BL, 256>>>(yb, zx, norm_w, nmh, nml);
    // GEMM2: out = nm @ W_out^T
    {
        dim3 grid(cfg::D_MODEL / 128, cfg::BL / 128);
        gemm_mma_kernel<<<grid, 256, mg::SMEM_BYTES>>>(nmh, nml, woh, wol, out,
                                                       cfg::BL, cfg::D_MODEL, cfg::D_INNER);
    }
}

// round 9
// speedup vs baseline: 4.5754x; 1.5488x over previous
#include <cuda_runtime.h>
#include <cuda_fp16.h>
#include <math.h>
#include <stdint.h>

// ---------------------------------------------------------------------------
// Problem constants (Mamba2 block, B=2, L=4096)
// ---------------------------------------------------------------------------
namespace cfg {
constexpr int D_MODEL   = 2048;
constexpr int D_INNER   = 4096;
constexpr int D_STATE   = 64;
constexpr int D_CONV    = 4;
constexpr int NHEADS    = 64;
constexpr int HEADDIM   = 64;
constexpr int D_XBC     = D_INNER + 2 * D_STATE;              // 4224
constexpr int D_IN_PROJ = 2 * D_INNER + 2 * D_STATE + NHEADS; // 8384
constexpr int LSEQ      = 4096;
constexpr int BATCH     = 2;
constexpr int BL        = BATCH * LSEQ;                       // 8192
constexpr int CHUNK     = 64;
constexpr int NCHUNK    = LSEQ / CHUNK;                       // 64
constexpr int NBH       = BATCH * NHEADS;                     // 128
constexpr int N1_PAD    = 8448;
}

// ---------------------------------------------------------------------------
// Scratch (allocation-free: __device__ globals; zero-init at load)
// ---------------------------------------------------------------------------
__device__ float g_zx [(size_t)cfg::BL * cfg::D_IN_PROJ];
__device__ float g_xbc[(size_t)cfg::BL * cfg::D_XBC];
__device__ float g_dt [(size_t)cfg::BL * cfg::NHEADS];
__device__ float g_y  [(size_t)cfg::BL * cfg::D_INNER];

// SSD intermediates
__device__ float g_G    [(size_t)cfg::NBH * cfg::NCHUNK * 64 * 64];
__device__ float g_sprev[(size_t)cfg::NBH * cfg::NCHUNK * 64 * 64];
__device__ float g_acum [(size_t)cfg::NBH * cfg::NCHUNK * 64];

// fp16 operands for tensor-core GEMMs (single plane — fp16 precision budget)
__device__ __half g_uh [(size_t)cfg::BL * cfg::D_MODEL];
__device__ __half g_wih[(size_t)cfg::N1_PAD * cfg::D_MODEL];   // pad rows zero
__device__ __half g_nmh[(size_t)cfg::BL * cfg::D_INNER];
__device__ __half g_woh[(size_t)cfg::D_MODEL * cfg::D_INNER];

// ---------------------------------------------------------------------------
// PTX helpers (family-portable: mma.sync / ldmatrix / cp.async)
// ---------------------------------------------------------------------------
__device__ __forceinline__ uint32_t smem_u32(const void* p) {
    uint32_t a;
    asm("{ .reg .u64 t; cvta.to.shared.u64 t, %1; cvt.u32.u64 %0, t; }"
        : "=r"(a) : "l"(p));
    return a;
}
__device__ __forceinline__ void cp_async16(uint32_t dst, const void* src) {
    asm volatile("cp.async.cg.shared.global [%0], [%1], 16;"
                 :: "r"(dst), "l"(src) : "memory");
}
__device__ __forceinline__ void ldsm4(uint32_t r[4], uint32_t addr) {
    asm volatile("ldmatrix.sync.aligned.m8n8.x4.shared.b16 {%0,%1,%2,%3}, [%4];"
                 : "=r"(r[0]), "=r"(r[1]), "=r"(r[2]), "=r"(r[3]) : "r"(addr));
}
__device__ __forceinline__ void ldsm2(uint32_t r[2], uint32_t addr) {
    asm volatile("ldmatrix.sync.aligned.m8n8.x2.shared.b16 {%0,%1}, [%2];"
                 : "=r"(r[0]), "=r"(r[1]) : "r"(addr));
}
__device__ __forceinline__ void mma16816h(float c[4], const uint32_t a[4],
                                          uint32_t b0, uint32_t b1) {
    asm volatile(
        "mma.sync.aligned.m16n8k16.row.col.f32.f16.f16.f32 "
        "{%0,%1,%2,%3}, {%4,%5,%6,%7}, {%8,%9}, {%0,%1,%2,%3};"
        : "+f"(c[0]), "+f"(c[1]), "+f"(c[2]), "+f"(c[3])
        : "r"(a[0]), "r"(a[1]), "r"(a[2]), "r"(a[3]), "r"(b0), "r"(b1));
}

// ---------------------------------------------------------------------------
// HMMA fp16 GEMM: C[M,N] = A[M,K] * B[N,K]^T, fp32 accum, single pass.
// Block 128x128x64, 8 warps, warp tile 64x32. 3-slot cp.async pipeline,
// one barrier per K-step (proven ordering: wait -> barrier -> issue(kb+2)
// into slot (kb-1)%3 -> compute slot kb%3).
// SMEM row = 128B (64 fp16); swizzle: 16B-group g' = g ^ (row & 7).
// ---------------------------------------------------------------------------
namespace mg {
constexpr int KT    = 64;
constexpr int PLANE = 128 * mg::KT * 2;      // 16384 B per operand tile
constexpr int STAGE = 2 * PLANE;             // 32768 B (A, B)
constexpr int STAGES = 3;
constexpr int SMEM_BYTES = STAGES * STAGE;   // 98304
}

__global__ __launch_bounds__(256, 2) void gemm_mma_kernel(
    const __half* __restrict__ A, const __half* __restrict__ B,
    float* __restrict__ C, int M, int N, int K)
{
    extern __shared__ char smraw[];
    const uint32_t sb = smem_u32(smraw);
    const int tid  = threadIdx.x;
    const int bm   = blockIdx.y * 128;
    const int bn   = blockIdx.x * 128;
    const int wid  = tid >> 5, lane = tid & 31;
    const int wm   = wid & 1;
    const int wn   = wid >> 1;
    const int NK   = K >> 6;                   // K-steps of 64

    // ---- hoisted loader state: row r = tid/2, group-half gh = (tid&1)*4 ----
    const int r  = tid >> 1;                   // 0..127
    const int gh = (tid & 1) * 4;              // groups gh..gh+3 of 8
    uint32_t dX[4];
#pragma unroll
    for (int i = 0; i < 4; i++)
        dX[i] = (uint32_t)(((gh + i) ^ (r & 7)) << 4);
    const uint32_t rowbase = (uint32_t)(r * 128);
    const __half* pA = A + (size_t)(bm + r) * K + gh * 8;
    const __half* pB = B + (size_t)(bn + r) * K + gh * 8;

    auto issue_load = [&](int stage, int kblk) {
        const uint32_t d = sb + stage * mg::STAGE + rowbase;
        const int k0 = kblk * mg::KT;
#pragma unroll
        for (int i = 0; i < 4; i++) {
            cp_async16(d + dX[i],             pA + k0 + i * 8);
            cp_async16(d + mg::PLANE + dX[i], pB + k0 + i * 8);
        }
    };

    float acc[4][4][4];
#pragma unroll
    for (int i = 0; i < 4; i++)
#pragma unroll
        for (int j = 0; j < 4; j++)
#pragma unroll
            for (int q = 0; q < 4; q++) acc[i][j][q] = 0.f;

    // prologue: 2 stages in flight
    issue_load(0, 0);
    asm volatile("cp.async.commit_group;" ::: "memory");
    issue_load(1, 1);
    asm volatile("cp.async.commit_group;" ::: "memory");

    for (int kb = 0; kb < NK; kb++) {
        asm volatile("cp.async.wait_group 1;" ::: "memory");
        __syncthreads();   // single barrier per iteration

        if (kb + 2 < NK) {
            issue_load((kb + 2) % mg::STAGES, kb + 2);  // slot (kb-1)%3: freed
            asm volatile("cp.async.commit_group;" ::: "memory");
        }

        const uint32_t sA = sb + (kb % mg::STAGES) * mg::STAGE;
        const uint32_t sB = sA + mg::PLANE;

#pragma unroll
        for (int ks = 0; ks < 4; ks++) {       // 4 k16 steps per KT=64
            uint32_t bf[4][2];
#pragma unroll
            for (int nt = 0; nt < 4; nt++) {
                int nr = wn * 32 + nt * 8 + (lane & 7);
                int g  = 2 * ks + ((lane >> 3) & 1);
                uint32_t off = nr * 128 + (((g ^ (nr & 7))) << 4);
                ldsm2(bf[nt], sB + off);
            }
            uint32_t a[4][4];
#pragma unroll
            for (int mt = 0; mt < 4; mt++) {
                int ar = wm * 64 + mt * 16 + (lane & 15);
                int g  = 2 * ks + (lane >> 4);
                uint32_t off = ar * 128 + (((g ^ (ar & 7))) << 4);
                ldsm4(a[mt], sA + off);
            }
#pragma unroll
            for (int mt = 0; mt < 4; mt++)
#pragma unroll
                for (int nt = 0; nt < 4; nt++)
                    mma16816h(acc[mt][nt], a[mt], bf[nt][0], bf[nt][1]);
        }
    }

#pragma unroll
    for (int mt = 0; mt < 4; mt++) {
#pragma unroll
        for (int nt = 0; nt < 4; nt++) {
            int row = bm + wm * 64 + mt * 16 + (lane >> 2);
            int col = bn + wn * 32 + nt * 8 + (lane & 3) * 2;
            if (col < N) {
                *(float2*)(C + (size_t)row * N + col) =
                    make_float2(acc[mt][nt][0], acc[mt][nt][1]);
                *(float2*)(C + (size_t)(row + 8) * N + col) =
                    make_float2(acc[mt][nt][2], acc[mt][nt][3]);
            }
        }
    }
}

// ---------------------------------------------------------------------------
// fp32 -> fp16 convert
// ---------------------------------------------------------------------------
__global__ void cvt_fp16_kernel(const float* __restrict__ src,
                                __half* __restrict__ dst, int n4)
{
    int i = blockIdx.x * blockDim.x + threadIdx.x;
    if (i >= n4) return;
    float4 v = ((const float4*)src)[i];
    __half2 h0 = __floats2half2_rn(v.x, v.y);
    __half2 h1 = __floats2half2_rn(v.z, v.w);
    ((__half2*)dst)[2 * i]     = h0;
    ((__half2*)dst)[2 * i + 1] = h1;
}

// ---------------------------------------------------------------------------
// Fused depthwise causal conv (width 4) + bias + silu, plus dt softplus.
// ---------------------------------------------------------------------------
namespace fc {
constexpr int NCONV = (cfg::BL * cfg::D_XBC + 255) / 256;
constexpr int NDT   = (cfg::BL * cfg::NHEADS + 255) / 256;
}

__global__ void conv_dt_kernel(const float* __restrict__ zx,
                               const float* __restrict__ cw,
                               const float* __restrict__ cb,
                               const float* __restrict__ dt_bias,
                               float* __restrict__ xbc_out,
                               float* __restrict__ dt_out)
{
    int blk = blockIdx.x;
    if (blk < fc::NCONV) {
        int idx = blk * 256 + threadIdx.x;
        if (idx >= cfg::BL * cfg::D_XBC) return;
        int j = idx % cfg::D_XBC;
        int t = idx / cfg::D_XBC;
        int l = t & (cfg::LSEQ - 1);
        int b = t >> 12;
        float v = cb[j];
#pragma unroll
        for (int k = 0; k < cfg::D_CONV; k++) {
            int ls = l + k - (cfg::D_CONV - 1);
            if (ls >= 0)
                v = fmaf(cw[j * cfg::D_CONV + k],
                         zx[(size_t)(b * cfg::LSEQ + ls) * cfg::D_IN_PROJ + cfg::D_INNER + j], v);
        }
        xbc_out[(size_t)t * cfg::D_XBC + j] = v / (1.f + expf(-v));
    } else {
        int idx = (blk - fc::NCONV) * 256 + threadIdx.x;
        if (idx >= cfg::BL * cfg::NHEADS) return;
        int h = idx & 63;
        int t = idx >> 6;
        float x = zx[(size_t)t * cfg::D_IN_PROJ + cfg::D_INNER + cfg::D_XBC + h] + dt_bias[h];
        dt_out[idx] = (x > 20.f) ? x : log1pf(expf(x));
    }
}

// ---------------------------------------------------------------------------
// SSD pass 1: per (bh, chunk) — chunk state contribution G and Acum.
// ---------------------------------------------------------------------------
__global__ __launch_bounds__(256) void ssd_pass1(
    const float* __restrict__ xbc, const float* __restrict__ dtg,
    const float* __restrict__ A_log,
    float* __restrict__ G, float* __restrict__ acum)
{
    __shared__ float Bl[64][64], Xs[64][64];
    __shared__ float Acum[64], ws[64];
    const int blk = blockIdx.x;
    const int c = blk & 63, bh = blk >> 6;
    const int h = bh & 63, b = bh >> 6;
    const int tid = threadIdx.x;
    const float Aneg = -expf(A_log[h]);
    const int l0g = c * cfg::CHUNK;
    const int ty = tid >> 4, tx = tid & 15;

    for (int idx = tid; idx < 64 * 64; idx += 256) {
        int l = idx >> 6, q = idx & 63;
        size_t row = (size_t)(b * cfg::LSEQ + l0g + l);
        const float* xr = xbc + row * cfg::D_XBC;
        float dtv = dtg[row * cfg::NHEADS + h];
        Xs[l][q] = xr[h * cfg::HEADDIM + q] * dtv;
        Bl[l][q] = xr[cfg::D_INNER + q];
    }
    if (tid < 64) {
        const int lane = tid & 31;
        size_t row = (size_t)(b * cfg::LSEQ + l0g + tid);
        float v = Aneg * dtg[row * cfg::NHEADS + h];
#pragma unroll
        for (int o = 1; o < 32; o <<= 1) {
            float n = __shfl_up_sync(0xffffffffu, v, o);
            if (lane >= o) v += n;
        }
        Acum[tid] = v;
    }
    __syncthreads();
    if (tid < 64) {
        float v = Acum[tid] + ((tid >= 32) ? Acum[31] : 0.f);
        Acum[tid] = v;
    }
    __syncthreads();
    if (tid < 64) {
        ws[tid] = expf(Acum[63] - Acum[tid]);
        acum[(size_t)blk * 64 + tid] = Acum[tid];
    }
    __syncthreads();

    const int n0 = ty * 4, p0 = tx * 4;
    float sa[4][4];
#pragma unroll
    for (int i = 0; i < 4; i++)
#pragma unroll
        for (int j = 0; j < 4; j++) sa[i][j] = 0.f;
#pragma unroll 4
    for (int l = 0; l < 64; l++) {
        float w = ws[l];
        float4 av = *(const float4*)&Bl[l][n0];
        float4 bv = *(const float4*)&Xs[l][p0];
        float a[4] = {av.x * w, av.y * w, av.z * w, av.w * w};
        float bb[4] = {bv.x, bv.y, bv.z, bv.w};
#pragma unroll
        for (int i = 0; i < 4; i++)
#pragma unroll
            for (int j = 0; j < 4; j++) sa[i][j] = fmaf(a[i], bb[j], sa[i][j]);
    }
    float* gout = G + (size_t)blk * 4096;
#pragma unroll
    for (int i = 0; i < 4; i++)
        *(float4*)(gout + (n0 + i) * 64 + p0) =
            make_float4(sa[i][0], sa[i][1], sa[i][2], sa[i][3]);
}

// ---------------------------------------------------------------------------
// SSD pass 2: elementwise chunk-state scan. grid = NBH*4 = 512, 256 threads.
// ---------------------------------------------------------------------------
__global__ __launch_bounds__(256) void ssd_pass2(
    const float* __restrict__ G, const float* __restrict__ acum,
    float* __restrict__ sprev)
{
    __shared__ float eAc[cfg::NCHUNK];
    const int bh    = blockIdx.x >> 2;
    const int slice = blockIdx.x & 3;
    const int tid   = threadIdx.x;
    if (tid < cfg::NCHUNK)
        eAc[tid] = expf(acum[((size_t)bh * cfg::NCHUNK + tid) * 64 + 63]);
    __syncthreads();

    const int f4 = slice * 256 + tid;
    float4 S = make_float4(0.f, 0.f, 0.f, 0.f);
    const size_t bhbase = (size_t)bh * cfg::NCHUNK * 4096;
    for (int c = 0; c < cfg::NCHUNK; c++) {
        const size_t base = bhbase + (size_t)c * 4096 + f4 * 4;
        *(float4*)(sprev + base) = S;
        float4 g = *(const float4*)(G + base);
        float ea = eAc[c];
        S.x = fmaf(ea, S.x, g.x);
        S.y = fmaf(ea, S.y, g.y);
        S.z = fmaf(ea, S.z, g.z);
        S.w = fmaf(ea, S.w, g.w);
    }
}

// ---------------------------------------------------------------------------
// SSD pass 3: per (bh, chunk) — Wt = masked decay CB, Y = Y_diag + Y_off + D*x.
// ---------------------------------------------------------------------------
struct P3Smem {
    float Bt[64][64], Ct[64][64], Xs[64][64], Xraw[64][64], Wt[64][64], Sp[64][64];
    float Acum[64], eA[64];
};

__global__ __launch_bounds__(256) void ssd_pass3(
    const float* __restrict__ xbc, const float* __restrict__ dtg,
    const float* __restrict__ D_param,
    const float* __restrict__ sprev, const float* __restrict__ acum,
    float* __restrict__ y)
{
    extern __shared__ char smraw[];
    P3Smem& sm = *reinterpret_cast<P3Smem*>(smraw);
    const int blk = blockIdx.x;
    const int c = blk & 63, bh = blk >> 6;
    const int h = bh & 63, b = bh >> 6;
    const int tid = threadIdx.x;
    const float Dh = D_param[h];
    const int l0g = c * cfg::CHUNK;
    const int ty = tid >> 4, tx = tid & 15;

    for (int idx = tid; idx < 64 * 64; idx += 256) {
        int l = idx >> 6, q = idx & 63;
        size_t row = (size_t)(b * cfg::LSEQ + l0g + l);
        const float* xr = xbc + row * cfg::D_XBC;
        float dtv = dtg[row * cfg::NHEADS + h];
        float xv  = xr[h * cfg::HEADDIM + q];
        sm.Xraw[l][q] = xv;
        sm.Xs[l][q]   = xv * dtv;
        sm.Bt[q][l]   = xr[cfg::D_INNER + q];
        sm.Ct[q][l]   = xr[cfg::D_INNER + cfg::D_STATE + q];
        (&sm.Sp[0][0])[idx] = sprev[(size_t)blk * 4096 + idx];
    }
    if (tid < 64) {
        float a = acum[(size_t)blk * 64 + tid];
        sm.Acum[tid] = a;
        sm.eA[tid]   = expf(a);
    }
    __syncthreads();

    {
        const int s0 = ty * 4, l0 = tx * 4;
        float acc[4][4];
#pragma unroll
        for (int i = 0; i < 4; i++)
#pragma unroll
            for (int j = 0; j < 4; j++) acc[i][j] = 0.f;
#pragma unroll 4
        for (int n = 0; n < 64; n++) {
            float4 av = *(const float4*)&sm.Bt[n][s0];
            float4 bv = *(const float4*)&sm.Ct[n][l0];
            float a[4] = {av.x, av.y, av.z, av.w};
            float bb[4] = {bv.x, bv.y, bv.z, bv.w};
#pragma unroll
            for (int i = 0; i < 4; i++)
#pragma unroll
                for (int j = 0; j < 4; j++) acc[i][j] = fmaf(a[i], bb[j], acc[i][j]);
        }
#pragma unroll
        for (int i = 0; i < 4; i++)
#pragma unroll
            for (int j = 0; j < 4; j++) {
                int s = s0 + i, l = l0 + j;
                float w = (s <= l) ? expf(sm.Acum[l] - sm.Acum[s]) : 0.f;
                sm.Wt[s][l] = acc[i][j] * w;
            }
    }
    __syncthreads();

    {
        const int l0 = ty * 4, p0 = tx * 4;
        float yd[4][4], yo[4][4];
#pragma unroll
        for (int i = 0; i < 4; i++)
#pragma unroll
            for (int j = 0; j < 4; j++) { yd[i][j] = 0.f; yo[i][j] = 0.f; }
#pragma unroll 4
        for (int s = 0; s < 64; s++) {
            float4 av = *(const float4*)&sm.Wt[s][l0];
            float4 bv = *(const float4*)&sm.Xs[s][p0];
            float a[4] = {av.x, av.y, av.z, av.w};
            float bb[4] = {bv.x, bv.y, bv.z, bv.w};
#pragma unroll
            for (int i = 0; i < 4; i++)
#pragma unroll
                for (int j = 0; j < 4; j++) yd[i][j] = fmaf(a[i], bb[j], yd[i][j]);
        }
#pragma unroll 4
        for (int n = 0; n < 64; n++) {
            float4 av = *(const float4*)&sm.Ct[n][l0];
            float4 bv = *(const float4*)&sm.Sp[n][p0];
            float a[4] = {av.x, av.y, av.z, av.w};
            float bb[4] = {bv.x, bv.y, bv.z, bv.w};
#pragma unroll
            for (int i = 0; i < 4; i++)
#pragma unroll
                for (int j = 0; j < 4; j++) yo[i][j] = fmaf(a[i], bb[j], yo[i][j]);
        }
#pragma unroll
        for (int i = 0; i < 4; i++) {
            int l = l0 + i;
            size_t row = (size_t)(b * cfg::LSEQ + l0g + l);
            float ea = sm.eA[l];
            float4 o;
            o.x = yd[i][0] + ea * yo[i][0] + Dh * sm.Xraw[l][p0 + 0];
            o.y = yd[i][1] + ea * yo[i][1] + Dh * sm.Xraw[l][p0 + 1];
            o.z = yd[i][2] + ea * yo[i][2] + Dh * sm.Xraw[l][p0 + 2];
            o.w = yd[i][3] + ea * yo[i][3] + Dh * sm.Xraw[l][p0 + 3];
            *(float4*)(y + row * cfg::D_INNER + h * cfg::HEADDIM + p0) = o;
        }
    }
}

// ---------------------------------------------------------------------------
// gate + RMSNorm -> fp16
// ---------------------------------------------------------------------------
__global__ __launch_bounds__(256) void gate_norm_kernel(
    const float* __restrict__ y, const float* __restrict__ zx,
    const float* __restrict__ nw, __half* __restrict__ nmh)
{
    __shared__ float gbuf[cfg::D_INNER];
    __shared__ float red[8];
    const int t = blockIdx.x;
    const int tid = threadIdx.x;
    const float* yr = y + (size_t)t * cfg::D_INNER;
    const float* zr = zx + (size_t)t * cfg::D_IN_PROJ;

    float ss = 0.f;
    for (int i = tid; i < cfg::D_INNER; i += 256) {
        float zv = zr[i];
        float gv = yr[i] * (zv / (1.f + expf(-zv)));
        gbuf[i] = gv;
        ss = fmaf(gv, gv, ss);
    }
#pragma unroll
    for (int o = 16; o; o >>= 1) ss += __shfl_xor_sync(0xffffffffu, ss, o);
    if ((tid & 31) == 0) red[tid >> 5] = ss;
    __syncthreads();
    if (tid < 32) {
        float v = (tid < 8) ? red[tid] : 0.f;
#pragma unroll
        for (int o = 4; o; o >>= 1) v += __shfl_xor_sync(0xffffffffu, v, o);
        if (tid == 0) red[0] = v;
    }
    __syncthreads();
    const float scale = rsqrtf(red[0] * (1.f / cfg::D_INNER) + 1e-5f);
    for (int i = tid; i < cfg::D_INNER; i += 256) {
        float val = gbuf[i] * scale * nw[i];
        nmh[(size_t)t * cfg::D_INNER + i] = __float2half_rn(val);
    }
}

// ---------------------------------------------------------------------------
// Host launch
// ---------------------------------------------------------------------------
extern "C" void kernel_launch(void* const* d_in, const int* in_sizes, int n_in,
                              void* d_out, int out_size)
{
    (void)in_sizes; (void)n_in; (void)out_size;
    const float* u       = (const float*)d_in[0];
    const float* W_in    = (const float*)d_in[1];
    const float* conv_w  = (const float*)d_in[2];
    const float* conv_b  = (const float*)d_in[3];
    const float* dt_bias = (const float*)d_in[4];
    const float* A_log   = (const float*)d_in[5];
    const float* D_param = (const float*)d_in[6];
    const float* norm_w  = (const float*)d_in[7];
    const float* W_out   = (const float*)d_in[8];
    float* out = (float*)d_out;

    void *pzx, *pxbc, *pdt, *py, *pG, *psp, *pac;
    void *puh, *pwih, *pnmh, *pwoh;
    cudaGetSymbolAddress(&pzx,  g_zx);
    cudaGetSymbolAddress(&pxbc, g_xbc);
    cudaGetSymbolAddress(&pdt,  g_dt);
    cudaGetSymbolAddress(&py,   g_y);
    cudaGetSymbolAddress(&pG,   g_G);
    cudaGetSymbolAddress(&psp,  g_sprev);
    cudaGetSymbolAddress(&pac,  g_acum);
    cudaGetSymbolAddress(&puh,  g_uh);
    cudaGetSymbolAddress(&pwih, g_wih);
    cudaGetSymbolAddress(&pnmh, g_nmh);
    cudaGetSymbolAddress(&pwoh, g_woh);
    float* zx  = (float*)pzx;
    float* xbc = (float*)pxbc;
    float* dtb = (float*)pdt;
    float* yb  = (float*)py;
    float* Gb  = (float*)pG;
    float* spb = (float*)psp;
    float* acb = (float*)pac;
    __half* uh  = (__half*)puh;
    __half* wih = (__half*)pwih;
    __half* nmh = (__half*)pnmh;
    __half* woh = (__half*)pwoh;

    cudaFuncSetAttribute(gemm_mma_kernel, cudaFuncAttributeMaxDynamicSharedMemorySize,
                         mg::SMEM_BYTES);
    cudaFuncSetAttribute(ssd_pass3, cudaFuncAttributeMaxDynamicSharedMemorySize,
                         (int)sizeof(P3Smem));

    // fp32 -> fp16 converts
    {
        int n4 = cfg::BL * cfg::D_MODEL / 4;
        cvt_fp16_kernel<<<(n4 + 255) / 256, 256>>>(u, uh, n4);
        n4 = cfg::D_IN_PROJ * cfg::D_MODEL / 4;
        cvt_fp16_kernel<<<(n4 + 255) / 256, 256>>>(W_in, wih, n4);
        n4 = cfg::D_MODEL * cfg::D_INNER / 4;
        cvt_fp16_kernel<<<(n4 + 255) / 256, 256>>>(W_out, woh, n4);
    }
    // GEMM1: zx = u @ W_in^T  (fp16 HMMA, fp32 accum)
    {
        dim3 grid(cfg::N1_PAD / 128, cfg::BL / 128);
        gemm_mma_kernel<<<grid, 256, mg::SMEM_BYTES>>>(uh, wih, zx,
                                                       cfg::BL, cfg::D_IN_PROJ, cfg::D_MODEL);
    }
    // fused conv+silu and dt softplus
    conv_dt_kernel<<<fc::NCONV + fc::NDT, 256>>>(zx, conv_w, conv_b, dt_bias, xbc, dtb);
    // SSD: 3 passes
    ssd_pass1<<<cfg::NBH * cfg::NCHUNK, 256>>>(xbc, dtb, A_log, Gb, acb);
    ssd_pass2<<<cfg::NBH * 4, 256>>>(Gb, acb, spb);
    ssd_pass3<<<cfg::NBH * cfg::NCHUNK, 256, sizeof(P3Smem)>>>(
        xbc, dtb, D_param, spb, acb, yb);
    // gate + rmsnorm -> fp16
    gate_norm_kernel<<<cfg::BL, 256>>>(yb, zx, norm_w, nmh);
    // GEMM2: out = nm @ W_out^T
    {
        dim3 grid(cfg::D_MODEL / 128, cfg::BL / 128);
        gemm_mma_kernel<<<grid, 256, mg::SMEM_BYTES>>>(nmh, woh, out,
                                                       cfg::BL, cfg::D_MODEL, cfg::D_INNER);
    }
}

// round 10
// speedup vs baseline: 5.7097x; 1.2479x over previous
#include <cuda_runtime.h>
#include <cuda_fp16.h>
#include <math.h>
#include <stdint.h>

// ---------------------------------------------------------------------------
// Problem constants (Mamba2 block, B=2, L=4096)
// ---------------------------------------------------------------------------
namespace cfg {
constexpr int D_MODEL   = 2048;
constexpr int D_INNER   = 4096;
constexpr int D_STATE   = 64;
constexpr int D_CONV    = 4;
constexpr int NHEADS    = 64;
constexpr int HEADDIM   = 64;
constexpr int D_XBC     = D_INNER + 2 * D_STATE;              // 4224
constexpr int D_IN_PROJ = 2 * D_INNER + 2 * D_STATE + NHEADS; // 8384
constexpr int LSEQ      = 4096;
constexpr int BATCH     = 2;
constexpr int BL        = BATCH * LSEQ;                       // 8192
constexpr int CHUNK     = 64;
constexpr int NCHUNK    = LSEQ / CHUNK;                       // 64
constexpr int NBH       = BATCH * NHEADS;                     // 128
constexpr int N1_PAD    = 8448;
}

// ---------------------------------------------------------------------------
// Scratch (allocation-free: __device__ globals; zero-init at load)
// ---------------------------------------------------------------------------
__device__ float g_zx [(size_t)cfg::BL * cfg::D_IN_PROJ];
__device__ float g_xbc[(size_t)cfg::BL * cfg::D_XBC];
__device__ float g_dt [(size_t)cfg::BL * cfg::NHEADS];
__device__ float g_y  [(size_t)cfg::BL * cfg::D_INNER];

// SSD intermediates
__device__ float g_G    [(size_t)cfg::NBH * cfg::NCHUNK * 64 * 64];
__device__ float g_sprev[(size_t)cfg::NBH * cfg::NCHUNK * 64 * 64];
__device__ float g_acum [(size_t)cfg::NBH * cfg::NCHUNK * 64];

// fp16 operands, PRE-SWIZZLED 16KB tiles (128 rows x 64 cols); tile (i,j) of an
// MxK matrix lives at halves offset (i*(K/64)+j)*8192; element (r,c8*8+e) at
// r*64 + ((c8 ^ (r&7))<<3) + e. Matches the GEMM smem LDSM layout exactly.
__device__ __half g_uh [(size_t)cfg::BL * cfg::D_MODEL];
__device__ __half g_wih[(size_t)cfg::N1_PAD * cfg::D_MODEL];
__device__ __half g_nmh[(size_t)cfg::BL * cfg::D_INNER];
__device__ __half g_woh[(size_t)cfg::D_MODEL * cfg::D_INNER];

// ---------------------------------------------------------------------------
// PTX helpers (family-portable: mma.sync / ldmatrix / cp.async.bulk / mbarrier)
// ---------------------------------------------------------------------------
__device__ __forceinline__ uint32_t smem_u32(const void* p) {
    uint32_t a;
    asm("{ .reg .u64 t; cvta.to.shared.u64 t, %1; cvt.u32.u64 %0, t; }"
        : "=r"(a) : "l"(p));
    return a;
}
__device__ __forceinline__ void ldsm4(uint32_t r[4], uint32_t addr) {
    asm volatile("ldmatrix.sync.aligned.m8n8.x4.shared.b16 {%0,%1,%2,%3}, [%4];"
                 : "=r"(r[0]), "=r"(r[1]), "=r"(r[2]), "=r"(r[3]) : "r"(addr));
}
__device__ __forceinline__ void ldsm2(uint32_t r[2], uint32_t addr) {
    asm volatile("ldmatrix.sync.aligned.m8n8.x2.shared.b16 {%0,%1}, [%2];"
                 : "=r"(r[0]), "=r"(r[1]) : "r"(addr));
}
__device__ __forceinline__ void mma16816h(float c[4], const uint32_t a[4],
                                          uint32_t b0, uint32_t b1) {
    asm volatile(
        "mma.sync.aligned.m16n8k16.row.col.f32.f16.f16.f32 "
        "{%0,%1,%2,%3}, {%4,%5,%6,%7}, {%8,%9}, {%0,%1,%2,%3};"
        : "+f"(c[0]), "+f"(c[1]), "+f"(c[2]), "+f"(c[3])
        : "r"(a[0]), "r"(a[1]), "r"(a[2]), "r"(a[3]), "r"(b0), "r"(b1));
}
__device__ __forceinline__ void bulk_cp(uint32_t dst, const void* src,
                                        uint32_t bytes, uint32_t mbar) {
    asm volatile(
        "cp.async.bulk.shared::cta.global.mbarrier::complete_tx::bytes "
        "[%0], [%1], %2, [%3];"
        :: "r"(dst), "l"(src), "r"(bytes), "r"(mbar) : "memory");
}
#define MBARRIER_INIT(addr, cnt) \
    asm volatile("mbarrier.init.shared.b64 [%0], %1;" :: "r"(addr), "r"(cnt) : "memory")
#define MBARRIER_EXPECT_TX(addr, bytes) \
    asm volatile("mbarrier.arrive.expect_tx.shared.b64 _, [%0], %1;" \
                 :: "r"(addr), "r"(bytes) : "memory")
#define MBARRIER_WAIT_PARITY(addr, par) do {                                      \
    uint32_t _m = (addr); uint32_t _p = (par); uint32_t _done;                    \
    asm volatile("{\n\t.reg .pred p;\n\t"                                         \
        "mbarrier.try_wait.parity.acquire.cta.shared::cta.b64 p, [%1], %2;\n\t"   \
        "selp.b32 %0, 1, 0, p;\n\t}" : "=r"(_done) : "r"(_m), "r"(_p) : "memory");\
    if (!_done) {                                                                 \
        asm volatile("{\n\t.reg .pred P1;\n\t"                                    \
        "WL_%=:\n\t"                                                              \
        "mbarrier.try_wait.parity.acquire.cta.shared::cta.b64 P1, [%0], %1, 0x989680;\n\t" \
        "@P1 bra.uni WD_%=;\n\tbra.uni WL_%=;\n\tWD_%=:\n\t}"                     \
        :: "r"(_m), "r"(_p) : "memory");                                          \
    } } while (0)

// ---------------------------------------------------------------------------
// HMMA fp16 GEMM on pre-swizzled tiles.  C[M,N] = A*B^T, fp32 accum.
// Block 128x128x64, 8 warps, warp tile 64x32. 3-slot pipeline; each stage is
// filled by TWO cp.async.bulk copies (A tile 16KB, B tile 16KB) issued by one
// thread, completion via mbarrier expect_tx. One __syncthreads per K-step
// orders buffer reuse (slot (kb-1)%3 re-issued at kb after all read it at kb-1).
// ---------------------------------------------------------------------------
namespace mg {
constexpr int KT    = 64;
constexpr int TILEB = 128 * KT * 2;          // 16384 B per operand tile
constexpr int STAGE = 2 * TILEB;             // 32768 B (A, B)
constexpr int STAGES = 3;
constexpr int MBAR_OFF = STAGES * STAGE;     // 98304
constexpr int SMEM_BYTES = MBAR_OFF + 64;    // + mbarriers
}

__global__ __launch_bounds__(256, 2) void gemm_mma_kernel(
    const __half* __restrict__ At, const __half* __restrict__ Bt,
    float* __restrict__ C, int M, int N, int K)
{
    extern __shared__ char smraw[];
    const uint32_t sb = smem_u32(smraw);
    const int tid  = threadIdx.x;
    const int bm   = blockIdx.y * 128;
    const int bn   = blockIdx.x * 128;
    const int wid  = tid >> 5, lane = tid & 31;
    const int wm   = wid & 1;
    const int wn   = wid >> 1;
    const int NK   = K >> 6;

    const __half* Abase = At + (size_t)blockIdx.y * NK * 8192;
    const __half* Bbase = Bt + (size_t)blockIdx.x * NK * 8192;
    const uint32_t mb = sb + mg::MBAR_OFF;

    if (tid == 0) {
        MBARRIER_INIT(mb,      1u);
        MBARRIER_INIT(mb + 8,  1u);
        MBARRIER_INIT(mb + 16, 1u);
    }
    __syncthreads();

    auto issue = [&](int stage, int kblk) {
        const uint32_t m = mb + stage * 8;
        MBARRIER_EXPECT_TX(m, (uint32_t)mg::STAGE);
        const uint32_t d = sb + stage * mg::STAGE;
        bulk_cp(d,             Abase + (size_t)kblk * 8192, mg::TILEB, m);
        bulk_cp(d + mg::TILEB, Bbase + (size_t)kblk * 8192, mg::TILEB, m);
    };

    float acc[4][4][4];
#pragma unroll
    for (int i = 0; i < 4; i++)
#pragma unroll
        for (int j = 0; j < 4; j++)
#pragma unroll
            for (int q = 0; q < 4; q++) acc[i][j][q] = 0.f;

    if (tid == 0) { issue(0, 0); issue(1, 1); }

    for (int kb = 0; kb < NK; kb++) {
        const int st = kb % mg::STAGES;
        MBARRIER_WAIT_PARITY(mb + st * 8, (uint32_t)((kb / 3) & 1));
        __syncthreads();   // all warps done reading slot (kb-1)%3

        if (kb + 2 < NK && tid == 0)
            issue((kb + 2) % mg::STAGES, kb + 2);

        const uint32_t sA = sb + st * mg::STAGE;
        const uint32_t sB = sA + mg::TILEB;

#pragma unroll
        for (int ks = 0; ks < 4; ks++) {       // 4 k16 steps per KT=64
            uint32_t bf[4][2];
#pragma unroll
            for (int nt = 0; nt < 4; nt++) {
                int nr = wn * 32 + nt * 8 + (lane & 7);
                int g  = 2 * ks + ((lane >> 3) & 1);
                uint32_t off = nr * 128 + (((g ^ (nr & 7))) << 4);
                ldsm2(bf[nt], sB + off);
            }
            uint32_t a[4][4];
#pragma unroll
            for (int mt = 0; mt < 4; mt++) {
                int ar = wm * 64 + mt * 16 + (lane & 15);
                int g  = 2 * ks + (lane >> 4);
                uint32_t off = ar * 128 + (((g ^ (ar & 7))) << 4);
                ldsm4(a[mt], sA + off);
            }
#pragma unroll
            for (int mt = 0; mt < 4; mt++)
#pragma unroll
                for (int nt = 0; nt < 4; nt++)
                    mma16816h(acc[mt][nt], a[mt], bf[nt][0], bf[nt][1]);
        }
    }

#pragma unroll
    for (int mt = 0; mt < 4; mt++) {
#pragma unroll
        for (int nt = 0; nt < 4; nt++) {
            int row = bm + wm * 64 + mt * 16 + (lane >> 2);
            int col = bn + wn * 32 + nt * 8 + (lane & 3) * 2;
            if (col < N) {
                *(float2*)(C + (size_t)row * N + col) =
                    make_float2(acc[mt][nt][0], acc[mt][nt][1]);
                *(float2*)(C + (size_t)(row + 8) * N + col) =
                    make_float2(acc[mt][nt][2], acc[mt][nt][3]);
            }
        }
    }
}

// ---------------------------------------------------------------------------
// fp32 row-major -> fp16 pre-swizzled 16KB tiles. One tile per block.
// rows beyond Mreal are zero-filled (GEMM1 B padding).
// ---------------------------------------------------------------------------
__global__ __launch_bounds__(256) void cvt_swz_kernel(
    const float* __restrict__ src, __half* __restrict__ dst, int Mreal, int K)
{
    const int NKt = K >> 6;
    const int tile = blockIdx.x;
    const int tm = tile / NKt, tk = tile % NKt;
    __half* d = dst + (size_t)tile * 8192;
#pragma unroll
    for (int it = 0; it < 4; it++) {
        int id = it * 256 + threadIdx.x;   // 0..1023 : 16B groups
        int r  = id >> 3, g = id & 7;
        int grow = tm * 128 + r;
        uint32_t off = (uint32_t)(r * 64 + ((g ^ (r & 7)) << 3));  // halves
        uint4 pk;
        if (grow < Mreal) {
            const float* s = src + (size_t)grow * K + tk * 64 + g * 8;
            float4 v0 = *(const float4*)s;
            float4 v1 = *(const float4*)(s + 4);
            __half2 h0 = __floats2half2_rn(v0.x, v0.y);
            __half2 h1 = __floats2half2_rn(v0.z, v0.w);
            __half2 h2 = __floats2half2_rn(v1.x, v1.y);
            __half2 h3 = __floats2half2_rn(v1.z, v1.w);
            pk.x = *(uint32_t*)&h0; pk.y = *(uint32_t*)&h1;
            pk.z = *(uint32_t*)&h2; pk.w = *(uint32_t*)&h3;
        } else {
            pk = make_uint4(0, 0, 0, 0);
        }
        *(uint4*)(d + off) = pk;
    }
}

// ---------------------------------------------------------------------------
// Fused depthwise causal conv (width 4) + bias + silu, plus dt softplus.
// ---------------------------------------------------------------------------
namespace fc {
constexpr int NCONV = (cfg::BL * cfg::D_XBC + 255) / 256;
constexpr int NDT   = (cfg::BL * cfg::NHEADS + 255) / 256;
}

__global__ void conv_dt_kernel(const float* __restrict__ zx,
                               const float* __restrict__ cw,
                               const float* __restrict__ cb,
                               const float* __restrict__ dt_bias,
                               float* __restrict__ xbc_out,
                               float* __restrict__ dt_out)
{
    int blk = blockIdx.x;
    if (blk < fc::NCONV) {
        int idx = blk * 256 + threadIdx.x;
        if (idx >= cfg::BL * cfg::D_XBC) return;
        int j = idx % cfg::D_XBC;
        int t = idx / cfg::D_XBC;
        int l = t & (cfg::LSEQ - 1);
        int b = t >> 12;
        float v = cb[j];
#pragma unroll
        for (int k = 0; k < cfg::D_CONV; k++) {
            int ls = l + k - (cfg::D_CONV - 1);
            if (ls >= 0)
                v = fmaf(cw[j * cfg::D_CONV + k],
                         zx[(size_t)(b * cfg::LSEQ + ls) * cfg::D_IN_PROJ + cfg::D_INNER + j], v);
        }
        xbc_out[(size_t)t * cfg::D_XBC + j] = v / (1.f + expf(-v));
    } else {
        int idx = (blk - fc::NCONV) * 256 + threadIdx.x;
        if (idx >= cfg::BL * cfg::NHEADS) return;
        int h = idx & 63;
        int t = idx >> 6;
        float x = zx[(size_t)t * cfg::D_IN_PROJ + cfg::D_INNER + cfg::D_XBC + h] + dt_bias[h];
        dt_out[idx] = (x > 20.f) ? x : log1pf(expf(x));
    }
}

// ---------------------------------------------------------------------------
// SSD pass 1: per (bh, chunk) — chunk state contribution G and Acum.
// ---------------------------------------------------------------------------
__global__ __launch_bounds__(256) void ssd_pass1(
    const float* __restrict__ xbc, const float* __restrict__ dtg,
    const float* __restrict__ A_log,
    float* __restrict__ G, float* __restrict__ acum)
{
    __shared__ float Bl[64][64], Xs[64][64];
    __shared__ float Acum[64], ws[64];
    const int blk = blockIdx.x;
    const int c = blk & 63, bh = blk >> 6;
    const int h = bh & 63, b = bh >> 6;
    const int tid = threadIdx.x;
    const float Aneg = -expf(A_log[h]);
    const int l0g = c * cfg::CHUNK;
    const int ty = tid >> 4, tx = tid & 15;

    for (int idx = tid; idx < 64 * 64; idx += 256) {
        int l = idx >> 6, q = idx & 63;
        size_t row = (size_t)(b * cfg::LSEQ + l0g + l);
        const float* xr = xbc + row * cfg::D_XBC;
        float dtv = dtg[row * cfg::NHEADS + h];
        Xs[l][q] = xr[h * cfg::HEADDIM + q] * dtv;
        Bl[l][q] = xr[cfg::D_INNER + q];
    }
    if (tid < 64) {
        const int lane = tid & 31;
        size_t row = (size_t)(b * cfg::LSEQ + l0g + tid);
        float v = Aneg * dtg[row * cfg::NHEADS + h];
#pragma unroll
        for (int o = 1; o < 32; o <<= 1) {
            float n = __shfl_up_sync(0xffffffffu, v, o);
            if (lane >= o) v += n;
        }
        Acum[tid] = v;
    }
    __syncthreads();
    if (tid < 64) {
        float v = Acum[tid] + ((tid >= 32) ? Acum[31] : 0.f);
        Acum[tid] = v;
    }
    __syncthreads();
    if (tid < 64) {
        ws[tid] = expf(Acum[63] - Acum[tid]);
        acum[(size_t)blk * 64 + tid] = Acum[tid];
    }
    __syncthreads();

    const int n0 = ty * 4, p0 = tx * 4;
    float sa[4][4];
#pragma unroll
    for (int i = 0; i < 4; i++)
#pragma unroll
        for (int j = 0; j < 4; j++) sa[i][j] = 0.f;
#pragma unroll 4
    for (int l = 0; l < 64; l++) {
        float w = ws[l];
        float4 av = *(const float4*)&Bl[l][n0];
        float4 bv = *(const float4*)&Xs[l][p0];
        float a[4] = {av.x * w, av.y * w, av.z * w, av.w * w};
        float bb[4] = {bv.x, bv.y, bv.z, bv.w};
#pragma unroll
        for (int i = 0; i < 4; i++)
#pragma unroll
            for (int j = 0; j < 4; j++) sa[i][j] = fmaf(a[i], bb[j], sa[i][j]);
    }
    float* gout = G + (size_t)blk * 4096;
#pragma unroll
    for (int i = 0; i < 4; i++)
        *(float4*)(gout + (n0 + i) * 64 + p0) =
            make_float4(sa[i][0], sa[i][1], sa[i][2], sa[i][3]);
}

// ---------------------------------------------------------------------------
// SSD pass 2: elementwise chunk-state scan. grid = NBH*4 = 512, 256 threads.
// ---------------------------------------------------------------------------
__global__ __launch_bounds__(256) void ssd_pass2(
    const float* __restrict__ G, const float* __restrict__ acum,
    float* __restrict__ sprev)
{
    __shared__ float eAc[cfg::NCHUNK];
    const int bh    = blockIdx.x >> 2;
    const int slice = blockIdx.x & 3;
    const int tid   = threadIdx.x;
    if (tid < cfg::NCHUNK)
        eAc[tid] = expf(acum[((size_t)bh * cfg::NCHUNK + tid) * 64 + 63]);
    __syncthreads();

    const int f4 = slice * 256 + tid;
    float4 S = make_float4(0.f, 0.f, 0.f, 0.f);
    const size_t bhbase = (size_t)bh * cfg::NCHUNK * 4096;
    for (int c = 0; c < cfg::NCHUNK; c++) {
        const size_t base = bhbase + (size_t)c * 4096 + f4 * 4;
        *(float4*)(sprev + base) = S;
        float4 g = *(const float4*)(G + base);
        float ea = eAc[c];
        S.x = fmaf(ea, S.x, g.x);
        S.y = fmaf(ea, S.y, g.y);
        S.z = fmaf(ea, S.z, g.z);
        S.w = fmaf(ea, S.w, g.w);
    }
}

// ---------------------------------------------------------------------------
// SSD pass 3: per (bh, chunk) — Wt = masked decay CB, Y = Y_diag + Y_off + D*x.
// ---------------------------------------------------------------------------
struct P3Smem {
    float Bt[64][64], Ct[64][64], Xs[64][64], Xraw[64][64], Wt[64][64], Sp[64][64];
    float Acum[64], eA[64];
};

__global__ __launch_bounds__(256) void ssd_pass3(
    const float* __restrict__ xbc, const float* __restrict__ dtg,
    const float* __restrict__ D_param,
    const float* __restrict__ sprev, const float* __restrict__ acum,
    float* __restrict__ y)
{
    extern __shared__ char smraw[];
    P3Smem& sm = *reinterpret_cast<P3Smem*>(smraw);
    const int blk = blockIdx.x;
    const int c = blk & 63, bh = blk >> 6;
    const int h = bh & 63, b = bh >> 6;
    const int tid = threadIdx.x;
    const float Dh = D_param[h];
    const int l0g = c * cfg::CHUNK;
    const int ty = tid >> 4, tx = tid & 15;

    for (int idx = tid; idx < 64 * 64; idx += 256) {
        int l = idx >> 6, q = idx & 63;
        size_t row = (size_t)(b * cfg::LSEQ + l0g + l);
        const float* xr = xbc + row * cfg::D_XBC;
        float dtv = dtg[row * cfg::NHEADS + h];
        float xv  = xr[h * cfg::HEADDIM + q];
        sm.Xraw[l][q] = xv;
        sm.Xs[l][q]   = xv * dtv;
        sm.Bt[q][l]   = xr[cfg::D_INNER + q];
        sm.Ct[q][l]   = xr[cfg::D_INNER + cfg::D_STATE + q];
        (&sm.Sp[0][0])[idx] = sprev[(size_t)blk * 4096 + idx];
    }
    if (tid < 64) {
        float a = acum[(size_t)blk * 64 + tid];
        sm.Acum[tid] = a;
        sm.eA[tid]   = expf(a);
    }
    __syncthreads();

    {
        const int s0 = ty * 4, l0 = tx * 4;
        float acc[4][4];
#pragma unroll
        for (int i = 0; i < 4; i++)
#pragma unroll
            for (int j = 0; j < 4; j++) acc[i][j] = 0.f;
#pragma unroll 4
        for (int n = 0; n < 64; n++) {
            float4 av = *(const float4*)&sm.Bt[n][s0];
            float4 bv = *(const float4*)&sm.Ct[n][l0];
            float a[4] = {av.x, av.y, av.z, av.w};
            float bb[4] = {bv.x, bv.y, bv.z, bv.w};
#pragma unroll
            for (int i = 0; i < 4; i++)
#pragma unroll
                for (int j = 0; j < 4; j++) acc[i][j] = fmaf(a[i], bb[j], acc[i][j]);
        }
#pragma unroll
        for (int i = 0; i < 4; i++)
#pragma unroll
            for (int j = 0; j < 4; j++) {
                int s = s0 + i, l = l0 + j;
                float w = (s <= l) ? expf(sm.Acum[l] - sm.Acum[s]) : 0.f;
                sm.Wt[s][l] = acc[i][j] * w;
            }
    }
    __syncthreads();

    {
        const int l0 = ty * 4, p0 = tx * 4;
        float yd[4][4], yo[4][4];
#pragma unroll
        for (int i = 0; i < 4; i++)
#pragma unroll
            for (int j = 0; j < 4; j++) { yd[i][j] = 0.f; yo[i][j] = 0.f; }
#pragma unroll 4
        for (int s = 0; s < 64; s++) {
            float4 av = *(const float4*)&sm.Wt[s][l0];
            float4 bv = *(const float4*)&sm.Xs[s][p0];
            float a[4] = {av.x, av.y, av.z, av.w};
            float bb[4] = {bv.x, bv.y, bv.z, bv.w};
#pragma unroll
            for (int i = 0; i < 4; i++)
#pragma unroll
                for (int j = 0; j < 4; j++) yd[i][j] = fmaf(a[i], bb[j], yd[i][j]);
        }
#pragma unroll 4
        for (int n = 0; n < 64; n++) {
            float4 av = *(const float4*)&sm.Ct[n][l0];
            float4 bv = *(const float4*)&sm.Sp[n][p0];
            float a[4] = {av.x, av.y, av.z, av.w};
            float bb[4] = {bv.x, bv.y, bv.z, bv.w};
#pragma unroll
            for (int i = 0; i < 4; i++)
#pragma unroll
                for (int j = 0; j < 4; j++) yo[i][j] = fmaf(a[i], bb[j], yo[i][j]);
        }
#pragma unroll
        for (int i = 0; i < 4; i++) {
            int l = l0 + i;
            size_t row = (size_t)(b * cfg::LSEQ + l0g + l);
            float ea = sm.eA[l];
            float4 o;
            o.x = yd[i][0] + ea * yo[i][0] + Dh * sm.Xraw[l][p0 + 0];
            o.y = yd[i][1] + ea * yo[i][1] + Dh * sm.Xraw[l][p0 + 1];
            o.z = yd[i][2] + ea * yo[i][2] + Dh * sm.Xraw[l][p0 + 2];
            o.w = yd[i][3] + ea * yo[i][3] + Dh * sm.Xraw[l][p0 + 3];
            *(float4*)(y + row * cfg::D_INNER + h * cfg::HEADDIM + p0) = o;
        }
    }
}

// ---------------------------------------------------------------------------
// gate + RMSNorm -> fp16, written directly in pre-swizzled tile layout
// ---------------------------------------------------------------------------
__global__ __launch_bounds__(256) void gate_norm_kernel(
    const float* __restrict__ y, const float* __restrict__ zx,
    const float* __restrict__ nw, __half* __restrict__ nmh)
{
    __shared__ float gbuf[cfg::D_INNER];
    __shared__ float red[8];
    const int t = blockIdx.x;
    const int tid = threadIdx.x;
    const float* yr = y + (size_t)t * cfg::D_INNER;
    const float* zr = zx + (size_t)t * cfg::D_IN_PROJ;

    float ss = 0.f;
    for (int i = tid; i < cfg::D_INNER; i += 256) {
        float zv = zr[i];
        float gv = yr[i] * (zv / (1.f + expf(-zv)));
        gbuf[i] = gv;
        ss = fmaf(gv, gv, ss);
    }
#pragma unroll
    for (int o = 16; o; o >>= 1) ss += __shfl_xor_sync(0xffffffffu, ss, o);
    if ((tid & 31) == 0) red[tid >> 5] = ss;
    __syncthreads();
    if (tid < 32) {
        float v = (tid < 8) ? red[tid] : 0.f;
#pragma unroll
        for (int o = 4; o; o >>= 1) v += __shfl_xor_sync(0xffffffffu, v, o);
        if (tid == 0) red[0] = v;
    }
    __syncthreads();
    const float scale = rsqrtf(red[0] * (1.f / cfg::D_INNER) + 1e-5f);
    // swizzled-tile write: row t, col i
    const int tm = t >> 7, r = t & 127;
    const size_t tmbase = (size_t)tm * (cfg::D_INNER / 64) * 8192;
    const uint32_t rx = (uint32_t)(r & 7);
    for (int i = tid; i < cfg::D_INNER; i += 256) {
        float val = gbuf[i] * scale * nw[i];
        int tk = i >> 6, g = (i >> 3) & 7, e = i & 7;
        size_t off = tmbase + (size_t)tk * 8192 + r * 64 + ((g ^ rx) << 3) + e;
        nmh[off] = __float2half_rn(val);
    }
}

// ---------------------------------------------------------------------------
// Host launch
// ---------------------------------------------------------------------------
extern "C" void kernel_launch(void* const* d_in, const int* in_sizes, int n_in,
                              void* d_out, int out_size)
{
    (void)in_sizes; (void)n_in; (void)out_size;
    const float* u       = (const float*)d_in[0];
    const float* W_in    = (const float*)d_in[1];
    const float* conv_w  = (const float*)d_in[2];
    const float* conv_b  = (const float*)d_in[3];
    const float* dt_bias = (const float*)d_in[4];
    const float* A_log   = (const float*)d_in[5];
    const float* D_param = (const float*)d_in[6];
    const float* norm_w  = (const float*)d_in[7];
    const float* W_out   = (const float*)d_in[8];
    float* out = (float*)d_out;

    void *pzx, *pxbc, *pdt, *py, *pG, *psp, *pac;
    void *puh, *pwih, *pnmh, *pwoh;
    cudaGetSymbolAddress(&pzx,  g_zx);
    cudaGetSymbolAddress(&pxbc, g_xbc);
    cudaGetSymbolAddress(&pdt,  g_dt);
    cudaGetSymbolAddress(&py,   g_y);
    cudaGetSymbolAddress(&pG,   g_G);
    cudaGetSymbolAddress(&psp,  g_sprev);
    cudaGetSymbolAddress(&pac,  g_acum);
    cudaGetSymbolAddress(&puh,  g_uh);
    cudaGetSymbolAddress(&pwih, g_wih);
    cudaGetSymbolAddress(&pnmh, g_nmh);
    cudaGetSymbolAddress(&pwoh, g_woh);
    float* zx  = (float*)pzx;
    float* xbc = (float*)pxbc;
    float* dtb = (float*)pdt;
    float* yb  = (float*)py;
    float* Gb  = (float*)pG;
    float* spb = (float*)psp;
    float* acb = (float*)pac;
    __half* uh  = (__half*)puh;
    __half* wih = (__half*)pwih;
    __half* nmh = (__half*)pnmh;
    __half* woh = (__half*)pwoh;

    cudaFuncSetAttribute(gemm_mma_kernel, cudaFuncAttributeMaxDynamicSharedMemorySize,
                         mg::SMEM_BYTES);
    cudaFuncSetAttribute(ssd_pass3, cudaFuncAttributeMaxDynamicSharedMemorySize,
                         (int)sizeof(P3Smem));

    // fp32 -> fp16 pre-swizzled tile converts
    cvt_swz_kernel<<<(cfg::BL / 128) * (cfg::D_MODEL / 64), 256>>>(
        u, uh, cfg::BL, cfg::D_MODEL);                         // 64x32 tiles
    cvt_swz_kernel<<<(cfg::N1_PAD / 128) * (cfg::D_MODEL / 64), 256>>>(
        W_in, wih, cfg::D_IN_PROJ, cfg::D_MODEL);              // 66x32 tiles
    cvt_swz_kernel<<<(cfg::D_MODEL / 128) * (cfg::D_INNER / 64), 256>>>(
        W_out, woh, cfg::D_MODEL, cfg::D_INNER);               // 16x64 tiles

    // GEMM1: zx = u @ W_in^T  (fp16 HMMA, fp32 accum, bulk-copy pipeline)
    {
        dim3 grid(cfg::N1_PAD / 128, cfg::BL / 128);
        gemm_mma_kernel<<<grid, 256, mg::SMEM_BYTES>>>(uh, wih, zx,
                                                       cfg::BL, cfg::D_IN_PROJ, cfg::D_MODEL);
    }
    // fused conv+silu and dt softplus
    conv_dt_kernel<<<fc::NCONV + fc::NDT, 256>>>(zx, conv_w, conv_b, dt_bias, xbc, dtb);
    // SSD: 3 passes
    ssd_pass1<<<cfg::NBH * cfg::NCHUNK, 256>>>(xbc, dtb, A_log, Gb, acb);
    ssd_pass2<<<cfg::NBH * 4, 256>>>(Gb, acb, spb);
    ssd_pass3<<<cfg::NBH * cfg::NCHUNK, 256, sizeof(P3Smem)>>>(
        xbc, dtb, D_param, spb, acb, yb);
    // gate + rmsnorm -> fp16 (swizzled tiles)
    gate_norm_kernel<<<cfg::BL, 256>>>(yb, zx, norm_w, nmh);
    // GEMM2: out = nm @ W_out^T
    {
        dim3 grid(cfg::D_MODEL / 128, cfg::BL / 128);
        gemm_mma_kernel<<<grid, 256, mg::SMEM_BYTES>>>(nmh, woh, out,
                                                       cfg::BL, cfg::D_MODEL, cfg::D_INNER);
    }
}

// round 11
// speedup vs baseline: 7.5474x; 1.3219x over previous
#include <cuda_runtime.h>
#include <cuda_fp16.h>
#include <math.h>
#include <stdint.h>

// ---------------------------------------------------------------------------
// Problem constants (Mamba2 block, B=2, L=4096)
// ---------------------------------------------------------------------------
namespace cfg {
constexpr int D_MODEL   = 2048;
constexpr int D_INNER   = 4096;
constexpr int D_STATE   = 64;
constexpr int D_CONV    = 4;
constexpr int NHEADS    = 64;
constexpr int HEADDIM   = 64;
constexpr int D_XBC     = D_INNER + 2 * D_STATE;              // 4224
constexpr int D_IN_PROJ = 2 * D_INNER + 2 * D_STATE + NHEADS; // 8384
constexpr int LSEQ      = 4096;
constexpr int BATCH     = 2;
constexpr int BL        = BATCH * LSEQ;                       // 8192
constexpr int CHUNK     = 64;
constexpr int NCHUNK    = LSEQ / CHUNK;                       // 64
constexpr int NBH       = BATCH * NHEADS;                     // 128
constexpr int N1_PAD    = 8448;
}

// ---------------------------------------------------------------------------
// Scratch (allocation-free: __device__ globals; zero-init at load)
// ---------------------------------------------------------------------------
__device__ float g_zx [(size_t)cfg::BL * cfg::D_IN_PROJ];
__device__ float g_xbc[(size_t)cfg::BL * cfg::D_XBC];
__device__ float g_dt [(size_t)cfg::BL * cfg::NHEADS];
__device__ float g_y  [(size_t)cfg::BL * cfg::D_INNER];

// SSD intermediates
__device__ float g_G    [(size_t)cfg::NBH * cfg::NCHUNK * 64 * 64];
__device__ float g_sprev[(size_t)cfg::NBH * cfg::NCHUNK * 64 * 64];
__device__ float g_acum [(size_t)cfg::NBH * cfg::NCHUNK * 64];

// fp16 operands, PRE-SWIZZLED 16KB tiles (128 rows x 64 cols)
__device__ __half g_uh [(size_t)cfg::BL * cfg::D_MODEL];
__device__ __half g_wih[(size_t)cfg::N1_PAD * cfg::D_MODEL];
__device__ __half g_nmh[(size_t)cfg::BL * cfg::D_INNER];
__device__ __half g_woh[(size_t)cfg::D_MODEL * cfg::D_INNER];

// ---------------------------------------------------------------------------
// PTX helpers (family-portable: mma.sync / ldmatrix / cp.async.bulk / mbarrier)
// ---------------------------------------------------------------------------
__device__ __forceinline__ uint32_t smem_u32(const void* p) {
    uint32_t a;
    asm("{ .reg .u64 t; cvta.to.shared.u64 t, %1; cvt.u32.u64 %0, t; }"
        : "=r"(a) : "l"(p));
    return a;
}
__device__ __forceinline__ void ldsm4(uint32_t r[4], uint32_t addr) {
    asm volatile("ldmatrix.sync.aligned.m8n8.x4.shared.b16 {%0,%1,%2,%3}, [%4];"
                 : "=r"(r[0]), "=r"(r[1]), "=r"(r[2]), "=r"(r[3]) : "r"(addr));
}
__device__ __forceinline__ void ldsm2(uint32_t r[2], uint32_t addr) {
    asm volatile("ldmatrix.sync.aligned.m8n8.x2.shared.b16 {%0,%1}, [%2];"
                 : "=r"(r[0]), "=r"(r[1]) : "r"(addr));
}
__device__ __forceinline__ void mma16816h(float c[4], const uint32_t a[4],
                                          uint32_t b0, uint32_t b1) {
    asm volatile(
        "mma.sync.aligned.m16n8k16.row.col.f32.f16.f16.f32 "
        "{%0,%1,%2,%3}, {%4,%5,%6,%7}, {%8,%9}, {%0,%1,%2,%3};"
        : "+f"(c[0]), "+f"(c[1]), "+f"(c[2]), "+f"(c[3])
        : "r"(a[0]), "r"(a[1]), "r"(a[2]), "r"(a[3]), "r"(b0), "r"(b1));
}
__device__ __forceinline__ void bulk_cp(uint32_t dst, const void* src,
                                        uint32_t bytes, uint32_t mbar) {
    asm volatile(
        "cp.async.bulk.shared::cta.global.mbarrier::complete_tx::bytes "
        "[%0], [%1], %2, [%3];"
        :: "r"(dst), "l"(src), "r"(bytes), "r"(mbar) : "memory");
}
#define MBARRIER_INIT(addr, cnt) \
    asm volatile("mbarrier.init.shared.b64 [%0], %1;" :: "r"(addr), "r"(cnt) : "memory")
#define MBARRIER_EXPECT_TX(addr, bytes) \
    asm volatile("mbarrier.arrive.expect_tx.shared.b64 _, [%0], %1;" \
                 :: "r"(addr), "r"(bytes) : "memory")
#define MBARRIER_WAIT_PARITY(addr, par) do {                                      \
    uint32_t _m = (addr); uint32_t _p = (par); uint32_t _done;                    \
    asm volatile("{\n\t.reg .pred p;\n\t"                                         \
        "mbarrier.try_wait.parity.acquire.cta.shared::cta.b64 p, [%1], %2;\n\t"   \
        "selp.b32 %0, 1, 0, p;\n\t}" : "=r"(_done) : "r"(_m), "r"(_p) : "memory");\
    if (!_done) {                                                                 \
        asm volatile("{\n\t.reg .pred P1;\n\t"                                    \
        "WL_%=:\n\t"                                                              \
        "mbarrier.try_wait.parity.acquire.cta.shared::cta.b64 P1, [%0], %1, 0x989680;\n\t" \
        "@P1 bra.uni WD_%=;\n\tbra.uni WL_%=;\n\tWD_%=:\n\t}"                     \
        :: "r"(_m), "r"(_p) : "memory");                                          \
    } } while (0)

// half-index of element (row, col) in a 64-col swizzled fp16 tile
__device__ __forceinline__ int swz_idx(int row, int col) {
    return row * 64 + (((col >> 3) ^ (row & 7)) << 3) + (col & 7);
}

// ---------------------------------------------------------------------------
// HMMA fp16 GEMM on pre-swizzled tiles (unchanged from R10 WIN).
// ---------------------------------------------------------------------------
namespace mg {
constexpr int KT    = 64;
constexpr int TILEB = 128 * KT * 2;          // 16384 B
constexpr int STAGE = 2 * TILEB;             // 32768 B
constexpr int STAGES = 3;
constexpr int MBAR_OFF = STAGES * STAGE;     // 98304
constexpr int SMEM_BYTES = MBAR_OFF + 64;
}

__global__ __launch_bounds__(256, 2) void gemm_mma_kernel(
    const __half* __restrict__ At, const __half* __restrict__ Bt,
    float* __restrict__ C, int M, int N, int K)
{
    extern __shared__ char smraw[];
    const uint32_t sb = smem_u32(smraw);
    const int tid  = threadIdx.x;
    const int bm   = blockIdx.y * 128;
    const int bn   = blockIdx.x * 128;
    const int wid  = tid >> 5, lane = tid & 31;
    const int wm   = wid & 1;
    const int wn   = wid >> 1;
    const int NK   = K >> 6;

    const __half* Abase = At + (size_t)blockIdx.y * NK * 8192;
    const __half* Bbase = Bt + (size_t)blockIdx.x * NK * 8192;
    const uint32_t mb = sb + mg::MBAR_OFF;

    if (tid == 0) {
        MBARRIER_INIT(mb,      1u);
        MBARRIER_INIT(mb + 8,  1u);
        MBARRIER_INIT(mb + 16, 1u);
    }
    __syncthreads();

    auto issue = [&](int stage, int kblk) {
        const uint32_t m = mb + stage * 8;
        MBARRIER_EXPECT_TX(m, (uint32_t)mg::STAGE);
        const uint32_t d = sb + stage * mg::STAGE;
        bulk_cp(d,             Abase + (size_t)kblk * 8192, mg::TILEB, m);
        bulk_cp(d + mg::TILEB, Bbase + (size_t)kblk * 8192, mg::TILEB, m);
    };

    float acc[4][4][4];
#pragma unroll
    for (int i = 0; i < 4; i++)
#pragma unroll
        for (int j = 0; j < 4; j++)
#pragma unroll
            for (int q = 0; q < 4; q++) acc[i][j][q] = 0.f;

    if (tid == 0) { issue(0, 0); issue(1, 1); }

    for (int kb = 0; kb < NK; kb++) {
        const int st = kb % mg::STAGES;
        MBARRIER_WAIT_PARITY(mb + st * 8, (uint32_t)((kb / 3) & 1));
        __syncthreads();

        if (kb + 2 < NK && tid == 0)
            issue((kb + 2) % mg::STAGES, kb + 2);

        const uint32_t sA = sb + st * mg::STAGE;
        const uint32_t sB = sA + mg::TILEB;

#pragma unroll
        for (int ks = 0; ks < 4; ks++) {
            uint32_t bf[4][2];
#pragma unroll
            for (int nt = 0; nt < 4; nt++) {
                int nr = wn * 32 + nt * 8 + (lane & 7);
                int g  = 2 * ks + ((lane >> 3) & 1);
                uint32_t off = nr * 128 + (((g ^ (nr & 7))) << 4);
                ldsm2(bf[nt], sB + off);
            }
            uint32_t a[4][4];
#pragma unroll
            for (int mt = 0; mt < 4; mt++) {
                int ar = wm * 64 + mt * 16 + (lane & 15);
                int g  = 2 * ks + (lane >> 4);
                uint32_t off = ar * 128 + (((g ^ (ar & 7))) << 4);
                ldsm4(a[mt], sA + off);
            }
#pragma unroll
            for (int mt = 0; mt < 4; mt++)
#pragma unroll
                for (int nt = 0; nt < 4; nt++)
                    mma16816h(acc[mt][nt], a[mt], bf[nt][0], bf[nt][1]);
        }
    }

#pragma unroll
    for (int mt = 0; mt < 4; mt++) {
#pragma unroll
        for (int nt = 0; nt < 4; nt++) {
            int row = bm + wm * 64 + mt * 16 + (lane >> 2);
            int col = bn + wn * 32 + nt * 8 + (lane & 3) * 2;
            if (col < N) {
                *(float2*)(C + (size_t)row * N + col) =
                    make_float2(acc[mt][nt][0], acc[mt][nt][1]);
                *(float2*)(C + (size_t)(row + 8) * N + col) =
                    make_float2(acc[mt][nt][2], acc[mt][nt][3]);
            }
        }
    }
}

// ---------------------------------------------------------------------------
// fp32 row-major -> fp16 pre-swizzled 16KB tiles (unchanged)
// ---------------------------------------------------------------------------
__global__ __launch_bounds__(256) void cvt_swz_kernel(
    const float* __restrict__ src, __half* __restrict__ dst, int Mreal, int K)
{
    const int NKt = K >> 6;
    const int tile = blockIdx.x;
    const int tm = tile / NKt, tk = tile % NKt;
    __half* d = dst + (size_t)tile * 8192;
#pragma unroll
    for (int it = 0; it < 4; it++) {
        int id = it * 256 + threadIdx.x;
        int r  = id >> 3, g = id & 7;
        int grow = tm * 128 + r;
        uint32_t off = (uint32_t)(r * 64 + ((g ^ (r & 7)) << 3));
        uint4 pk;
        if (grow < Mreal) {
            const float* s = src + (size_t)grow * K + tk * 64 + g * 8;
            float4 v0 = *(const float4*)s;
            float4 v1 = *(const float4*)(s + 4);
            __half2 h0 = __floats2half2_rn(v0.x, v0.y);
            __half2 h1 = __floats2half2_rn(v0.z, v0.w);
            __half2 h2 = __floats2half2_rn(v1.x, v1.y);
            __half2 h3 = __floats2half2_rn(v1.z, v1.w);
            pk.x = *(uint32_t*)&h0; pk.y = *(uint32_t*)&h1;
            pk.z = *(uint32_t*)&h2; pk.w = *(uint32_t*)&h3;
        } else {
            pk = make_uint4(0, 0, 0, 0);
        }
        *(uint4*)(d + off) = pk;
    }
}

// ---------------------------------------------------------------------------
// Fused conv+silu and dt softplus (unchanged)
// ---------------------------------------------------------------------------
namespace fc {
constexpr int NCONV = (cfg::BL * cfg::D_XBC + 255) / 256;
constexpr int NDT   = (cfg::BL * cfg::NHEADS + 255) / 256;
}

__global__ void conv_dt_kernel(const float* __restrict__ zx,
                               const float* __restrict__ cw,
                               const float* __restrict__ cb,
                               const float* __restrict__ dt_bias,
                               float* __restrict__ xbc_out,
                               float* __restrict__ dt_out)
{
    int blk = blockIdx.x;
    if (blk < fc::NCONV) {
        int idx = blk * 256 + threadIdx.x;
        if (idx >= cfg::BL * cfg::D_XBC) return;
        int j = idx % cfg::D_XBC;
        int t = idx / cfg::D_XBC;
        int l = t & (cfg::LSEQ - 1);
        int b = t >> 12;
        float v = cb[j];
#pragma unroll
        for (int k = 0; k < cfg::D_CONV; k++) {
            int ls = l + k - (cfg::D_CONV - 1);
            if (ls >= 0)
                v = fmaf(cw[j * cfg::D_CONV + k],
                         zx[(size_t)(b * cfg::LSEQ + ls) * cfg::D_IN_PROJ + cfg::D_INNER + j], v);
        }
        xbc_out[(size_t)t * cfg::D_XBC + j] = v / (1.f + expf(-v));
    } else {
        int idx = (blk - fc::NCONV) * 256 + threadIdx.x;
        if (idx >= cfg::BL * cfg::NHEADS) return;
        int h = idx & 63;
        int t = idx >> 6;
        float x = zx[(size_t)t * cfg::D_IN_PROJ + cfg::D_INNER + cfg::D_XBC + h] + dt_bias[h];
        dt_out[idx] = (x > 20.f) ? x : log1pf(expf(x));
    }
}

// ---------------------------------------------------------------------------
// SSD pass 1 (HMMA): G[n][p] = sum_l (ws[l]*B[l][n]) * (x[l][p]*dt[l])
// Warp w: rows 16*(w&3), cols 32*(w>>2). fp16 operands, fp32 accum.
// ---------------------------------------------------------------------------
__global__ __launch_bounds__(256) void ssd_pass1(
    const float* __restrict__ xbc, const float* __restrict__ dtg,
    const float* __restrict__ A_log,
    float* __restrict__ G, float* __restrict__ acum)
{
    __shared__ __half Bw[4096];   // [n][l] swizzled
    __shared__ __half Xt[4096];   // [p][l] swizzled
    __shared__ float Acum[64], ws[64], dts[64];
    const int blk = blockIdx.x;
    const int c = blk & 63, bh = blk >> 6;
    const int h = bh & 63, b = bh >> 6;
    const int tid = threadIdx.x;
    const float Aneg = -expf(A_log[h]);
    const int l0g = c * cfg::CHUNK;

    if (tid < 64) {
        const int lane = tid & 31;
        size_t row = (size_t)(b * cfg::LSEQ + l0g + tid);
        float dtv = dtg[row * cfg::NHEADS + h];
        dts[tid] = dtv;
        float v = Aneg * dtv;
#pragma unroll
        for (int o = 1; o < 32; o <<= 1) {
            float n = __shfl_up_sync(0xffffffffu, v, o);
            if (lane >= o) v += n;
        }
        Acum[tid] = v;
    }
    __syncthreads();
    if (tid < 64) {
        float v = Acum[tid] + ((tid >= 32) ? Acum[31] : 0.f);
        Acum[tid] = v;
    }
    __syncthreads();
    if (tid < 64) {
        ws[tid] = expf(Acum[63] - Acum[tid]);
        acum[(size_t)blk * 64 + tid] = Acum[tid];
    }
    __syncthreads();

    // load + convert + transpose
    for (int idx = tid; idx < 1024; idx += 256) {
        int l = idx >> 4, q4 = (idx & 15) * 4;
        size_t row = (size_t)(b * cfg::LSEQ + l0g + l);
        const float* xr = xbc + row * cfg::D_XBC;
        float dtv = dts[l], wv = ws[l];
        float4 xv = *(const float4*)(xr + h * cfg::HEADDIM + q4);
        float4 bv = *(const float4*)(xr + cfg::D_INNER + q4);
        float xa[4] = {xv.x, xv.y, xv.z, xv.w};
        float ba[4] = {bv.x, bv.y, bv.z, bv.w};
#pragma unroll
        for (int e = 0; e < 4; e++) {
            int p = q4 + e;
            Xt[swz_idx(p, l)] = __float2half_rn(xa[e] * dtv);
            Bw[swz_idx(p, l)] = __float2half_rn(ba[e] * wv);
        }
    }
    __syncthreads();

    const int wid = tid >> 5, lane = tid & 31;
    const int wr = wid & 3, wc = wid >> 2;
    const uint32_t sBw = smem_u32(Bw), sXt = smem_u32(Xt);
    float acc[4][4];
#pragma unroll
    for (int i = 0; i < 4; i++)
#pragma unroll
        for (int j = 0; j < 4; j++) acc[i][j] = 0.f;

#pragma unroll
    for (int ks = 0; ks < 4; ks++) {
        uint32_t a[4];
        {
            int ar = wr * 16 + (lane & 15);
            int g  = 2 * ks + (lane >> 4);
            ldsm4(a, sBw + ar * 128 + ((g ^ (ar & 7)) << 4));
        }
#pragma unroll
        for (int nt = 0; nt < 4; nt++) {
            uint32_t bb[2];
            int nr = wc * 32 + nt * 8 + (lane & 7);
            int g  = 2 * ks + ((lane >> 3) & 1);
            ldsm2(bb, sXt + nr * 128 + ((g ^ (nr & 7)) << 4));
            mma16816h(acc[nt], a, bb[0], bb[1]);
        }
    }

    float* gout = G + (size_t)blk * 4096;
    const int n0 = wr * 16 + (lane >> 2);
#pragma unroll
    for (int nt = 0; nt < 4; nt++) {
        int p = wc * 32 + nt * 8 + (lane & 3) * 2;
        *(float2*)(gout + n0 * 64 + p)       = make_float2(acc[nt][0], acc[nt][1]);
        *(float2*)(gout + (n0 + 8) * 64 + p) = make_float2(acc[nt][2], acc[nt][3]);
    }
}

// ---------------------------------------------------------------------------
// SSD pass 2: elementwise chunk-state scan (unchanged)
// ---------------------------------------------------------------------------
__global__ __launch_bounds__(256) void ssd_pass2(
    const float* __restrict__ G, const float* __restrict__ acum,
    float* __restrict__ sprev)
{
    __shared__ float eAc[cfg::NCHUNK];
    const int bh    = blockIdx.x >> 2;
    const int slice = blockIdx.x & 3;
    const int tid   = threadIdx.x;
    if (tid < cfg::NCHUNK)
        eAc[tid] = expf(acum[((size_t)bh * cfg::NCHUNK + tid) * 64 + 63]);
    __syncthreads();

    const int f4 = slice * 256 + tid;
    float4 S = make_float4(0.f, 0.f, 0.f, 0.f);
    const size_t bhbase = (size_t)bh * cfg::NCHUNK * 4096;
    for (int c = 0; c < cfg::NCHUNK; c++) {
        const size_t base = bhbase + (size_t)c * 4096 + f4 * 4;
        *(float4*)(sprev + base) = S;
        float4 g = *(const float4*)(G + base);
        float ea = eAc[c];
        S.x = fmaf(ea, S.x, g.x);
        S.y = fmaf(ea, S.y, g.y);
        S.z = fmaf(ea, S.z, g.z);
        S.w = fmaf(ea, S.w, g.w);
    }
}

// ---------------------------------------------------------------------------
// SSD pass 3 (HMMA): W2[l][s] = masked-decay(C_l . B_s) fp16;
// Y[l][p] = W2 x Xs + eA[l]*(C x Sp^T) + Dh * Xraw.
// ---------------------------------------------------------------------------
struct P3S {
    __half Ct [4096];   // [l][n]
    __half Bt [4096];   // [s][n]
    __half Xt [4096];   // [p][l]  (x*dt, transposed)
    __half Spt[4096];   // [p][n]  (sprev transposed)
    __half W2 [4096];   // [l][s]
    float  Xraw[4096];  // [l][p]
    float  Acum[64], eA[64], dts[64];
};

__global__ __launch_bounds__(256) void ssd_pass3(
    const float* __restrict__ xbc, const float* __restrict__ dtg,
    const float* __restrict__ D_param,
    const float* __restrict__ sprev, const float* __restrict__ acum,
    float* __restrict__ y)
{
    extern __shared__ char smraw[];
    P3S& sm = *reinterpret_cast<P3S*>(smraw);
    const int blk = blockIdx.x;
    const int c = blk & 63, bh = blk >> 6;
    const int h = bh & 63, b = bh >> 6;
    const int tid = threadIdx.x;
    const float Dh = D_param[h];
    const int l0g = c * cfg::CHUNK;

    if (tid < 64) {
        size_t row = (size_t)(b * cfg::LSEQ + l0g + tid);
        sm.dts[tid] = dtg[row * cfg::NHEADS + h];
        float a = acum[(size_t)blk * 64 + tid];
        sm.Acum[tid] = a;
        sm.eA[tid]   = expf(a);
    }
    __syncthreads();

    // load + convert (+ transposes)
    const float* spin = sprev + (size_t)blk * 4096;
    for (int idx = tid; idx < 1024; idx += 256) {
        int r = idx >> 4, q4 = (idx & 15) * 4;
        size_t grow = (size_t)(b * cfg::LSEQ + l0g + r);
        const float* xr = xbc + grow * cfg::D_XBC;
        float dtv = sm.dts[r];
        float4 xv = *(const float4*)(xr + h * cfg::HEADDIM + q4);
        float4 bv = *(const float4*)(xr + cfg::D_INNER + q4);
        float4 cv = *(const float4*)(xr + cfg::D_INNER + cfg::D_STATE + q4);
        float4 sv = *(const float4*)(spin + r * 64 + q4);

        *(float4*)&sm.Xraw[r * 64 + q4] = xv;
        // Ct/Bt: row r, cols q4..q4+3 (8B packed store)
        {
            __half2 c0 = __floats2half2_rn(cv.x, cv.y);
            __half2 c1 = __floats2half2_rn(cv.z, cv.w);
            __half2 b0 = __floats2half2_rn(bv.x, bv.y);
            __half2 b1 = __floats2half2_rn(bv.z, bv.w);
            int ci = swz_idx(r, q4);
            uint2 pc; pc.x = *(uint32_t*)&c0; pc.y = *(uint32_t*)&c1;
            uint2 pb; pb.x = *(uint32_t*)&b0; pb.y = *(uint32_t*)&b1;
            *(uint2*)&sm.Ct[ci] = pc;
            *(uint2*)&sm.Bt[ci] = pb;
        }
        float xa[4] = {xv.x, xv.y, xv.z, xv.w};
        float sa[4] = {sv.x, sv.y, sv.z, sv.w};
#pragma unroll
        for (int e = 0; e < 4; e++) {
            int p = q4 + e;
            sm.Xt [swz_idx(p, r)] = __float2half_rn(xa[e] * dtv);
            sm.Spt[swz_idx(p, r)] = __float2half_rn(sa[e]);
        }
    }
    __syncthreads();

    const int wid = tid >> 5, lane = tid & 31;
    const int wr = wid & 3, wc = wid >> 2;
    const uint32_t sCt = smem_u32(sm.Ct),  sBt = smem_u32(sm.Bt);
    const uint32_t sXt = smem_u32(sm.Xt),  sSp = smem_u32(sm.Spt);
    const uint32_t sW2 = smem_u32(sm.W2);
    const int l0 = wr * 16 + (lane >> 2);

    // ---- phase A: W2 = masked-decay(C x B^T) ----
    {
        float accw[4][4];
#pragma unroll
        for (int i = 0; i < 4; i++)
#pragma unroll
            for (int j = 0; j < 4; j++) accw[i][j] = 0.f;
#pragma unroll
        for (int ks = 0; ks < 4; ks++) {
            uint32_t a[4];
            int ar = wr * 16 + (lane & 15);
            int ga = 2 * ks + (lane >> 4);
            ldsm4(a, sCt + ar * 128 + ((ga ^ (ar & 7)) << 4));
#pragma unroll
            for (int nt = 0; nt < 4; nt++) {
                uint32_t bb[2];
                int sr = wc * 32 + nt * 8 + (lane & 7);
                int gb = 2 * ks + ((lane >> 3) & 1);
                ldsm2(bb, sBt + sr * 128 + ((gb ^ (sr & 7)) << 4));
                mma16816h(accw[nt], a, bb[0], bb[1]);
            }
        }
        float A0 = sm.Acum[l0], A1 = sm.Acum[l0 + 8];
#pragma unroll
        for (int nt = 0; nt < 4; nt++) {
            int s0 = wc * 32 + nt * 8 + (lane & 3) * 2;
            float As0 = sm.Acum[s0], As1 = sm.Acum[s0 + 1];
            float w00 = (s0     <= l0) ? expf(A0 - As0) : 0.f;
            float w01 = (s0 + 1 <= l0) ? expf(A0 - As1) : 0.f;
            float w10 = (s0     <= l0 + 8) ? expf(A1 - As0) : 0.f;
            float w11 = (s0 + 1 <= l0 + 8) ? expf(A1 - As1) : 0.f;
            __half2 h0 = __floats2half2_rn(accw[nt][0] * w00, accw[nt][1] * w01);
            __half2 h1 = __floats2half2_rn(accw[nt][2] * w10, accw[nt][3] * w11);
            *(uint32_t*)&sm.W2[swz_idx(l0,     s0)] = *(uint32_t*)&h0;
            *(uint32_t*)&sm.W2[swz_idx(l0 + 8, s0)] = *(uint32_t*)&h1;
        }
    }
    __syncthreads();

    // ---- phase B: Y = W2 x Xs + eA*(C x Sp^T) + Dh*Xraw ----
    float accd[4][4], acco[4][4];
#pragma unroll
    for (int i = 0; i < 4; i++)
#pragma unroll
        for (int j = 0; j < 4; j++) { accd[i][j] = 0.f; acco[i][j] = 0.f; }

#pragma unroll
    for (int ks = 0; ks < 4; ks++) {
        uint32_t a[4];
        int ar = wr * 16 + (lane & 15);
        int ga = 2 * ks + (lane >> 4);
        ldsm4(a, sW2 + ar * 128 + ((ga ^ (ar & 7)) << 4));
#pragma unroll
        for (int nt = 0; nt < 4; nt++) {
            uint32_t bb[2];
            int nr = wc * 32 + nt * 8 + (lane & 7);
            int gb = 2 * ks + ((lane >> 3) & 1);
            ldsm2(bb, sXt + nr * 128 + ((gb ^ (nr & 7)) << 4));
            mma16816h(accd[nt], a, bb[0], bb[1]);
        }
    }
#pragma unroll
    for (int ks = 0; ks < 4; ks++) {
        uint32_t a[4];
        int ar = wr * 16 + (lane & 15);
        int ga = 2 * ks + (lane >> 4);
        ldsm4(a, sCt + ar * 128 + ((ga ^ (ar & 7)) << 4));
#pragma unroll
        for (int nt = 0; nt < 4; nt++) {
            uint32_t bb[2];
            int nr = wc * 32 + nt * 8 + (lane & 7);
            int gb = 2 * ks + ((lane >> 3) & 1);
            ldsm2(bb, sSp + nr * 128 + ((gb ^ (nr & 7)) << 4));
            mma16816h(acco[nt], a, bb[0], bb[1]);
        }
    }

    const float eA0 = sm.eA[l0], eA1 = sm.eA[l0 + 8];
    const size_t row0 = (size_t)(b * cfg::LSEQ + l0g + l0);
#pragma unroll
    for (int nt = 0; nt < 4; nt++) {
        int p = wc * 32 + nt * 8 + (lane & 3) * 2;
        float x00 = sm.Xraw[l0 * 64 + p],      x01 = sm.Xraw[l0 * 64 + p + 1];
        float x10 = sm.Xraw[(l0 + 8) * 64 + p], x11 = sm.Xraw[(l0 + 8) * 64 + p + 1];
        float2 v0 = make_float2(accd[nt][0] + eA0 * acco[nt][0] + Dh * x00,
                                accd[nt][1] + eA0 * acco[nt][1] + Dh * x01);
        float2 v1 = make_float2(accd[nt][2] + eA1 * acco[nt][2] + Dh * x10,
                                accd[nt][3] + eA1 * acco[nt][3] + Dh * x11);
        *(float2*)(y + row0 * cfg::D_INNER + h * cfg::HEADDIM + p)       = v0;
        *(float2*)(y + (row0 + 8) * cfg::D_INNER + h * cfg::HEADDIM + p) = v1;
    }
}

// ---------------------------------------------------------------------------
// gate + RMSNorm -> fp16 pre-swizzled tiles (unchanged)
// ---------------------------------------------------------------------------
__global__ __launch_bounds__(256) void gate_norm_kernel(
    const float* __restrict__ y, const float* __restrict__ zx,
    const float* __restrict__ nw, __half* __restrict__ nmh)
{
    __shared__ float gbuf[cfg::D_INNER];
    __shared__ float red[8];
    const int t = blockIdx.x;
    const int tid = threadIdx.x;
    const float* yr = y + (size_t)t * cfg::D_INNER;
    const float* zr = zx + (size_t)t * cfg::D_IN_PROJ;

    float ss = 0.f;
    for (int i = tid; i < cfg::D_INNER; i += 256) {
        float zv = zr[i];
        float gv = yr[i] * (zv / (1.f + expf(-zv)));
        gbuf[i] = gv;
        ss = fmaf(gv, gv, ss);
    }
#pragma unroll
    for (int o = 16; o; o >>= 1) ss += __shfl_xor_sync(0xffffffffu, ss, o);
    if ((tid & 31) == 0) red[tid >> 5] = ss;
    __syncthreads();
    if (tid < 32) {
        float v = (tid < 8) ? red[tid] : 0.f;
#pragma unroll
        for (int o = 4; o; o >>= 1) v += __shfl_xor_sync(0xffffffffu, v, o);
        if (tid == 0) red[0] = v;
    }
    __syncthreads();
    const float scale = rsqrtf(red[0] * (1.f / cfg::D_INNER) + 1e-5f);
    const int tm = t >> 7, r = t & 127;
    const size_t tmbase = (size_t)tm * (cfg::D_INNER / 64) * 8192;
    const uint32_t rx = (uint32_t)(r & 7);
    for (int i = tid; i < cfg::D_INNER; i += 256) {
        float val = gbuf[i] * scale * nw[i];
        int tk = i >> 6, g = (i >> 3) & 7, e = i & 7;
        size_t off = tmbase + (size_t)tk * 8192 + r * 64 + ((g ^ rx) << 3) + e;
        nmh[off] = __float2half_rn(val);
    }
}

// ---------------------------------------------------------------------------
// Host launch
// ---------------------------------------------------------------------------
extern "C" void kernel_launch(void* const* d_in, const int* in_sizes, int n_in,
                              void* d_out, int out_size)
{
    (void)in_sizes; (void)n_in; (void)out_size;
    const float* u       = (const float*)d_in[0];
    const float* W_in    = (const float*)d_in[1];
    const float* conv_w  = (const float*)d_in[2];
    const float* conv_b  = (const float*)d_in[3];
    const float* dt_bias = (const float*)d_in[4];
    const float* A_log   = (const float*)d_in[5];
    const float* D_param = (const float*)d_in[6];
    const float* norm_w  = (const float*)d_in[7];
    const float* W_out   = (const float*)d_in[8];
    float* out = (float*)d_out;

    void *pzx, *pxbc, *pdt, *py, *pG, *psp, *pac;
    void *puh, *pwih, *pnmh, *pwoh;
    cudaGetSymbolAddress(&pzx,  g_zx);
    cudaGetSymbolAddress(&pxbc, g_xbc);
    cudaGetSymbolAddress(&pdt,  g_dt);
    cudaGetSymbolAddress(&py,   g_y);
    cudaGetSymbolAddress(&pG,   g_G);
    cudaGetSymbolAddress(&psp,  g_sprev);
    cudaGetSymbolAddress(&pac,  g_acum);
    cudaGetSymbolAddress(&puh,  g_uh);
    cudaGetSymbolAddress(&pwih, g_wih);
    cudaGetSymbolAddress(&pnmh, g_nmh);
    cudaGetSymbolAddress(&pwoh, g_woh);
    float* zx  = (float*)pzx;
    float* xbc = (float*)pxbc;
    float* dtb = (float*)pdt;
    float* yb  = (float*)py;
    float* Gb  = (float*)pG;
    float* spb = (float*)psp;
    float* acb = (float*)pac;
    __half* uh  = (__half*)puh;
    __half* wih = (__half*)pwih;
    __half* nmh = (__half*)pnmh;
    __half* woh = (__half*)pwoh;

    cudaFuncSetAttribute(gemm_mma_kernel, cudaFuncAttributeMaxDynamicSharedMemorySize,
                         mg::SMEM_BYTES);
    cudaFuncSetAttribute(ssd_pass3, cudaFuncAttributeMaxDynamicSharedMemorySize,
                         (int)sizeof(P3S));

    // fp32 -> fp16 pre-swizzled tile converts
    cvt_swz_kernel<<<(cfg::BL / 128) * (cfg::D_MODEL / 64), 256>>>(
        u, uh, cfg::BL, cfg::D_MODEL);
    cvt_swz_kernel<<<(cfg::N1_PAD / 128) * (cfg::D_MODEL / 64), 256>>>(
        W_in, wih, cfg::D_IN_PROJ, cfg::D_MODEL);
    cvt_swz_kernel<<<(cfg::D_MODEL / 128) * (cfg::D_INNER / 64), 256>>>(
        W_out, woh, cfg::D_MODEL, cfg::D_INNER);

    // GEMM1: zx = u @ W_in^T
    {
        dim3 grid(cfg::N1_PAD / 128, cfg::BL / 128);
        gemm_mma_kernel<<<grid, 256, mg::SMEM_BYTES>>>(uh, wih, zx,
                                                       cfg::BL, cfg::D_IN_PROJ, cfg::D_MODEL);
    }
    // fused conv+silu and dt softplus
    conv_dt_kernel<<<fc::NCONV + fc::NDT, 256>>>(zx, conv_w, conv_b, dt_bias, xbc, dtb);
    // SSD: 3 passes (pass1/pass3 now HMMA)
    ssd_pass1<<<cfg::NBH * cfg::NCHUNK, 256>>>(xbc, dtb, A_log, Gb, acb);
    ssd_pass2<<<cfg::NBH * 4, 256>>>(Gb, acb, spb);
    ssd_pass3<<<cfg::NBH * cfg::NCHUNK, 256, sizeof(P3S)>>>(
        xbc, dtb, D_param, spb, acb, yb);
    // gate + rmsnorm -> fp16 (swizzled tiles)
    gate_norm_kernel<<<cfg::BL, 256>>>(yb, zx, norm_w, nmh);
    // GEMM2: out = nm @ W_out^T
    {
        dim3 grid(cfg::D_MODEL / 128, cfg::BL / 128);
        gemm_mma_kernel<<<grid, 256, mg::SMEM_BYTES>>>(nmh, woh, out,
                                                       cfg::BL, cfg::D_MODEL, cfg::D_INNER);
    }
}